// round 5
// baseline (speedup 1.0000x reference)
#include <cuda_runtime.h>

#define ROWS 38400
#define BIG  4915200

// ---------------- device scratch ----------------
__device__ float g_q[BIG];
__device__ float g_k[BIG];
__device__ float g_v[BIG];
__device__ float g_o[BIG];
__device__ float g_dtw[BIG];
__device__ float g_ex[BIG];
__device__ float g_res[BIG];
__device__ float g_tmp[BIG];
__device__ float g_xp[786432];
__device__ float g_kp[786432];
__device__ float g_vp[786432];
__device__ float g_sen[51200];
__device__ float g_edge[51200];
__device__ float g_senx[51200];

// ---------------- SGEMM: C[M x 128] = A[M x 128] @ W[128 x 128] + bias ----------------
__global__ void __launch_bounds__(256) gemm128_kernel(
    const float* __restrict__ A, const float* __restrict__ W,
    const float* __restrict__ bias, float* __restrict__ C, int M)
{
    __shared__ float As[16 * 65];
    __shared__ float Bs[16 * 64];
    const int rowBase = blockIdx.x * 64;
    const int colBase = blockIdx.y * 64;
    const int tid = threadIdx.x;
    const int tx = tid & 15, ty = tid >> 4;
    float acc[4][4];
#pragma unroll
    for (int i = 0; i < 4; i++)
#pragma unroll
        for (int j = 0; j < 4; j++) acc[i][j] = 0.f;

    for (int kb = 0; kb < 128; kb += 16) {
#pragma unroll
        for (int i = tid; i < 1024; i += 256) {
            int r = i >> 4, kk = i & 15;
            int row = rowBase + r;
            As[kk * 65 + r] = (row < M) ? A[row * 128 + kb + kk] : 0.f;
        }
#pragma unroll
        for (int i = tid; i < 1024; i += 256) {
            int kk = i >> 6, c = i & 63;
            Bs[kk * 64 + c] = W[(kb + kk) * 128 + colBase + c];
        }
        __syncthreads();
#pragma unroll
        for (int kk = 0; kk < 16; ++kk) {
            float a0 = As[kk * 65 + ty * 4 + 0];
            float a1 = As[kk * 65 + ty * 4 + 1];
            float a2 = As[kk * 65 + ty * 4 + 2];
            float a3 = As[kk * 65 + ty * 4 + 3];
            float4 b = *(const float4*)&Bs[kk * 64 + tx * 4];
            acc[0][0] += a0 * b.x; acc[0][1] += a0 * b.y; acc[0][2] += a0 * b.z; acc[0][3] += a0 * b.w;
            acc[1][0] += a1 * b.x; acc[1][1] += a1 * b.y; acc[1][2] += a1 * b.z; acc[1][3] += a1 * b.w;
            acc[2][0] += a2 * b.x; acc[2][1] += a2 * b.y; acc[2][2] += a2 * b.z; acc[2][3] += a2 * b.w;
            acc[3][0] += a3 * b.x; acc[3][1] += a3 * b.y; acc[3][2] += a3 * b.z; acc[3][3] += a3 * b.w;
        }
        __syncthreads();
    }
#pragma unroll
    for (int i = 0; i < 4; i++) {
        int row = rowBase + ty * 4 + i;
        if (row >= M) continue;
#pragma unroll
        for (int j = 0; j < 4; j++) {
            int col = colBase + tx * 4 + j;
            C[row * 128 + col] = acc[i][j] + bias[col];
        }
    }
}

// ---------------- LayerNorm of (a [+ b] [+ c] [+ d]) over last dim 128 ----------------
__global__ void __launch_bounds__(128) ln_kernel(
    const float* __restrict__ a, const float* __restrict__ b,
    const float* __restrict__ c, const float* __restrict__ d,
    const float* __restrict__ gamma, const float* __restrict__ beta,
    float* __restrict__ out)
{
    __shared__ float red[8];
    long long idx = (long long)blockIdx.x * 128 + threadIdx.x;
    float v = a[idx];
    if (b) v += b[idx];
    if (c) v += c[idx];
    if (d) v += d[idx];
    float s = v, ss = v * v;
#pragma unroll
    for (int o = 16; o; o >>= 1) {
        s  += __shfl_xor_sync(0xffffffffu, s,  o);
        ss += __shfl_xor_sync(0xffffffffu, ss, o);
    }
    int w = threadIdx.x >> 5;
    if ((threadIdx.x & 31) == 0) { red[w] = s; red[4 + w] = ss; }
    __syncthreads();
    s  = red[0] + red[1] + red[2] + red[3];
    ss = red[4] + red[5] + red[6] + red[7];
    float m = s * (1.f / 128.f);
    float var = ss * (1.f / 128.f) - m * m;
    float inv = rsqrtf(var + 1e-5f);
    out[idx] = (v - m) * inv * gamma[threadIdx.x] + beta[threadIdx.x];
}

// ---------------- adaptive avg pool over node axis: (bt,400,128) -> (bt,64,128) ----------------
__global__ void __launch_bounds__(128) pool_kernel(const float* __restrict__ x, float* __restrict__ xp)
{
    int bid = blockIdx.x;           // bt*64 + c
    int bt = bid >> 6, c = bid & 63;
    int s = (c * 400) >> 6;
    int e = ((c + 1) * 400 + 63) >> 6;
    float sum = 0.f;
    for (int n = s; n < e; ++n) sum += x[(bt * 400 + n) * 128 + threadIdx.x];
    xp[bid * 128 + threadIdx.x] = sum / (float)(e - s);
}

// ---------------- GEANet per row (mode 0: node with permuted store, 1: edge) ----------------
__global__ void __launch_bounds__(128) gea_kernel(
    const float* __restrict__ in, const float* __restrict__ w, const float* __restrict__ bb,
    float* __restrict__ outp, int mode)
{
    __shared__ float xr[128], tmp[128], s1[16], rs[8], w0[256], w1[256], b0v[16], b1v[16];
    int tid = threadIdx.x;
    int h = tid >> 4, u = tid & 15;
    w0[tid] = w[tid];        w0[128 + tid] = w[128 + tid];
    w1[tid] = w[256 + tid];  w1[128 + tid] = w[384 + tid];
    if (tid < 16) { b0v[tid] = bb[tid]; b1v[tid] = bb[16 + tid]; }
    int id = blockIdx.x;
    if (mode == 0) xr[tid] = in[id * 128 + tid];
    else           xr[tid] = in[id * 128 + u * 8 + h];
    __syncthreads();

    float a = b0v[u];
#pragma unroll
    for (int k = 0; k < 16; k++) a += xr[h * 16 + k] * w0[k * 16 + u];
    tmp[tid] = a;
    __syncthreads();
    float m = tmp[u];
#pragma unroll
    for (int hh = 1; hh < 8; hh++) m = fmaxf(m, tmp[hh * 16 + u]);
    float ev = __expf(a - m);
    __syncthreads();
    tmp[tid] = ev;
    __syncthreads();
    if (tid < 16) { float s = 0.f; for (int hh = 0; hh < 8; hh++) s += tmp[hh * 16 + tid]; s1[tid] = s; }
    __syncthreads();
    float vv = ev / s1[u];
    __syncthreads();
    tmp[tid] = vv;
    __syncthreads();
    if (tid < 8) { float s = 0.f; for (int uu = 0; uu < 16; uu++) s += tmp[tid * 16 + uu]; rs[tid] = s; }
    __syncthreads();
    float dn = vv / rs[h];
    __syncthreads();
    tmp[tid] = dn;
    __syncthreads();
    float o = b1v[u];
#pragma unroll
    for (int k = 0; k < 16; k++) o += tmp[h * 16 + k] * w1[k * 16 + u];

    if (mode == 0) {
        int b = id / 4800, r2 = id % 4800, t = r2 / 400, n = r2 % 400;
        outp[((b * 400 + n) * 12 + t) * 128 + tid] = o;   // (B,N,T,D) flat == (B,T,N,D) reinterp
    } else {
        outp[id * 128 + tid] = o;
    }
}

// ---------------- full attention, 400 keys, block per (bt, head), dynamic SMEM ----------------
__global__ void __launch_bounds__(256) attn_full_kernel(
    const float* __restrict__ q, const float* __restrict__ k, const float* __restrict__ v,
    float* __restrict__ o)
{
    extern __shared__ float sm[];
    float* Ks = sm;                    // [16][401]
    float* Vs = sm + 16 * 401;         // [16][401]
    float* pball = sm + 2 * 16 * 401;  // [8][400]
    int bid = blockIdx.x;
    int bt = bid >> 3, h = bid & 7;
    int tid = threadIdx.x;
    int base = bt * 400 * 128 + h * 16;
    for (int i = tid; i < 6400; i += 256) {
        int kk = i >> 4, d = i & 15;
        Ks[d * 401 + kk] = k[base + kk * 128 + d];
        Vs[d * 401 + kk] = v[base + kk * 128 + d];
    }
    __syncthreads();
    int warp = tid >> 5, lane = tid & 31;
    float* pb = pball + warp * 400;
    for (int qi = warp; qi < 400; qi += 8) {
        float qd[16];
#pragma unroll
        for (int d = 0; d < 16; d++) qd[d] = q[base + qi * 128 + d];
        float sc[13];
        float m = -3.4e38f;
#pragma unroll
        for (int j = 0; j < 13; j++) {
            int kk = lane + j * 32;
            float s = -3.4e38f;
            if (kk < 400) {
                s = 0.f;
#pragma unroll
                for (int d = 0; d < 16; d++) s += qd[d] * Ks[d * 401 + kk];
                s *= 0.25f;
            }
            sc[j] = s;
            m = fmaxf(m, s);
        }
#pragma unroll
        for (int off = 16; off; off >>= 1) m = fmaxf(m, __shfl_xor_sync(0xffffffffu, m, off));
        float lsum = 0.f;
#pragma unroll
        for (int j = 0; j < 13; j++) {
            int kk = lane + j * 32;
            if (kk < 400) { float p = __expf(sc[j] - m); sc[j] = p; lsum += p; }
        }
#pragma unroll
        for (int off = 16; off; off >>= 1) lsum += __shfl_xor_sync(0xffffffffu, lsum, off);
#pragma unroll
        for (int j = 0; j < 13; j++) {
            int kk = lane + j * 32;
            if (kk < 400) pb[kk] = sc[j];
        }
        __syncwarp();
        int d = lane & 15, half = lane >> 4;
        const float* Vrow = Vs + d * 401;
        float acc = 0.f;
        int c0 = half * 200;
#pragma unroll 4
        for (int c = c0; c < c0 + 200; ++c) acc += pb[c] * Vrow[c];
        acc += __shfl_xor_sync(0xffffffffu, acc, 16);
        if (lane < 16) o[base + qi * 128 + d] = acc / lsum;
        __syncwarp();
    }
}

// ---------------- pooled attention, 64 keys + positional bias ----------------
__global__ void __launch_bounds__(256) attn_pool_kernel(
    const float* __restrict__ q, const float* __restrict__ kp, const float* __restrict__ vp,
    const float* __restrict__ pos, float* __restrict__ o)
{
    __shared__ float Ks[16 * 65], Vs[16 * 65], pball[8 * 64];
    int bid = blockIdx.x;
    int bt = bid >> 3, h = bid & 7;
    int tid = threadIdx.x;
    int kbase = bt * 64 * 128 + h * 16;
    int qbase = bt * 400 * 128 + h * 16;
    for (int i = tid; i < 1024; i += 256) {
        int kk = i >> 4, d = i & 15;
        Ks[d * 65 + kk] = kp[kbase + kk * 128 + d];
        Vs[d * 65 + kk] = vp[kbase + kk * 128 + d];
    }
    __syncthreads();
    int warp = tid >> 5, lane = tid & 31;
    float* pb = pball + warp * 64;
    for (int qi = warp; qi < 400; qi += 8) {
        float qd[16];
#pragma unroll
        for (int d = 0; d < 16; d++) qd[d] = q[qbase + qi * 128 + d];
        float sc[2];
        float m = -3.4e38f;
#pragma unroll
        for (int j = 0; j < 2; j++) {
            int kk = lane + 32 * j;
            float s = 0.f;
#pragma unroll
            for (int d = 0; d < 16; d++) s += qd[d] * Ks[d * 65 + kk];
            s = s * 0.25f + pos[qi * 64 + kk];
            sc[j] = s; m = fmaxf(m, s);
        }
#pragma unroll
        for (int off = 16; off; off >>= 1) m = fmaxf(m, __shfl_xor_sync(0xffffffffu, m, off));
        float lsum = 0.f;
#pragma unroll
        for (int j = 0; j < 2; j++) { float p = __expf(sc[j] - m); sc[j] = p; lsum += p; }
#pragma unroll
        for (int off = 16; off; off >>= 1) lsum += __shfl_xor_sync(0xffffffffu, lsum, off);
        pb[lane] = sc[0]; pb[lane + 32] = sc[1];
        __syncwarp();
        int d = lane & 15, half = lane >> 4;
        float acc = 0.f;
#pragma unroll
        for (int c = half * 32; c < half * 32 + 32; ++c) acc += pb[c] * Vs[d * 65 + c];
        acc += __shfl_xor_sync(0xffffffffu, acc, 16);
        if (lane < 16) o[qbase + qi * 128 + d] = acc / lsum;
        __syncwarp();
    }
}

// ---------------- fused FF: out = relu(in(*mul) @ w1 + b1) @ w2 + b2, hidden in SMEM ----------------
// dynamic SMEM layout (floats): Rows[32*128] | W1s[128*68] | Hs[32*68] | W2s[64*132]
#define FF_ROWS_OFF 0
#define FF_W1_OFF   4096
#define FF_H_OFF    12800
#define FF_W2_OFF   14976
#define FF_SMEM_FLOATS 23424

__global__ void __launch_bounds__(256) ff_kernel(
    const float* __restrict__ in, const float* __restrict__ mulp,
    const float* __restrict__ w1, const float* __restrict__ b1,
    const float* __restrict__ w2, const float* __restrict__ b2,
    float* __restrict__ outp)
{
    extern __shared__ float sm[];
    float* Rows = sm + FF_ROWS_OFF;
    float* W1s  = sm + FF_W1_OFF;
    float* Hs   = sm + FF_H_OFF;
    float* W2s  = sm + FF_W2_OFF;
    int tid = threadIdx.x;
    int row0 = blockIdx.x * 32;
    for (int i = tid; i < 32 * 128; i += 256) {
        int r = i >> 7, k = i & 127;
        int row = row0 + r;
        float vv = in[(long long)row * 128 + k];
        if (mulp) vv *= mulp[(row % 400) * 128 + k];
        Rows[r * 128 + k] = vv;
    }
    int ry = tid >> 4;        // owns rows ry*2, ry*2+1
    int jx = tid & 15;        // phase A: cols jx*4..+3 ; phase B: cols jx*8..+7
    int r0 = ry * 2;
    float acc[2][8];
#pragma unroll
    for (int a = 0; a < 2; a++)
#pragma unroll
        for (int j = 0; j < 8; j++) acc[a][j] = 0.f;

    for (int jb = 0; jb < 2048; jb += 64) {
        __syncthreads();
        for (int i = tid; i < 128 * 64; i += 256) {
            int k = i >> 6, j = i & 63;
            W1s[k * 68 + j] = w1[k * 2048 + jb + j];
        }
        for (int i = tid; i < 64 * 128; i += 256) {
            int k2 = i >> 7, c = i & 127;
            W2s[k2 * 132 + c] = w2[(jb + k2) * 128 + c];
        }
        __syncthreads();
        // phase A: H[32][64] = Rows @ W1chunk + b1
        float hh[2][4];
#pragma unroll
        for (int a = 0; a < 2; a++)
#pragma unroll
            for (int j = 0; j < 4; j++) hh[a][j] = b1[jb + jx * 4 + j];
#pragma unroll 4
        for (int k = 0; k < 128; k++) {
            float a0 = Rows[r0 * 128 + k];
            float a1 = Rows[(r0 + 1) * 128 + k];
            float4 w = *(const float4*)&W1s[k * 68 + jx * 4];
            hh[0][0] += a0 * w.x; hh[0][1] += a0 * w.y; hh[0][2] += a0 * w.z; hh[0][3] += a0 * w.w;
            hh[1][0] += a1 * w.x; hh[1][1] += a1 * w.y; hh[1][2] += a1 * w.z; hh[1][3] += a1 * w.w;
        }
#pragma unroll
        for (int a = 0; a < 2; a++)
#pragma unroll
            for (int j = 0; j < 4; j++)
                Hs[(r0 + a) * 68 + jx * 4 + j] = fmaxf(hh[a][j], 0.f);
        __syncthreads();
        // phase B: acc += H @ W2chunk
#pragma unroll 4
        for (int k2 = 0; k2 < 64; k2++) {
            float h0 = Hs[r0 * 68 + k2];
            float h1 = Hs[(r0 + 1) * 68 + k2];
            float4 wlo = *(const float4*)&W2s[k2 * 132 + jx * 8];
            float4 whi = *(const float4*)&W2s[k2 * 132 + jx * 8 + 4];
            acc[0][0] += h0 * wlo.x; acc[0][1] += h0 * wlo.y; acc[0][2] += h0 * wlo.z; acc[0][3] += h0 * wlo.w;
            acc[0][4] += h0 * whi.x; acc[0][5] += h0 * whi.y; acc[0][6] += h0 * whi.z; acc[0][7] += h0 * whi.w;
            acc[1][0] += h1 * wlo.x; acc[1][1] += h1 * wlo.y; acc[1][2] += h1 * wlo.z; acc[1][3] += h1 * wlo.w;
            acc[1][4] += h1 * whi.x; acc[1][5] += h1 * whi.y; acc[1][6] += h1 * whi.z; acc[1][7] += h1 * whi.w;
        }
    }
#pragma unroll
    for (int a = 0; a < 2; a++) {
        long long row = row0 + r0 + a;
#pragma unroll
        for (int j = 0; j < 8; j++) {
            int c = jx * 8 + j;
            outp[row * 128 + c] = acc[a][j] + b2[c];
        }
    }
}

// ---------------- final add + copy sen_extra ----------------
__global__ void add_kernel(const float* __restrict__ a, const float* __restrict__ b,
                           float* __restrict__ o, int n)
{
    int i = blockIdx.x * 256 + threadIdx.x;
    if (i < n) o[i] = a[i] + b[i];
}

__global__ void copy_kernel(const float* __restrict__ a, float* __restrict__ o, int n)
{
    int i = blockIdx.x * 256 + threadIdx.x;
    if (i < n) o[i] = a[i];
}

// ---------------- host ----------------
static float* sym(const void* s) { void* p = nullptr; cudaGetSymbolAddress(&p, s); return (float*)p; }

extern "C" void kernel_launch(void* const* d_in, const int* in_sizes, int n_in,
                              void* d_out, int out_size)
{
    const float* x        = (const float*)d_in[0];
    const float* semb     = (const float*)d_in[1];
    const float* dqkv_w   = (const float*)d_in[2];
    const float* dqkv_b   = (const float*)d_in[3];
    const float* dout_w   = (const float*)d_in[4];
    const float* dout_b   = (const float*)d_in[5];
    const float* aqkv_w   = (const float*)d_in[6];
    const float* aqkv_b   = (const float*)d_in[7];
    const float* aout_w   = (const float*)d_in[8];
    const float* aout_b   = (const float*)d_in[9];
    const float* adp_pos  = (const float*)d_in[10];
    const float* gsh_w    = (const float*)d_in[11];
    const float* gsh_b    = (const float*)d_in[12];
    const float* gnode_w  = (const float*)d_in[13];
    const float* gnode_b  = (const float*)d_in[14];
    const float* gedge_w  = (const float*)d_in[15];
    const float* gedge_b  = (const float*)d_in[16];
    const float* sp_w     = (const float*)d_in[17];
    const float* sp_b     = (const float*)d_in[18];
    const float* f1w1     = (const float*)d_in[19];
    const float* f1b1     = (const float*)d_in[20];
    const float* f1w2     = (const float*)d_in[21];
    const float* f1b2     = (const float*)d_in[22];
    const float* f2w1     = (const float*)d_in[23];
    const float* f2b1     = (const float*)d_in[24];
    const float* f2w2     = (const float*)d_in[25];
    const float* f2b2     = (const float*)d_in[26];
    const float* lns      = (const float*)d_in[27];
    const float* lnb      = (const float*)d_in[28];
    float* out = (float*)d_out;

    float *q = sym(g_q), *k = sym(g_k), *v = sym(g_v), *o = sym(g_o);
    float *dtw = sym(g_dtw), *ex = sym(g_ex), *res = sym(g_res), *tmp = sym(g_tmp);
    float *xp = sym(g_xp), *kp = sym(g_kp), *vp = sym(g_vp);
    float *sen = sym(g_sen), *edge = sym(g_edge), *senx = sym(g_senx);

    const int ATT_SMEM = (2 * 16 * 401 + 8 * 400) * 4;       // 64128 B
    const int FF_SMEM  = FF_SMEM_FLOATS * 4;                 // 93696 B
    cudaFuncSetAttribute(attn_full_kernel, cudaFuncAttributeMaxDynamicSharedMemorySize, ATT_SMEM);
    cudaFuncSetAttribute(ff_kernel, cudaFuncAttributeMaxDynamicSharedMemorySize, FF_SMEM);

    dim3 gBig(600, 2), gPool(96, 2), gSmall(7, 2);

    // dtw = full MHA
    gemm128_kernel<<<gBig, 256>>>(x, dqkv_w,          dqkv_b,       q, ROWS);
    gemm128_kernel<<<gBig, 256>>>(x, dqkv_w + 16384,  dqkv_b + 128, k, ROWS);
    gemm128_kernel<<<gBig, 256>>>(x, dqkv_w + 32768,  dqkv_b + 256, v, ROWS);
    attn_full_kernel<<<768, 256, ATT_SMEM>>>(q, k, v, o);
    gemm128_kernel<<<gBig, 256>>>(o, dout_w, dout_b, dtw, ROWS);

    // pooled MHA
    pool_kernel<<<6144, 128>>>(x, xp);
    gemm128_kernel<<<gBig,  256>>>(x,  aqkv_w,          aqkv_b,       q,  ROWS);
    gemm128_kernel<<<gPool, 256>>>(xp, aqkv_w + 16384,  aqkv_b + 128, kp, 6144);
    gemm128_kernel<<<gPool, 256>>>(xp, aqkv_w + 32768,  aqkv_b + 256, vp, 6144);
    attn_pool_kernel<<<768, 256>>>(q, kp, vp, adp_pos, o);
    gemm128_kernel<<<gBig, 256>>>(o, aout_w, aout_b, k, ROWS);   // oa -> k

    // sen + GEANet edge
    gemm128_kernel<<<gSmall, 256>>>(semb, sp_w, sp_b, sen, 400);
    ln_kernel<<<400, 128>>>(sen, nullptr, nullptr, nullptr, lns + 3 * 128, lnb + 3 * 128, sen);
    gemm128_kernel<<<gSmall, 256>>>(sen, gsh_w, gsh_b, edge, 400);
    gea_kernel<<<400, 128>>>(edge, gedge_w, gedge_b, senx, 1);

    // GEANet node
    gemm128_kernel<<<gBig, 256>>>(x, gsh_w, gsh_b, v, ROWS);
    gea_kernel<<<ROWS, 128>>>(v, gnode_w, gnode_b, ex, 0);

    // out = LN(x + dtw + oa + extra)
    ln_kernel<<<ROWS, 128>>>(x, dtw, k, ex, lns, lnb, res);

    // out_attn = LN(FF1(out) + out)
    ff_kernel<<<1200, 256, FF_SMEM>>>(res, nullptr, f1w1, f1b1, f1w2, f1b2, tmp);
    ln_kernel<<<ROWS, 128>>>(tmp, res, nullptr, nullptr, lns + 128, lnb + 128, dtw);  // out_attn -> dtw

    // sp = LN(FF2(out_attn * sen_extra))
    ff_kernel<<<1200, 256, FF_SMEM>>>(dtw, senx, f2w1, f2b1, f2w2, f2b2, tmp);
    ln_kernel<<<ROWS, 128>>>(tmp, nullptr, nullptr, nullptr, lns + 256, lnb + 256, ex); // sp -> ex

    // outputs
    add_kernel<<<(BIG + 255) / 256, 256>>>(dtw, ex, out, BIG);
    if (out_size >= BIG + 51200)
        copy_kernel<<<(51200 + 255) / 256, 256>>>(senx, out + BIG, 51200);
}

// round 6
// speedup vs baseline: 2.2051x; 2.2051x over previous
#include <cuda_runtime.h>

#define ROWS 38400
#define BIG  4915200

// ---------------- device scratch ----------------
__device__ float g_q[BIG];
__device__ float g_k[BIG];
__device__ float g_v[BIG];
__device__ float g_o[BIG];
__device__ float g_dtw[BIG];
__device__ float g_ex[BIG];
__device__ float g_res[BIG];
__device__ float g_tmp[BIG];
__device__ float g_hid[78643200];   // 38400 x 2048 FF hidden
__device__ float g_xp[786432];
__device__ float g_kp[786432];
__device__ float g_vp[786432];
__device__ float g_sen[51200];
__device__ float g_edge[51200];
__device__ float g_senx[51200];

// ---------------- tf32 helpers ----------------
__device__ __forceinline__ unsigned f2tf(float x) {
    unsigned u;
    asm("cvt.rna.tf32.f32 %0, %1;" : "=r"(u) : "f"(x));
    return u;
}
__device__ __forceinline__ void mma8(float* c, const unsigned* a, const unsigned* b) {
    asm volatile(
        "mma.sync.aligned.m16n8k8.row.col.f32.tf32.tf32.f32 "
        "{%0,%1,%2,%3}, {%4,%5,%6,%7}, {%8,%9}, {%0,%1,%2,%3};"
        : "+f"(c[0]), "+f"(c[1]), "+f"(c[2]), "+f"(c[3])
        : "r"(a[0]), "r"(a[1]), "r"(a[2]), "r"(a[3]), "r"(b[0]), "r"(b[1]));
}

// ---------------- tf32 tensor-core GEMM: C[MxN] = epi(A[MxK] @ W[KxN] + bias) ----------------
// block tile 128x64, 8 warps (4M x 2N), warp tile 32x32, k-chunk 32.
// mulp (optional): A row r scaled elementwise by mulp[(r%400)*128 + k] (K must be 128).
__global__ void __launch_bounds__(256) mma_gemm(
    const float* __restrict__ A, const float* __restrict__ W,
    const float* __restrict__ bias, const float* __restrict__ mulp,
    float* __restrict__ C, int M, int N, int K, int relu)
{
    __shared__ unsigned As[128 * 36];
    __shared__ unsigned Bs[64 * 36];
    const int tid = threadIdx.x;
    const int lane = tid & 31, w = tid >> 5;
    const int mw = (w & 3) * 32, nw = (w >> 2) * 32;
    const int rowBlk = blockIdx.x * 128, colBlk = blockIdx.y * 64;
    const int gp = lane >> 2, tg = lane & 3;

    float acc[2][4][4];
#pragma unroll
    for (int mt = 0; mt < 2; mt++)
#pragma unroll
        for (int nt = 0; nt < 4; nt++)
#pragma unroll
            for (int i = 0; i < 4; i++) acc[mt][nt][i] = 0.f;

    for (int k0 = 0; k0 < K; k0 += 32) {
        for (int i = tid; i < 4096; i += 256) {
            int r = i >> 5, kk = i & 31;
            int row = rowBlk + r;
            float vv = 0.f;
            if (row < M) {
                vv = A[(long long)row * K + k0 + kk];
                if (mulp) vv *= mulp[(row % 400) * 128 + k0 + kk];
            }
            As[r * 36 + kk] = f2tf(vv);
        }
        for (int i = tid; i < 2048; i += 256) {
            int kk = i >> 6, n = i & 63;
            Bs[n * 36 + kk] = f2tf(W[(long long)(k0 + kk) * N + colBlk + n]);
        }
        __syncthreads();
#pragma unroll
        for (int ks = 0; ks < 32; ks += 8) {
            unsigned a[2][4], b[4][2];
#pragma unroll
            for (int mt = 0; mt < 2; mt++) {
                int r = mw + mt * 16 + gp;
                a[mt][0] = As[r * 36 + ks + tg];
                a[mt][1] = As[(r + 8) * 36 + ks + tg];
                a[mt][2] = As[r * 36 + ks + tg + 4];
                a[mt][3] = As[(r + 8) * 36 + ks + tg + 4];
            }
#pragma unroll
            for (int nt = 0; nt < 4; nt++) {
                int n = nw + nt * 8 + gp;
                b[nt][0] = Bs[n * 36 + ks + tg];
                b[nt][1] = Bs[n * 36 + ks + tg + 4];
            }
#pragma unroll
            for (int mt = 0; mt < 2; mt++)
#pragma unroll
                for (int nt = 0; nt < 4; nt++)
                    mma8(acc[mt][nt], a[mt], b[nt]);
        }
        __syncthreads();
    }
#pragma unroll
    for (int mt = 0; mt < 2; mt++) {
        int row = rowBlk + mw + mt * 16 + gp;
#pragma unroll
        for (int nt = 0; nt < 4; nt++) {
            int col = colBlk + nw + nt * 8 + tg * 2;
            float b0 = bias[col], b1 = bias[col + 1];
            float* cp = acc[mt][nt];
            float v0 = cp[0] + b0, v1 = cp[1] + b1;
            float v2 = cp[2] + b0, v3 = cp[3] + b1;
            if (relu) {
                v0 = fmaxf(v0, 0.f); v1 = fmaxf(v1, 0.f);
                v2 = fmaxf(v2, 0.f); v3 = fmaxf(v3, 0.f);
            }
            if (row < M)     *(float2*)&C[(long long)row * N + col]       = make_float2(v0, v1);
            if (row + 8 < M) *(float2*)&C[(long long)(row + 8) * N + col] = make_float2(v2, v3);
        }
    }
}

// ---------------- LayerNorm of (a [+ b] [+ c] [+ d]) over last dim 128 ----------------
__global__ void __launch_bounds__(128) ln_kernel(
    const float* __restrict__ a, const float* __restrict__ b,
    const float* __restrict__ c, const float* __restrict__ d,
    const float* __restrict__ gamma, const float* __restrict__ beta,
    float* __restrict__ out)
{
    __shared__ float red[8];
    long long idx = (long long)blockIdx.x * 128 + threadIdx.x;
    float v = a[idx];
    if (b) v += b[idx];
    if (c) v += c[idx];
    if (d) v += d[idx];
    float s = v, ss = v * v;
#pragma unroll
    for (int o = 16; o; o >>= 1) {
        s  += __shfl_xor_sync(0xffffffffu, s,  o);
        ss += __shfl_xor_sync(0xffffffffu, ss, o);
    }
    int w = threadIdx.x >> 5;
    if ((threadIdx.x & 31) == 0) { red[w] = s; red[4 + w] = ss; }
    __syncthreads();
    s  = red[0] + red[1] + red[2] + red[3];
    ss = red[4] + red[5] + red[6] + red[7];
    float m = s * (1.f / 128.f);
    float var = ss * (1.f / 128.f) - m * m;
    float inv = rsqrtf(var + 1e-5f);
    out[idx] = (v - m) * inv * gamma[threadIdx.x] + beta[threadIdx.x];
}

// ---------------- adaptive avg pool over node axis ----------------
__global__ void __launch_bounds__(128) pool_kernel(const float* __restrict__ x, float* __restrict__ xp)
{
    int bid = blockIdx.x;
    int bt = bid >> 6, c = bid & 63;
    int s = (c * 400) >> 6;
    int e = ((c + 1) * 400 + 63) >> 6;
    float sum = 0.f;
    for (int n = s; n < e; ++n) sum += x[(bt * 400 + n) * 128 + threadIdx.x];
    xp[bid * 128 + threadIdx.x] = sum / (float)(e - s);
}

// ---------------- GEANet per row (mode 0: node permuted store, 1: edge) ----------------
__global__ void __launch_bounds__(128) gea_kernel(
    const float* __restrict__ in, const float* __restrict__ w, const float* __restrict__ bb,
    float* __restrict__ outp, int mode)
{
    __shared__ float xr[128], tmp[128], s1[16], rs[8], w0[256], w1[256], b0v[16], b1v[16];
    int tid = threadIdx.x;
    int h = tid >> 4, u = tid & 15;
    w0[tid] = w[tid];        w0[128 + tid] = w[128 + tid];
    w1[tid] = w[256 + tid];  w1[128 + tid] = w[384 + tid];
    if (tid < 16) { b0v[tid] = bb[tid]; b1v[tid] = bb[16 + tid]; }
    int id = blockIdx.x;
    if (mode == 0) xr[tid] = in[id * 128 + tid];
    else           xr[tid] = in[id * 128 + u * 8 + h];
    __syncthreads();

    float a = b0v[u];
#pragma unroll
    for (int k = 0; k < 16; k++) a += xr[h * 16 + k] * w0[k * 16 + u];
    tmp[tid] = a;
    __syncthreads();
    float m = tmp[u];
#pragma unroll
    for (int hh = 1; hh < 8; hh++) m = fmaxf(m, tmp[hh * 16 + u]);
    float ev = __expf(a - m);
    __syncthreads();
    tmp[tid] = ev;
    __syncthreads();
    if (tid < 16) { float s = 0.f; for (int hh = 0; hh < 8; hh++) s += tmp[hh * 16 + tid]; s1[tid] = s; }
    __syncthreads();
    float vv = ev / s1[u];
    __syncthreads();
    tmp[tid] = vv;
    __syncthreads();
    if (tid < 8) { float s = 0.f; for (int uu = 0; uu < 16; uu++) s += tmp[tid * 16 + uu]; rs[tid] = s; }
    __syncthreads();
    float dn = vv / rs[h];
    __syncthreads();
    tmp[tid] = dn;
    __syncthreads();
    float o = b1v[u];
#pragma unroll
    for (int k = 0; k < 16; k++) o += tmp[h * 16 + k] * w1[k * 16 + u];

    if (mode == 0) {
        int b = id / 4800, r2 = id % 4800, t = r2 / 400, n = r2 % 400;
        outp[((b * 400 + n) * 12 + t) * 128 + tid] = o;
    } else {
        outp[id * 128 + tid] = o;
    }
}

// ---------------- full attention, 400 keys ----------------
__global__ void __launch_bounds__(256) attn_full_kernel(
    const float* __restrict__ q, const float* __restrict__ k, const float* __restrict__ v,
    float* __restrict__ o)
{
    extern __shared__ float sm[];
    float* Ks = sm;
    float* Vs = sm + 16 * 401;
    float* pball = sm + 2 * 16 * 401;
    int bid = blockIdx.x;
    int bt = bid >> 3, h = bid & 7;
    int tid = threadIdx.x;
    int base = bt * 400 * 128 + h * 16;
    for (int i = tid; i < 6400; i += 256) {
        int kk = i >> 4, d = i & 15;
        Ks[d * 401 + kk] = k[base + kk * 128 + d];
        Vs[d * 401 + kk] = v[base + kk * 128 + d];
    }
    __syncthreads();
    int warp = tid >> 5, lane = tid & 31;
    float* pb = pball + warp * 400;
    for (int qi = warp; qi < 400; qi += 8) {
        float qd[16];
#pragma unroll
        for (int d = 0; d < 16; d++) qd[d] = q[base + qi * 128 + d];
        float sc[13];
        float m = -3.4e38f;
#pragma unroll
        for (int j = 0; j < 13; j++) {
            int kk = lane + j * 32;
            float s = -3.4e38f;
            if (kk < 400) {
                s = 0.f;
#pragma unroll
                for (int d = 0; d < 16; d++) s += qd[d] * Ks[d * 401 + kk];
                s *= 0.25f;
            }
            sc[j] = s;
            m = fmaxf(m, s);
        }
#pragma unroll
        for (int off = 16; off; off >>= 1) m = fmaxf(m, __shfl_xor_sync(0xffffffffu, m, off));
        float lsum = 0.f;
#pragma unroll
        for (int j = 0; j < 13; j++) {
            int kk = lane + j * 32;
            if (kk < 400) { float p = __expf(sc[j] - m); sc[j] = p; lsum += p; }
        }
#pragma unroll
        for (int off = 16; off; off >>= 1) lsum += __shfl_xor_sync(0xffffffffu, lsum, off);
#pragma unroll
        for (int j = 0; j < 13; j++) {
            int kk = lane + j * 32;
            if (kk < 400) pb[kk] = sc[j];
        }
        __syncwarp();
        // even/odd split: bank offset between halves = 1 -> conflict-free
        int d = lane & 15, half = lane >> 4;
        const float* Vrow = Vs + d * 401;
        float acc = 0.f;
#pragma unroll 4
        for (int i = 0; i < 200; ++i) { int c = 2 * i + half; acc += pb[c] * Vrow[c]; }
        acc += __shfl_xor_sync(0xffffffffu, acc, 16);
        if (lane < 16) o[base + qi * 128 + d] = acc / lsum;
        __syncwarp();
    }
}

// ---------------- pooled attention, 64 keys + positional bias ----------------
__global__ void __launch_bounds__(256) attn_pool_kernel(
    const float* __restrict__ q, const float* __restrict__ kp, const float* __restrict__ vp,
    const float* __restrict__ pos, float* __restrict__ o)
{
    __shared__ float Ks[16 * 65], Vs[16 * 65], pball[8 * 64];
    int bid = blockIdx.x;
    int bt = bid >> 3, h = bid & 7;
    int tid = threadIdx.x;
    int kbase = bt * 64 * 128 + h * 16;
    int qbase = bt * 400 * 128 + h * 16;
    for (int i = tid; i < 1024; i += 256) {
        int kk = i >> 4, d = i & 15;
        Ks[d * 65 + kk] = kp[kbase + kk * 128 + d];
        Vs[d * 65 + kk] = vp[kbase + kk * 128 + d];
    }
    __syncthreads();
    int warp = tid >> 5, lane = tid & 31;
    float* pb = pball + warp * 64;
    for (int qi = warp; qi < 400; qi += 8) {
        float qd[16];
#pragma unroll
        for (int d = 0; d < 16; d++) qd[d] = q[qbase + qi * 128 + d];
        float sc[2];
        float m = -3.4e38f;
#pragma unroll
        for (int j = 0; j < 2; j++) {
            int kk = lane + 32 * j;
            float s = 0.f;
#pragma unroll
            for (int d = 0; d < 16; d++) s += qd[d] * Ks[d * 65 + kk];
            s = s * 0.25f + pos[qi * 64 + kk];
            sc[j] = s; m = fmaxf(m, s);
        }
#pragma unroll
        for (int off = 16; off; off >>= 1) m = fmaxf(m, __shfl_xor_sync(0xffffffffu, m, off));
        float lsum = 0.f;
#pragma unroll
        for (int j = 0; j < 2; j++) { float p = __expf(sc[j] - m); sc[j] = p; lsum += p; }
#pragma unroll
        for (int off = 16; off; off >>= 1) lsum += __shfl_xor_sync(0xffffffffu, lsum, off);
        pb[lane] = sc[0]; pb[lane + 32] = sc[1];
        __syncwarp();
        int d = lane & 15, half = lane >> 4;
        float acc = 0.f;
#pragma unroll
        for (int i = 0; i < 32; ++i) { int c = 2 * i + half; acc += pb[c] * Vs[d * 65 + c]; }
        acc += __shfl_xor_sync(0xffffffffu, acc, 16);
        if (lane < 16) o[qbase + qi * 128 + d] = acc / lsum;
        __syncwarp();
    }
}

// ---------------- final add + copy sen_extra ----------------
__global__ void add_kernel(const float* __restrict__ a, const float* __restrict__ b,
                           float* __restrict__ o, int n)
{
    int i = blockIdx.x * 256 + threadIdx.x;
    if (i < n) o[i] = a[i] + b[i];
}
__global__ void copy_kernel(const float* __restrict__ a, float* __restrict__ o, int n)
{
    int i = blockIdx.x * 256 + threadIdx.x;
    if (i < n) o[i] = a[i];
}

// ---------------- host ----------------
static float* sym(const void* s) { void* p = nullptr; cudaGetSymbolAddress(&p, s); return (float*)p; }

extern "C" void kernel_launch(void* const* d_in, const int* in_sizes, int n_in,
                              void* d_out, int out_size)
{
    const float* x      = (const float*)d_in[0];
    const float* semb   = (const float*)d_in[1];
    const float* dqkv_w = (const float*)d_in[2];
    const float* dqkv_b = (const float*)d_in[3];
    const float* dout_w = (const float*)d_in[4];
    const float* dout_b = (const float*)d_in[5];
    const float* aqkv_w = (const float*)d_in[6];
    const float* aqkv_b = (const float*)d_in[7];
    const float* aout_w = (const float*)d_in[8];
    const float* aout_b = (const float*)d_in[9];
    const float* adp_pos= (const float*)d_in[10];
    const float* gsh_w  = (const float*)d_in[11];
    const float* gsh_b  = (const float*)d_in[12];
    const float* gnode_w= (const float*)d_in[13];
    const float* gnode_b= (const float*)d_in[14];
    const float* gedge_w= (const float*)d_in[15];
    const float* gedge_b= (const float*)d_in[16];
    const float* sp_w   = (const float*)d_in[17];
    const float* sp_b   = (const float*)d_in[18];
    const float* f1w1   = (const float*)d_in[19];
    const float* f1b1   = (const float*)d_in[20];
    const float* f1w2   = (const float*)d_in[21];
    const float* f1b2   = (const float*)d_in[22];
    const float* f2w1   = (const float*)d_in[23];
    const float* f2b1   = (const float*)d_in[24];
    const float* f2w2   = (const float*)d_in[25];
    const float* f2b2   = (const float*)d_in[26];
    const float* lns    = (const float*)d_in[27];
    const float* lnb    = (const float*)d_in[28];
    float* out = (float*)d_out;

    float *q = sym(g_q), *k = sym(g_k), *v = sym(g_v), *o = sym(g_o);
    float *dtw = sym(g_dtw), *ex = sym(g_ex), *res = sym(g_res), *tmp = sym(g_tmp);
    float *hid = sym(g_hid);
    float *xp = sym(g_xp), *kp = sym(g_kp), *vp = sym(g_vp);
    float *sen = sym(g_sen), *edge = sym(g_edge), *senx = sym(g_senx);

    const int ATT_SMEM = (2 * 16 * 401 + 8 * 400) * 4;
    cudaFuncSetAttribute(attn_full_kernel, cudaFuncAttributeMaxDynamicSharedMemorySize, ATT_SMEM);

    dim3 gBig(300, 2), gPool(48, 2), gSmall(4, 2), gFFa(300, 32);

    // dtw = full MHA
    mma_gemm<<<gBig, 256>>>(x, dqkv_w,         dqkv_b,       nullptr, q, ROWS, 128, 128, 0);
    mma_gemm<<<gBig, 256>>>(x, dqkv_w + 16384, dqkv_b + 128, nullptr, k, ROWS, 128, 128, 0);
    mma_gemm<<<gBig, 256>>>(x, dqkv_w + 32768, dqkv_b + 256, nullptr, v, ROWS, 128, 128, 0);
    attn_full_kernel<<<768, 256, ATT_SMEM>>>(q, k, v, o);
    mma_gemm<<<gBig, 256>>>(o, dout_w, dout_b, nullptr, dtw, ROWS, 128, 128, 0);

    // pooled MHA (pool(xW+b) == (pool x)W + b)
    pool_kernel<<<6144, 128>>>(x, xp);
    mma_gemm<<<gBig,  256>>>(x,  aqkv_w,         aqkv_b,       nullptr, q,  ROWS, 128, 128, 0);
    mma_gemm<<<gPool, 256>>>(xp, aqkv_w + 16384, aqkv_b + 128, nullptr, kp, 6144, 128, 128, 0);
    mma_gemm<<<gPool, 256>>>(xp, aqkv_w + 32768, aqkv_b + 256, nullptr, vp, 6144, 128, 128, 0);
    attn_pool_kernel<<<768, 256>>>(q, kp, vp, adp_pos, o);
    mma_gemm<<<gBig, 256>>>(o, aout_w, aout_b, nullptr, k, ROWS, 128, 128, 0);   // oa -> k

    // sen + GEANet edge
    mma_gemm<<<gSmall, 256>>>(semb, sp_w, sp_b, nullptr, sen, 400, 128, 128, 0);
    ln_kernel<<<400, 128>>>(sen, nullptr, nullptr, nullptr, lns + 3 * 128, lnb + 3 * 128, sen);
    mma_gemm<<<gSmall, 256>>>(sen, gsh_w, gsh_b, nullptr, edge, 400, 128, 128, 0);
    gea_kernel<<<400, 128>>>(edge, gedge_w, gedge_b, senx, 1);

    // GEANet node
    mma_gemm<<<gBig, 256>>>(x, gsh_w, gsh_b, nullptr, v, ROWS, 128, 128, 0);
    gea_kernel<<<ROWS, 128>>>(v, gnode_w, gnode_b, ex, 0);

    // out = LN(x + dtw + oa + extra)
    ln_kernel<<<ROWS, 128>>>(x, dtw, k, ex, lns, lnb, res);

    // out_attn = LN(FF1(out) + out)
    mma_gemm<<<gFFa, 256>>>(res, f1w1, f1b1, nullptr, hid, ROWS, 2048, 128, 1);
    mma_gemm<<<gBig, 256>>>(hid, f1w2, f1b2, nullptr, tmp, ROWS, 128, 2048, 0);
    ln_kernel<<<ROWS, 128>>>(tmp, res, nullptr, nullptr, lns + 128, lnb + 128, dtw);  // out_attn -> dtw

    // sp = LN(FF2(out_attn * sen_extra))
    mma_gemm<<<gFFa, 256>>>(dtw, f2w1, f2b1, senx, hid, ROWS, 2048, 128, 1);
    mma_gemm<<<gBig, 256>>>(hid, f2w2, f2b2, nullptr, tmp, ROWS, 128, 2048, 0);
    ln_kernel<<<ROWS, 128>>>(tmp, nullptr, nullptr, nullptr, lns + 256, lnb + 256, ex); // sp -> ex

    // outputs
    add_kernel<<<(BIG + 255) / 256, 256>>>(dtw, ex, out, BIG);
    if (out_size >= BIG + 51200)
        copy_kernel<<<(51200 + 255) / 256, 256>>>(senx, out + BIG, 51200);
}

// round 7
// speedup vs baseline: 2.9765x; 1.3498x over previous
#include <cuda_runtime.h>

#define ROWS 38400
#define BIG  4915200

// ---------------- device scratch ----------------
__device__ float g_q[BIG];
__device__ float g_k[BIG];
__device__ float g_v[BIG];
__device__ float g_o[BIG];
__device__ float g_dtw[BIG];
__device__ float g_ex[BIG];
__device__ float g_res[BIG];
__device__ float g_tmp[BIG];
__device__ float g_hid[78643200];   // 38400 x 2048 FF hidden
__device__ float g_xp[786432];
__device__ float g_kp[786432];
__device__ float g_vp[786432];
__device__ float g_sen[51200];
__device__ float g_edge[51200];
__device__ float g_senx[51200];

// ---------------- tf32 helpers ----------------
__device__ __forceinline__ unsigned f2tf(float x) {
    unsigned u;
    asm("cvt.rna.tf32.f32 %0, %1;" : "=r"(u) : "f"(x));
    return u;
}
__device__ __forceinline__ void mma8(float* c, const unsigned* a, const unsigned* b) {
    asm volatile(
        "mma.sync.aligned.m16n8k8.row.col.f32.tf32.tf32.f32 "
        "{%0,%1,%2,%3}, {%4,%5,%6,%7}, {%8,%9}, {%0,%1,%2,%3};"
        : "+f"(c[0]), "+f"(c[1]), "+f"(c[2]), "+f"(c[3])
        : "r"(a[0]), "r"(a[1]), "r"(a[2]), "r"(a[3]), "r"(b[0]), "r"(b[1]));
}

// ---------------- tf32 GEMM, double-buffered: C = epi(A[MxK] @ W[KxN] + bias) ----------------
// block tile 128x64, 8 warps (4M x 2N), warp tile 32x32, k-chunk 32, 2 SMEM stages.
__global__ void __launch_bounds__(256) mma_gemm(
    const float* __restrict__ A, const float* __restrict__ W,
    const float* __restrict__ bias, const float* __restrict__ mulp,
    float* __restrict__ C, int M, int N, int K, int relu)
{
    extern __shared__ unsigned smu[];
    unsigned* As = smu;            // 2 x 128*36
    unsigned* Bs = smu + 2 * 4608; // 2 x 64*36
    const int tid = threadIdx.x;
    const int lane = tid & 31, w = tid >> 5;
    const int mw = (w & 3) * 32, nw = (w >> 2) * 32;
    const int rowBlk = blockIdx.x * 128, colBlk = blockIdx.y * 64;
    const int gp = lane >> 2, tg = lane & 3;

    float acc[2][4][4];
#pragma unroll
    for (int mt = 0; mt < 2; mt++)
#pragma unroll
        for (int nt = 0; nt < 4; nt++)
#pragma unroll
            for (int i = 0; i < 4; i++) acc[mt][nt][i] = 0.f;

    float ar[16], br[8];
    const int T = K >> 5;

    auto ldT = [&](int t) {
        int k0 = t * 32;
#pragma unroll
        for (int i = 0; i < 16; i++) {
            int idx = tid + i * 256;
            int r = idx >> 5, kk = idx & 31;
            int row = rowBlk + r;
            float vv = 0.f;
            if (row < M) {
                vv = A[(long long)row * K + k0 + kk];
                if (mulp) vv *= mulp[(row % 400) * 128 + k0 + kk];
            }
            ar[i] = vv;
        }
#pragma unroll
        for (int i = 0; i < 8; i++) {
            int idx = tid + i * 256;
            int kk = idx >> 6, n = idx & 63;
            br[i] = W[(long long)(k0 + kk) * N + colBlk + n];
        }
    };
    auto stT = [&](int s) {
        unsigned* Ad = As + s * 4608;
        unsigned* Bd = Bs + s * 2304;
#pragma unroll
        for (int i = 0; i < 16; i++) {
            int idx = tid + i * 256;
            Ad[(idx >> 5) * 36 + (idx & 31)] = f2tf(ar[i]);
        }
#pragma unroll
        for (int i = 0; i < 8; i++) {
            int idx = tid + i * 256;
            Bd[(idx & 63) * 36 + (idx >> 6)] = f2tf(br[i]);
        }
    };

    ldT(0); stT(0);
    __syncthreads();
    for (int t = 0; t < T; t++) {
        if (t + 1 < T) ldT(t + 1);
        unsigned* Ad = As + (t & 1) * 4608;
        unsigned* Bd = Bs + (t & 1) * 2304;
#pragma unroll
        for (int ks = 0; ks < 32; ks += 8) {
            unsigned a[2][4], b[4][2];
#pragma unroll
            for (int mt = 0; mt < 2; mt++) {
                int r = mw + mt * 16 + gp;
                a[mt][0] = Ad[r * 36 + ks + tg];
                a[mt][1] = Ad[(r + 8) * 36 + ks + tg];
                a[mt][2] = Ad[r * 36 + ks + tg + 4];
                a[mt][3] = Ad[(r + 8) * 36 + ks + tg + 4];
            }
#pragma unroll
            for (int nt = 0; nt < 4; nt++) {
                int n = nw + nt * 8 + gp;
                b[nt][0] = Bd[n * 36 + ks + tg];
                b[nt][1] = Bd[n * 36 + ks + tg + 4];
            }
#pragma unroll
            for (int mt = 0; mt < 2; mt++)
#pragma unroll
                for (int nt = 0; nt < 4; nt++)
                    mma8(acc[mt][nt], a[mt], b[nt]);
        }
        if (t + 1 < T) stT((t + 1) & 1);
        __syncthreads();
    }
#pragma unroll
    for (int mt = 0; mt < 2; mt++) {
        int row = rowBlk + mw + mt * 16 + gp;
#pragma unroll
        for (int nt = 0; nt < 4; nt++) {
            int col = colBlk + nw + nt * 8 + tg * 2;
            float b0 = bias[col], b1 = bias[col + 1];
            float* cp = acc[mt][nt];
            float v0 = cp[0] + b0, v1 = cp[1] + b1;
            float v2 = cp[2] + b0, v3 = cp[3] + b1;
            if (relu) {
                v0 = fmaxf(v0, 0.f); v1 = fmaxf(v1, 0.f);
                v2 = fmaxf(v2, 0.f); v3 = fmaxf(v3, 0.f);
            }
            if (row < M)     *(float2*)&C[(long long)row * N + col]       = make_float2(v0, v1);
            if (row + 8 < M) *(float2*)&C[(long long)(row + 8) * N + col] = make_float2(v2, v3);
        }
    }
}

// ---------------- tensor-core full attention (400 keys) ----------------
// SMEM floats: Kt[400*17] | Vt[16*401] | S[32*401] | Qs[32*17] | ls[32]
#define ATT_TC_FLOATS (400 * 17 + 16 * 401 + 32 * 401 + 32 * 17 + 32)
__global__ void __launch_bounds__(256) attn_tc_kernel(
    const float* __restrict__ q, const float* __restrict__ k, const float* __restrict__ v,
    float* __restrict__ o)
{
    extern __shared__ float sm[];
    unsigned* Kt = (unsigned*)sm;                       // [400][17] tf32
    unsigned* Vt = (unsigned*)sm + 400 * 17;            // [16][401] tf32 (d-major)
    float*    S  = sm + 400 * 17 + 16 * 401;            // [32][401]
    unsigned* Qs = (unsigned*)(S + 32 * 401);           // [32][17] tf32
    float*    ls = (float*)(Qs + 32 * 17);              // [32]
    int bid = blockIdx.x, bt = bid >> 3, h = bid & 7;
    int tid = threadIdx.x, lane = tid & 31, w = tid >> 5;
    int gp = lane >> 2, tg = lane & 3;
    int base = bt * 400 * 128 + h * 16;

    for (int i = tid; i < 6400; i += 256) {
        int key = i >> 4, d = i & 15;
        float kv = k[base + key * 128 + d];
        float vv = v[base + key * 128 + d];
        Kt[key * 17 + d]  = f2tf(kv);
        Vt[d * 401 + key] = f2tf(vv);
    }
    __syncthreads();

    for (int qt = 0; qt < 400; qt += 32) {
        for (int i = tid; i < 512; i += 256) {
            int r = i >> 4, d = i & 15;
            int qr = qt + r;
            Qs[r * 17 + d] = f2tf(qr < 400 ? q[base + qr * 128 + d] : 0.f);
        }
        __syncthreads();
        // phase 1: S = 0.25 * Q K^T   (2 m-tiles x 50 n-tiles over 8 warps)
        for (int p = w; p < 100; p += 8) {
            int mt = p & 1, nt = p >> 1;
            float c[4] = {0.f, 0.f, 0.f, 0.f};
#pragma unroll
            for (int ks = 0; ks < 16; ks += 8) {
                unsigned a[4], b[2];
                a[0] = Qs[(mt * 16 + gp) * 17 + ks + tg];
                a[1] = Qs[(mt * 16 + gp + 8) * 17 + ks + tg];
                a[2] = Qs[(mt * 16 + gp) * 17 + ks + tg + 4];
                a[3] = Qs[(mt * 16 + gp + 8) * 17 + ks + tg + 4];
                b[0] = Kt[(nt * 8 + gp) * 17 + ks + tg];
                b[1] = Kt[(nt * 8 + gp) * 17 + ks + tg + 4];
                mma8(c, a, b);
            }
            int r0 = mt * 16 + gp, cc = nt * 8 + tg * 2;
            S[r0 * 401 + cc]       = c[0] * 0.25f;
            S[r0 * 401 + cc + 1]   = c[1] * 0.25f;
            S[(r0 + 8) * 401 + cc]     = c[2] * 0.25f;
            S[(r0 + 8) * 401 + cc + 1] = c[3] * 0.25f;
        }
        __syncthreads();
        // phase 2: row softmax, store P as tf32 in place
        for (int rr = 0; rr < 4; rr++) {
            int row = w * 4 + rr;
            float sc[13];
            float m = -3.4e38f;
#pragma unroll
            for (int j = 0; j < 13; j++) {
                int kk = lane + j * 32;
                float s_ = (kk < 400) ? S[row * 401 + kk] : -3.4e38f;
                sc[j] = s_; m = fmaxf(m, s_);
            }
#pragma unroll
            for (int off = 16; off; off >>= 1) m = fmaxf(m, __shfl_xor_sync(0xffffffffu, m, off));
            float l = 0.f;
#pragma unroll
            for (int j = 0; j < 13; j++) {
                int kk = lane + j * 32;
                if (kk < 400) {
                    float p_ = __expf(sc[j] - m);
                    ((unsigned*)S)[row * 401 + kk] = f2tf(p_);
                    l += p_;
                }
            }
#pragma unroll
            for (int off = 16; off; off >>= 1) l += __shfl_xor_sync(0xffffffffu, l, off);
            if (lane == 0) ls[row] = 1.f / l;
        }
        __syncthreads();
        // phase 3: O = P @ V  (4 warps: 2 m-tiles x 2 n-tiles, K=400)
        if (w < 4) {
            int mt = w & 1, nt = w >> 1;
            const unsigned* Pt = (const unsigned*)S;
            float c[4] = {0.f, 0.f, 0.f, 0.f};
            for (int k0 = 0; k0 < 400; k0 += 8) {
                unsigned a[4], b[2];
                a[0] = Pt[(mt * 16 + gp) * 401 + k0 + tg];
                a[1] = Pt[(mt * 16 + gp + 8) * 401 + k0 + tg];
                a[2] = Pt[(mt * 16 + gp) * 401 + k0 + tg + 4];
                a[3] = Pt[(mt * 16 + gp + 8) * 401 + k0 + tg + 4];
                b[0] = Vt[(nt * 8 + gp) * 401 + k0 + tg];
                b[1] = Vt[(nt * 8 + gp) * 401 + k0 + tg + 4];
                mma8(c, a, b);
            }
            int r0 = mt * 16 + gp, d0 = nt * 8 + tg * 2;
            int qr0 = qt + r0, qr1 = qt + r0 + 8;
            if (qr0 < 400) {
                o[base + qr0 * 128 + d0]     = c[0] * ls[r0];
                o[base + qr0 * 128 + d0 + 1] = c[1] * ls[r0];
            }
            if (qr1 < 400) {
                o[base + qr1 * 128 + d0]     = c[2] * ls[r0 + 8];
                o[base + qr1 * 128 + d0 + 1] = c[3] * ls[r0 + 8];
            }
        }
        __syncthreads();
    }
}

// ---------------- LayerNorm of (a [+ b] [+ c] [+ d]) over last dim 128 ----------------
__global__ void __launch_bounds__(128) ln_kernel(
    const float* __restrict__ a, const float* __restrict__ b,
    const float* __restrict__ c, const float* __restrict__ d,
    const float* __restrict__ gamma, const float* __restrict__ beta,
    float* __restrict__ out)
{
    __shared__ float red[8];
    long long idx = (long long)blockIdx.x * 128 + threadIdx.x;
    float v = a[idx];
    if (b) v += b[idx];
    if (c) v += c[idx];
    if (d) v += d[idx];
    float s = v, ss = v * v;
#pragma unroll
    for (int o = 16; o; o >>= 1) {
        s  += __shfl_xor_sync(0xffffffffu, s,  o);
        ss += __shfl_xor_sync(0xffffffffu, ss, o);
    }
    int w = threadIdx.x >> 5;
    if ((threadIdx.x & 31) == 0) { red[w] = s; red[4 + w] = ss; }
    __syncthreads();
    s  = red[0] + red[1] + red[2] + red[3];
    ss = red[4] + red[5] + red[6] + red[7];
    float m = s * (1.f / 128.f);
    float var = ss * (1.f / 128.f) - m * m;
    float inv = rsqrtf(var + 1e-5f);
    out[idx] = (v - m) * inv * gamma[threadIdx.x] + beta[threadIdx.x];
}

// ---------------- adaptive avg pool over node axis ----------------
__global__ void __launch_bounds__(128) pool_kernel(const float* __restrict__ x, float* __restrict__ xp)
{
    int bid = blockIdx.x;
    int bt = bid >> 6, c = bid & 63;
    int s = (c * 400) >> 6;
    int e = ((c + 1) * 400 + 63) >> 6;
    float sum = 0.f;
    for (int n = s; n < e; ++n) sum += x[(bt * 400 + n) * 128 + threadIdx.x];
    xp[bid * 128 + threadIdx.x] = sum / (float)(e - s);
}

// ---------------- GEANet per row (mode 0: node permuted store, 1: edge) ----------------
__global__ void __launch_bounds__(128) gea_kernel(
    const float* __restrict__ in, const float* __restrict__ w, const float* __restrict__ bb,
    float* __restrict__ outp, int mode)
{
    __shared__ float xr[128], tmp[128], s1[16], rs[8], w0[256], w1[256], b0v[16], b1v[16];
    int tid = threadIdx.x;
    int h = tid >> 4, u = tid & 15;
    w0[tid] = w[tid];        w0[128 + tid] = w[128 + tid];
    w1[tid] = w[256 + tid];  w1[128 + tid] = w[384 + tid];
    if (tid < 16) { b0v[tid] = bb[tid]; b1v[tid] = bb[16 + tid]; }
    int id = blockIdx.x;
    if (mode == 0) xr[tid] = in[id * 128 + tid];
    else           xr[tid] = in[id * 128 + u * 8 + h];
    __syncthreads();

    float a = b0v[u];
#pragma unroll
    for (int k = 0; k < 16; k++) a += xr[h * 16 + k] * w0[k * 16 + u];
    tmp[tid] = a;
    __syncthreads();
    float m = tmp[u];
#pragma unroll
    for (int hh = 1; hh < 8; hh++) m = fmaxf(m, tmp[hh * 16 + u]);
    float ev = __expf(a - m);
    __syncthreads();
    tmp[tid] = ev;
    __syncthreads();
    if (tid < 16) { float s = 0.f; for (int hh = 0; hh < 8; hh++) s += tmp[hh * 16 + tid]; s1[tid] = s; }
    __syncthreads();
    float vv = ev / s1[u];
    __syncthreads();
    tmp[tid] = vv;
    __syncthreads();
    if (tid < 8) { float s = 0.f; for (int uu = 0; uu < 16; uu++) s += tmp[tid * 16 + uu]; rs[tid] = s; }
    __syncthreads();
    float dn = vv / rs[h];
    __syncthreads();
    tmp[tid] = dn;
    __syncthreads();
    float o = b1v[u];
#pragma unroll
    for (int k = 0; k < 16; k++) o += tmp[h * 16 + k] * w1[k * 16 + u];

    if (mode == 0) {
        int b = id / 4800, r2 = id % 4800, t = r2 / 400, n = r2 % 400;
        outp[((b * 400 + n) * 12 + t) * 128 + tid] = o;
    } else {
        outp[id * 128 + tid] = o;
    }
}

// ---------------- pooled attention, 64 keys + positional bias ----------------
__global__ void __launch_bounds__(256) attn_pool_kernel(
    const float* __restrict__ q, const float* __restrict__ kp, const float* __restrict__ vp,
    const float* __restrict__ pos, float* __restrict__ o)
{
    __shared__ float Ks[16 * 65], Vs[16 * 65], pball[8 * 64];
    int bid = blockIdx.x;
    int bt = bid >> 3, h = bid & 7;
    int tid = threadIdx.x;
    int kbase = bt * 64 * 128 + h * 16;
    int qbase = bt * 400 * 128 + h * 16;
    for (int i = tid; i < 1024; i += 256) {
        int kk = i >> 4, d = i & 15;
        Ks[d * 65 + kk] = kp[kbase + kk * 128 + d];
        Vs[d * 65 + kk] = vp[kbase + kk * 128 + d];
    }
    __syncthreads();
    int warp = tid >> 5, lane = tid & 31;
    float* pb = pball + warp * 64;
    for (int qi = warp; qi < 400; qi += 8) {
        float qd[16];
#pragma unroll
        for (int d = 0; d < 16; d++) qd[d] = q[qbase + qi * 128 + d];
        float sc[2];
        float m = -3.4e38f;
#pragma unroll
        for (int j = 0; j < 2; j++) {
            int kk = lane + 32 * j;
            float s = 0.f;
#pragma unroll
            for (int d = 0; d < 16; d++) s += qd[d] * Ks[d * 65 + kk];
            s = s * 0.25f + pos[qi * 64 + kk];
            sc[j] = s; m = fmaxf(m, s);
        }
#pragma unroll
        for (int off = 16; off; off >>= 1) m = fmaxf(m, __shfl_xor_sync(0xffffffffu, m, off));
        float lsum = 0.f;
#pragma unroll
        for (int j = 0; j < 2; j++) { float p = __expf(sc[j] - m); sc[j] = p; lsum += p; }
#pragma unroll
        for (int off = 16; off; off >>= 1) lsum += __shfl_xor_sync(0xffffffffu, lsum, off);
        pb[lane] = sc[0]; pb[lane + 32] = sc[1];
        __syncwarp();
        int d = lane & 15, half = lane >> 4;
        float acc = 0.f;
#pragma unroll
        for (int i = 0; i < 32; ++i) { int c = 2 * i + half; acc += pb[c] * Vs[d * 65 + c]; }
        acc += __shfl_xor_sync(0xffffffffu, acc, 16);
        if (lane < 16) o[qbase + qi * 128 + d] = acc / lsum;
        __syncwarp();
    }
}

// ---------------- final add + copy sen_extra ----------------
__global__ void add_kernel(const float* __restrict__ a, const float* __restrict__ b,
                           float* __restrict__ o, int n)
{
    int i = blockIdx.x * 256 + threadIdx.x;
    if (i < n) o[i] = a[i] + b[i];
}
__global__ void copy_kernel(const float* __restrict__ a, float* __restrict__ o, int n)
{
    int i = blockIdx.x * 256 + threadIdx.x;
    if (i < n) o[i] = a[i];
}

// ---------------- host ----------------
static float* sym(const void* s) { void* p = nullptr; cudaGetSymbolAddress(&p, s); return (float*)p; }

extern "C" void kernel_launch(void* const* d_in, const int* in_sizes, int n_in,
                              void* d_out, int out_size)
{
    const float* x      = (const float*)d_in[0];
    const float* semb   = (const float*)d_in[1];
    const float* dqkv_w = (const float*)d_in[2];
    const float* dqkv_b = (const float*)d_in[3];
    const float* dout_w = (const float*)d_in[4];
    const float* dout_b = (const float*)d_in[5];
    const float* aqkv_w = (const float*)d_in[6];
    const float* aqkv_b = (const float*)d_in[7];
    const float* aout_w = (const float*)d_in[8];
    const float* aout_b = (const float*)d_in[9];
    const float* adp_pos= (const float*)d_in[10];
    const float* gsh_w  = (const float*)d_in[11];
    const float* gsh_b  = (const float*)d_in[12];
    const float* gnode_w= (const float*)d_in[13];
    const float* gnode_b= (const float*)d_in[14];
    const float* gedge_w= (const float*)d_in[15];
    const float* gedge_b= (const float*)d_in[16];
    const float* sp_w   = (const float*)d_in[17];
    const float* sp_b   = (const float*)d_in[18];
    const float* f1w1   = (const float*)d_in[19];
    const float* f1b1   = (const float*)d_in[20];
    const float* f1w2   = (const float*)d_in[21];
    const float* f1b2   = (const float*)d_in[22];
    const float* f2w1   = (const float*)d_in[23];
    const float* f2b1   = (const float*)d_in[24];
    const float* f2w2   = (const float*)d_in[25];
    const float* f2b2   = (const float*)d_in[26];
    const float* lns    = (const float*)d_in[27];
    const float* lnb    = (const float*)d_in[28];
    float* out = (float*)d_out;

    float *q = sym(g_q), *k = sym(g_k), *v = sym(g_v), *o = sym(g_o);
    float *dtw = sym(g_dtw), *ex = sym(g_ex), *res = sym(g_res), *tmp = sym(g_tmp);
    float *hid = sym(g_hid);
    float *xp = sym(g_xp), *kp = sym(g_kp), *vp = sym(g_vp);
    float *sen = sym(g_sen), *edge = sym(g_edge), *senx = sym(g_senx);

    const int GEMM_SMEM = (2 * 4608 + 2 * 2304) * 4;      // 55296 B
    const int ATT_SMEM  = ATT_TC_FLOATS * 4;              // 106496 B
    cudaFuncSetAttribute(mma_gemm, cudaFuncAttributeMaxDynamicSharedMemorySize, GEMM_SMEM);
    cudaFuncSetAttribute(attn_tc_kernel, cudaFuncAttributeMaxDynamicSharedMemorySize, ATT_SMEM);

    dim3 gBig(300, 2), gPool(48, 2), gSmall(4, 2), gFFa(300, 32);

    // dtw = full MHA
    mma_gemm<<<gBig, 256, GEMM_SMEM>>>(x, dqkv_w,         dqkv_b,       nullptr, q, ROWS, 128, 128, 0);
    mma_gemm<<<gBig, 256, GEMM_SMEM>>>(x, dqkv_w + 16384, dqkv_b + 128, nullptr, k, ROWS, 128, 128, 0);
    mma_gemm<<<gBig, 256, GEMM_SMEM>>>(x, dqkv_w + 32768, dqkv_b + 256, nullptr, v, ROWS, 128, 128, 0);
    attn_tc_kernel<<<768, 256, ATT_SMEM>>>(q, k, v, o);
    mma_gemm<<<gBig, 256, GEMM_SMEM>>>(o, dout_w, dout_b, nullptr, dtw, ROWS, 128, 128, 0);

    // pooled MHA (pool(xW+b) == (pool x)W + b)
    pool_kernel<<<6144, 128>>>(x, xp);
    mma_gemm<<<gBig,  256, GEMM_SMEM>>>(x,  aqkv_w,         aqkv_b,       nullptr, q,  ROWS, 128, 128, 0);
    mma_gemm<<<gPool, 256, GEMM_SMEM>>>(xp, aqkv_w + 16384, aqkv_b + 128, nullptr, kp, 6144, 128, 128, 0);
    mma_gemm<<<gPool, 256, GEMM_SMEM>>>(xp, aqkv_w + 32768, aqkv_b + 256, nullptr, vp, 6144, 128, 128, 0);
    attn_pool_kernel<<<768, 256>>>(q, kp, vp, adp_pos, o);
    mma_gemm<<<gBig, 256, GEMM_SMEM>>>(o, aout_w, aout_b, nullptr, k, ROWS, 128, 128, 0);   // oa -> k

    // sen + GEANet edge
    mma_gemm<<<gSmall, 256, GEMM_SMEM>>>(semb, sp_w, sp_b, nullptr, sen, 400, 128, 128, 0);
    ln_kernel<<<400, 128>>>(sen, nullptr, nullptr, nullptr, lns + 3 * 128, lnb + 3 * 128, sen);
    mma_gemm<<<gSmall, 256, GEMM_SMEM>>>(sen, gsh_w, gsh_b, nullptr, edge, 400, 128, 128, 0);
    gea_kernel<<<400, 128>>>(edge, gedge_w, gedge_b, senx, 1);

    // GEANet node
    mma_gemm<<<gBig, 256, GEMM_SMEM>>>(x, gsh_w, gsh_b, nullptr, v, ROWS, 128, 128, 0);
    gea_kernel<<<ROWS, 128>>>(v, gnode_w, gnode_b, ex, 0);

    // out = LN(x + dtw + oa + extra)
    ln_kernel<<<ROWS, 128>>>(x, dtw, k, ex, lns, lnb, res);

    // out_attn = LN(FF1(out) + out)
    mma_gemm<<<gFFa, 256, GEMM_SMEM>>>(res, f1w1, f1b1, nullptr, hid, ROWS, 2048, 128, 1);
    mma_gemm<<<gBig, 256, GEMM_SMEM>>>(hid, f1w2, f1b2, nullptr, tmp, ROWS, 128, 2048, 0);
    ln_kernel<<<ROWS, 128>>>(tmp, res, nullptr, nullptr, lns + 128, lnb + 128, dtw);  // out_attn -> dtw

    // sp = LN(FF2(out_attn * sen_extra))
    mma_gemm<<<gFFa, 256, GEMM_SMEM>>>(dtw, f2w1, f2b1, senx, hid, ROWS, 2048, 128, 1);
    mma_gemm<<<gBig, 256, GEMM_SMEM>>>(hid, f2w2, f2b2, nullptr, tmp, ROWS, 128, 2048, 0);
    ln_kernel<<<ROWS, 128>>>(tmp, nullptr, nullptr, nullptr, lns + 256, lnb + 256, ex); // sp -> ex

    // outputs
    add_kernel<<<(BIG + 255) / 256, 256>>>(dtw, ex, out, BIG);
    if (out_size >= BIG + 51200)
        copy_kernel<<<(51200 + 255) / 256, 256>>>(senx, out + BIG, 51200);
}

// round 8
// speedup vs baseline: 4.7531x; 1.5969x over previous
#include <cuda_runtime.h>

#define ROWS 38400
#define BIG  4915200

// ---------------- device scratch ----------------
__device__ float g_q[BIG];
__device__ float g_k[BIG];
__device__ float g_v[BIG];
__device__ float g_o[BIG];
__device__ float g_dtw[BIG];
__device__ float g_ex[BIG];
__device__ float g_res[BIG];
__device__ float g_tmp[BIG];
__device__ float g_hid[78643200];   // 38400 x 2048 FF hidden
__device__ float g_xp[786432];
__device__ float g_kp[786432];
__device__ float g_vp[786432];
__device__ float g_sen[51200];
__device__ float g_edge[51200];
__device__ float g_senx[51200];

// ---------------- mma / cp.async helpers ----------------
__device__ __forceinline__ void mma8(float* c, const unsigned* a, const unsigned* b) {
    asm volatile(
        "mma.sync.aligned.m16n8k8.row.col.f32.tf32.tf32.f32 "
        "{%0,%1,%2,%3}, {%4,%5,%6,%7}, {%8,%9}, {%0,%1,%2,%3};"
        : "+f"(c[0]), "+f"(c[1]), "+f"(c[2]), "+f"(c[3])
        : "r"(a[0]), "r"(a[1]), "r"(a[2]), "r"(a[3]), "r"(b[0]), "r"(b[1]));
}
__device__ __forceinline__ void cpa16(unsigned dst, const float* src, bool p) {
    int sz = p ? 16 : 0;
    asm volatile("cp.async.cg.shared.global [%0], [%1], 16, %2;"
                 :: "r"(dst), "l"(src), "r"(sz));
}
#define CP_COMMIT() asm volatile("cp.async.commit_group;")
#define CP_WAIT1()  asm volatile("cp.async.wait_group 1;")

// ---------------- tf32 GEMM, cp.async 3-stage: C = epi(A[MxK] @ W[KxN] + bias) ----------------
// block tile 128x128, 8 warps (4M x 2N), warp tile 32x64, k-chunk 32.
// SMEM floats per stage: A 128*36 = 4608, B 32*136 = 4352.
__global__ void __launch_bounds__(256) mma_gemm(
    const float* __restrict__ A, const float* __restrict__ W,
    const float* __restrict__ bias, float* __restrict__ C,
    int M, int N, int K, int relu)
{
    extern __shared__ float smf[];
    float* As = smf;                 // 3 x 4608
    float* Bs = smf + 3 * 4608;      // 3 x 4352
    const unsigned sA = (unsigned)__cvta_generic_to_shared(As);
    const unsigned sB = (unsigned)__cvta_generic_to_shared(Bs);
    const int tid = threadIdx.x;
    const int lane = tid & 31, w = tid >> 5;
    const int mw = (w >> 1) * 32, nw = (w & 1) * 64;
    const int rowBlk = blockIdx.x * 128, colBlk = blockIdx.y * 128;
    const int gp = lane >> 2, tg = lane & 3;
    const int T = K >> 5;

    float acc[2][8][4];
#pragma unroll
    for (int mt = 0; mt < 2; mt++)
#pragma unroll
        for (int nt = 0; nt < 8; nt++)
#pragma unroll
            for (int i = 0; i < 4; i++) acc[mt][nt][i] = 0.f;

    auto issue = [&](int t) {
        if (t < T) {
            int s = t % 3, k0 = t * 32;
#pragma unroll
            for (int i = 0; i < 4; i++) {
                int idx = tid + i * 256;
                int r = idx >> 3, kq = idx & 7;
                int row = rowBlk + r;
                bool p = row < M;
                int rc = p ? row : (M - 1);
                cpa16(sA + (s * 4608 + r * 36 + kq * 4) * 4,
                      A + (long long)rc * K + k0 + kq * 4, p);
            }
#pragma unroll
            for (int i = 0; i < 4; i++) {
                int idx = tid + i * 256;
                int kk = idx >> 5, nq = idx & 31;
                cpa16(sB + (s * 4352 + kk * 136 + nq * 4) * 4,
                      W + (long long)(k0 + kk) * N + colBlk + nq * 4, true);
            }
        }
        CP_COMMIT();
    };

    issue(0); issue(1);
    for (int t = 0; t < T; t++) {
        CP_WAIT1();
        __syncthreads();
        const unsigned* Ad = (const unsigned*)(As + (t % 3) * 4608);
        const unsigned* Bd = (const unsigned*)(Bs + (t % 3) * 4352);
#pragma unroll
        for (int ks = 0; ks < 32; ks += 8) {
            unsigned a[2][4], b[8][2];
#pragma unroll
            for (int mt = 0; mt < 2; mt++) {
                int r = mw + mt * 16 + gp;
                a[mt][0] = Ad[r * 36 + ks + tg];
                a[mt][1] = Ad[(r + 8) * 36 + ks + tg];
                a[mt][2] = Ad[r * 36 + ks + tg + 4];
                a[mt][3] = Ad[(r + 8) * 36 + ks + tg + 4];
            }
#pragma unroll
            for (int nt = 0; nt < 8; nt++) {
                int n = nw + nt * 8 + gp;
                b[nt][0] = Bd[(ks + tg) * 136 + n];
                b[nt][1] = Bd[(ks + tg + 4) * 136 + n];
            }
#pragma unroll
            for (int mt = 0; mt < 2; mt++)
#pragma unroll
                for (int nt = 0; nt < 8; nt++)
                    mma8(acc[mt][nt], a[mt], b[nt]);
        }
        issue(t + 2);
    }
#pragma unroll
    for (int mt = 0; mt < 2; mt++) {
        int row = rowBlk + mw + mt * 16 + gp;
#pragma unroll
        for (int nt = 0; nt < 8; nt++) {
            int col = colBlk + nw + nt * 8 + tg * 2;
            float b0 = bias[col], b1 = bias[col + 1];
            float* cp = acc[mt][nt];
            float v0 = cp[0] + b0, v1 = cp[1] + b1;
            float v2 = cp[2] + b0, v3 = cp[3] + b1;
            if (relu) {
                v0 = fmaxf(v0, 0.f); v1 = fmaxf(v1, 0.f);
                v2 = fmaxf(v2, 0.f); v3 = fmaxf(v3, 0.f);
            }
            if (row < M)     *(float2*)&C[(long long)row * N + col]       = make_float2(v0, v1);
            if (row + 8 < M) *(float2*)&C[(long long)(row + 8) * N + col] = make_float2(v2, v3);
        }
    }
}

// ---------------- tensor-core full attention (400 keys) ----------------
// SMEM floats: Kt[400*20] | Vt[16*404] | S[32*404] | Qs[32*20] | ls[32] | Po[32*68]
#define ATT_KT 0
#define ATT_VT 8000
#define ATT_S  14464
#define ATT_QS 27392
#define ATT_LS 28032
#define ATT_PO 28064
#define ATT_TC_FLOATS 30240
__global__ void __launch_bounds__(256) attn_tc_kernel(
    const float* __restrict__ q, const float* __restrict__ k, const float* __restrict__ v,
    float* __restrict__ o)
{
    extern __shared__ float sm[];
    float* Kt = sm + ATT_KT;
    float* Vt = sm + ATT_VT;
    float* S  = sm + ATT_S;
    float* Qs = sm + ATT_QS;
    float* ls = sm + ATT_LS;
    float* Po = sm + ATT_PO;
    int bid = blockIdx.x, bt = bid >> 3, h = bid & 7;
    int tid = threadIdx.x, lane = tid & 31, w = tid >> 5;
    int gp = lane >> 2, tg = lane & 3;
    int base = bt * 400 * 128 + h * 16;

    for (int i = tid; i < 6400; i += 256) {
        int key = i >> 4, d = i & 15;
        Kt[key * 20 + d]  = k[base + key * 128 + d];
        Vt[d * 404 + key] = v[base + key * 128 + d];
    }
    __syncthreads();

    const unsigned* Ku = (const unsigned*)Kt;
    const unsigned* Vu = (const unsigned*)Vt;
    const unsigned* Qu = (const unsigned*)Qs;
    const unsigned* Pu = (const unsigned*)S;

    for (int qt = 0; qt < 400; qt += 32) {
        for (int i = tid; i < 512; i += 256) {
            int r = i >> 4, d = i & 15;
            int qr = qt + r;
            Qs[r * 20 + d] = (qr < 400) ? q[base + qr * 128 + d] : 0.f;
        }
        __syncthreads();
        // phase 1: S = 0.25 * Q K^T   (hoisted Q fragments, warps stride keys)
        {
            unsigned af[2][2][4];
#pragma unroll
            for (int mt = 0; mt < 2; mt++)
#pragma unroll
                for (int ksi = 0; ksi < 2; ksi++) {
                    int r = mt * 16 + gp, ks = ksi * 8;
                    af[mt][ksi][0] = Qu[r * 20 + ks + tg];
                    af[mt][ksi][1] = Qu[(r + 8) * 20 + ks + tg];
                    af[mt][ksi][2] = Qu[r * 20 + ks + tg + 4];
                    af[mt][ksi][3] = Qu[(r + 8) * 20 + ks + tg + 4];
                }
            for (int nt = w; nt < 50; nt += 8) {
                float c0[4] = {0.f, 0.f, 0.f, 0.f};
                float c1[4] = {0.f, 0.f, 0.f, 0.f};
#pragma unroll
                for (int ksi = 0; ksi < 2; ksi++) {
                    int ks = ksi * 8;
                    unsigned b[2];
                    b[0] = Ku[(nt * 8 + gp) * 20 + ks + tg];
                    b[1] = Ku[(nt * 8 + gp) * 20 + ks + tg + 4];
                    mma8(c0, af[0][ksi], b);
                    mma8(c1, af[1][ksi], b);
                }
                int cc = nt * 8 + tg * 2;
                S[gp * 404 + cc]            = c0[0] * 0.25f;
                S[gp * 404 + cc + 1]        = c0[1] * 0.25f;
                S[(gp + 8) * 404 + cc]      = c0[2] * 0.25f;
                S[(gp + 8) * 404 + cc + 1]  = c0[3] * 0.25f;
                S[(gp + 16) * 404 + cc]     = c1[0] * 0.25f;
                S[(gp + 16) * 404 + cc + 1] = c1[1] * 0.25f;
                S[(gp + 24) * 404 + cc]     = c1[2] * 0.25f;
                S[(gp + 24) * 404 + cc + 1] = c1[3] * 0.25f;
            }
        }
        __syncthreads();
        // phase 2: row softmax (P stored back into S as fp32)
        for (int rr = 0; rr < 4; rr++) {
            int row = w * 4 + rr;
            float sc[13];
            float m = -3.4e38f;
#pragma unroll
            for (int j = 0; j < 13; j++) {
                int kk = lane + j * 32;
                float s_ = (kk < 400) ? S[row * 404 + kk] : -3.4e38f;
                sc[j] = s_; m = fmaxf(m, s_);
            }
#pragma unroll
            for (int off = 16; off; off >>= 1) m = fmaxf(m, __shfl_xor_sync(0xffffffffu, m, off));
            float l = 0.f;
#pragma unroll
            for (int j = 0; j < 13; j++) {
                int kk = lane + j * 32;
                if (kk < 400) {
                    float p_ = __expf(sc[j] - m);
                    S[row * 404 + kk] = p_;
                    l += p_;
                }
            }
#pragma unroll
            for (int off = 16; off; off >>= 1) l += __shfl_xor_sync(0xffffffffu, l, off);
            if (lane == 0) ls[row] = 1.f / l;
        }
        __syncthreads();
        // phase 3: O = P @ V, all 8 warps via split-K (two 200-key halves)
        {
            int mt = w & 1, nt = (w >> 1) & 1, kh = w >> 2;
            float c[4] = {0.f, 0.f, 0.f, 0.f};
            int kbase = kh * 200;
#pragma unroll 5
            for (int i = 0; i < 25; i++) {
                int k0 = kbase + i * 8;
                unsigned a[4], b[2];
                a[0] = Pu[(mt * 16 + gp) * 404 + k0 + tg];
                a[1] = Pu[(mt * 16 + gp + 8) * 404 + k0 + tg];
                a[2] = Pu[(mt * 16 + gp) * 404 + k0 + tg + 4];
                a[3] = Pu[(mt * 16 + gp + 8) * 404 + k0 + tg + 4];
                b[0] = Vu[(nt * 8 + gp) * 404 + k0 + tg];
                b[1] = Vu[(nt * 8 + gp) * 404 + k0 + tg + 4];
                mma8(c, a, b);
            }
            int r0 = mt * 16 + gp, d0 = nt * 8 + tg * 2;
            if (kh == 1) {
                Po[r0 * 68 + d0]           = c[0];
                Po[r0 * 68 + d0 + 1]       = c[1];
                Po[(r0 + 8) * 68 + d0]     = c[2];
                Po[(r0 + 8) * 68 + d0 + 1] = c[3];
            }
            __syncthreads();
            if (kh == 0) {
                float s0 = ls[r0], s1 = ls[r0 + 8];
                int qr0 = qt + r0, qr1 = qt + r0 + 8;
                if (qr0 < 400) {
                    o[base + qr0 * 128 + d0]     = (c[0] + Po[r0 * 68 + d0]) * s0;
                    o[base + qr0 * 128 + d0 + 1] = (c[1] + Po[r0 * 68 + d0 + 1]) * s0;
                }
                if (qr1 < 400) {
                    o[base + qr1 * 128 + d0]     = (c[2] + Po[(r0 + 8) * 68 + d0]) * s1;
                    o[base + qr1 * 128 + d0 + 1] = (c[3] + Po[(r0 + 8) * 68 + d0 + 1]) * s1;
                }
            }
        }
        __syncthreads();
    }
}

// ---------------- LayerNorm of (a [+ b] [+ c] [+ d]) over last dim 128, optional +addp ----------------
__global__ void __launch_bounds__(128) ln_kernel(
    const float* __restrict__ a, const float* __restrict__ b,
    const float* __restrict__ c, const float* __restrict__ d,
    const float* __restrict__ gamma, const float* __restrict__ beta,
    float* __restrict__ out, const float* __restrict__ addp)
{
    __shared__ float red[8];
    long long idx = (long long)blockIdx.x * 128 + threadIdx.x;
    float v = a[idx];
    if (b) v += b[idx];
    if (c) v += c[idx];
    if (d) v += d[idx];
    float s = v, ss = v * v;
#pragma unroll
    for (int o = 16; o; o >>= 1) {
        s  += __shfl_xor_sync(0xffffffffu, s,  o);
        ss += __shfl_xor_sync(0xffffffffu, ss, o);
    }
    int w = threadIdx.x >> 5;
    if ((threadIdx.x & 31) == 0) { red[w] = s; red[4 + w] = ss; }
    __syncthreads();
    s  = red[0] + red[1] + red[2] + red[3];
    ss = red[4] + red[5] + red[6] + red[7];
    float m = s * (1.f / 128.f);
    float var = ss * (1.f / 128.f) - m * m;
    float inv = rsqrtf(var + 1e-5f);
    float r = (v - m) * inv * gamma[threadIdx.x] + beta[threadIdx.x];
    if (addp) r += addp[idx];
    out[idx] = r;
}

// ---------------- elementwise mul by broadcast (N,D) ----------------
__global__ void mul_kernel(const float* __restrict__ a, const float* __restrict__ bm,
                           float* __restrict__ o, int n)
{
    int i = blockIdx.x * 256 + threadIdx.x;
    if (i < n) o[i] = a[i] * bm[i % 51200];
}

// ---------------- adaptive avg pool over node axis ----------------
__global__ void __launch_bounds__(128) pool_kernel(const float* __restrict__ x, float* __restrict__ xp)
{
    int bid = blockIdx.x;
    int bt = bid >> 6, c = bid & 63;
    int s = (c * 400) >> 6;
    int e = ((c + 1) * 400 + 63) >> 6;
    float sum = 0.f;
    for (int n = s; n < e; ++n) sum += x[(bt * 400 + n) * 128 + threadIdx.x];
    xp[bid * 128 + threadIdx.x] = sum / (float)(e - s);
}

// ---------------- GEANet per row (mode 0: node permuted store, 1: edge) ----------------
__global__ void __launch_bounds__(128) gea_kernel(
    const float* __restrict__ in, const float* __restrict__ w, const float* __restrict__ bb,
    float* __restrict__ outp, int mode)
{
    __shared__ float xr[128], tmp[128], s1[16], rs[8], w0[256], w1[256], b0v[16], b1v[16];
    int tid = threadIdx.x;
    int h = tid >> 4, u = tid & 15;
    w0[tid] = w[tid];        w0[128 + tid] = w[128 + tid];
    w1[tid] = w[256 + tid];  w1[128 + tid] = w[384 + tid];
    if (tid < 16) { b0v[tid] = bb[tid]; b1v[tid] = bb[16 + tid]; }
    int id = blockIdx.x;
    if (mode == 0) xr[tid] = in[id * 128 + tid];
    else           xr[tid] = in[id * 128 + u * 8 + h];
    __syncthreads();

    float a = b0v[u];
#pragma unroll
    for (int k = 0; k < 16; k++) a += xr[h * 16 + k] * w0[k * 16 + u];
    tmp[tid] = a;
    __syncthreads();
    float m = tmp[u];
#pragma unroll
    for (int hh = 1; hh < 8; hh++) m = fmaxf(m, tmp[hh * 16 + u]);
    float ev = __expf(a - m);
    __syncthreads();
    tmp[tid] = ev;
    __syncthreads();
    if (tid < 16) { float s = 0.f; for (int hh = 0; hh < 8; hh++) s += tmp[hh * 16 + tid]; s1[tid] = s; }
    __syncthreads();
    float vv = ev / s1[u];
    __syncthreads();
    tmp[tid] = vv;
    __syncthreads();
    if (tid < 8) { float s = 0.f; for (int uu = 0; uu < 16; uu++) s += tmp[tid * 16 + uu]; rs[tid] = s; }
    __syncthreads();
    float dn = vv / rs[h];
    __syncthreads();
    tmp[tid] = dn;
    __syncthreads();
    float o = b1v[u];
#pragma unroll
    for (int k = 0; k < 16; k++) o += tmp[h * 16 + k] * w1[k * 16 + u];

    if (mode == 0) {
        int b = id / 4800, r2 = id % 4800, t = r2 / 400, n = r2 % 400;
        outp[((b * 400 + n) * 12 + t) * 128 + tid] = o;
    } else {
        outp[id * 128 + tid] = o;
    }
}

// ---------------- pooled attention, 64 keys + positional bias ----------------
__global__ void __launch_bounds__(256) attn_pool_kernel(
    const float* __restrict__ q, const float* __restrict__ kp, const float* __restrict__ vp,
    const float* __restrict__ pos, float* __restrict__ o)
{
    __shared__ float Ks[16 * 65], Vs[16 * 65], pball[8 * 64];
    int bid = blockIdx.x;
    int bt = bid >> 3, h = bid & 7;
    int tid = threadIdx.x;
    int kbase = bt * 64 * 128 + h * 16;
    int qbase = bt * 400 * 128 + h * 16;
    for (int i = tid; i < 1024; i += 256) {
        int kk = i >> 4, d = i & 15;
        Ks[d * 65 + kk] = kp[kbase + kk * 128 + d];
        Vs[d * 65 + kk] = vp[kbase + kk * 128 + d];
    }
    __syncthreads();
    int warp = tid >> 5, lane = tid & 31;
    float* pb = pball + warp * 64;
    for (int qi = warp; qi < 400; qi += 8) {
        float qd[16];
#pragma unroll
        for (int d = 0; d < 16; d++) qd[d] = q[qbase + qi * 128 + d];
        float sc[2];
        float m = -3.4e38f;
#pragma unroll
        for (int j = 0; j < 2; j++) {
            int kk = lane + 32 * j;
            float s = 0.f;
#pragma unroll
            for (int d = 0; d < 16; d++) s += qd[d] * Ks[d * 65 + kk];
            s = s * 0.25f + pos[qi * 64 + kk];
            sc[j] = s; m = fmaxf(m, s);
        }
#pragma unroll
        for (int off = 16; off; off >>= 1) m = fmaxf(m, __shfl_xor_sync(0xffffffffu, m, off));
        float lsum = 0.f;
#pragma unroll
        for (int j = 0; j < 2; j++) { float p = __expf(sc[j] - m); sc[j] = p; lsum += p; }
#pragma unroll
        for (int off = 16; off; off >>= 1) lsum += __shfl_xor_sync(0xffffffffu, lsum, off);
        pb[lane] = sc[0]; pb[lane + 32] = sc[1];
        __syncwarp();
        int d = lane & 15, half = lane >> 4;
        float acc = 0.f;
#pragma unroll
        for (int i = 0; i < 32; ++i) { int c = 2 * i + half; acc += pb[c] * Vs[d * 65 + c]; }
        acc += __shfl_xor_sync(0xffffffffu, acc, 16);
        if (lane < 16) o[qbase + qi * 128 + d] = acc / lsum;
        __syncwarp();
    }
}

__global__ void copy_kernel(const float* __restrict__ a, float* __restrict__ o, int n)
{
    int i = blockIdx.x * 256 + threadIdx.x;
    if (i < n) o[i] = a[i];
}

// ---------------- host ----------------
static float* sym(const void* s) { void* p = nullptr; cudaGetSymbolAddress(&p, s); return (float*)p; }

extern "C" void kernel_launch(void* const* d_in, const int* in_sizes, int n_in,
                              void* d_out, int out_size)
{
    const float* x      = (const float*)d_in[0];
    const float* semb   = (const float*)d_in[1];
    const float* dqkv_w = (const float*)d_in[2];
    const float* dqkv_b = (const float*)d_in[3];
    const float* dout_w = (const float*)d_in[4];
    const float* dout_b = (const float*)d_in[5];
    const float* aqkv_w = (const float*)d_in[6];
    const float* aqkv_b = (const float*)d_in[7];
    const float* aout_w = (const float*)d_in[8];
    const float* aout_b = (const float*)d_in[9];
    const float* adp_pos= (const float*)d_in[10];
    const float* gsh_w  = (const float*)d_in[11];
    const float* gsh_b  = (const float*)d_in[12];
    const float* gnode_w= (const float*)d_in[13];
    const float* gnode_b= (const float*)d_in[14];
    const float* gedge_w= (const float*)d_in[15];
    const float* gedge_b= (const float*)d_in[16];
    const float* sp_w   = (const float*)d_in[17];
    const float* sp_b   = (const float*)d_in[18];
    const float* f1w1   = (const float*)d_in[19];
    const float* f1b1   = (const float*)d_in[20];
    const float* f1w2   = (const float*)d_in[21];
    const float* f1b2   = (const float*)d_in[22];
    const float* f2w1   = (const float*)d_in[23];
    const float* f2b1   = (const float*)d_in[24];
    const float* f2w2   = (const float*)d_in[25];
    const float* f2b2   = (const float*)d_in[26];
    const float* lns    = (const float*)d_in[27];
    const float* lnb    = (const float*)d_in[28];
    float* out = (float*)d_out;

    float *q = sym(g_q), *k = sym(g_k), *v = sym(g_v), *o = sym(g_o);
    float *dtw = sym(g_dtw), *ex = sym(g_ex), *res = sym(g_res), *tmp = sym(g_tmp);
    float *hid = sym(g_hid);
    float *xp = sym(g_xp), *kp = sym(g_kp), *vp = sym(g_vp);
    float *sen = sym(g_sen), *edge = sym(g_edge), *senx = sym(g_senx);

    const int GEMM_SMEM = 3 * (4608 + 4352) * 4;   // 107520 B
    const int ATT_SMEM  = ATT_TC_FLOATS * 4;       // 120960 B
    cudaFuncSetAttribute(mma_gemm, cudaFuncAttributeMaxDynamicSharedMemorySize, GEMM_SMEM);
    cudaFuncSetAttribute(attn_tc_kernel, cudaFuncAttributeMaxDynamicSharedMemorySize, ATT_SMEM);

    dim3 gBig(300, 1), gPool(48, 1), gSmall(4, 1), gFFa(300, 16);

    // dtw = full MHA
    mma_gemm<<<gBig, 256, GEMM_SMEM>>>(x, dqkv_w,         dqkv_b,       q, ROWS, 128, 128, 0);
    mma_gemm<<<gBig, 256, GEMM_SMEM>>>(x, dqkv_w + 16384, dqkv_b + 128, k, ROWS, 128, 128, 0);
    mma_gemm<<<gBig, 256, GEMM_SMEM>>>(x, dqkv_w + 32768, dqkv_b + 256, v, ROWS, 128, 128, 0);
    attn_tc_kernel<<<768, 256, ATT_SMEM>>>(q, k, v, o);
    mma_gemm<<<gBig, 256, GEMM_SMEM>>>(o, dout_w, dout_b, dtw, ROWS, 128, 128, 0);

    // pooled MHA (pool(xW+b) == (pool x)W + b)
    pool_kernel<<<6144, 128>>>(x, xp);
    mma_gemm<<<gBig,  256, GEMM_SMEM>>>(x,  aqkv_w,         aqkv_b,       q,  ROWS, 128, 128, 0);
    mma_gemm<<<gPool, 256, GEMM_SMEM>>>(xp, aqkv_w + 16384, aqkv_b + 128, kp, 6144, 128, 128, 0);
    mma_gemm<<<gPool, 256, GEMM_SMEM>>>(xp, aqkv_w + 32768, aqkv_b + 256, vp, 6144, 128, 128, 0);
    attn_pool_kernel<<<768, 256>>>(q, kp, vp, adp_pos, o);
    mma_gemm<<<gBig, 256, GEMM_SMEM>>>(o, aout_w, aout_b, k, ROWS, 128, 128, 0);   // oa -> k

    // sen + GEANet edge
    mma_gemm<<<gSmall, 256, GEMM_SMEM>>>(semb, sp_w, sp_b, sen, 400, 128, 128, 0);
    ln_kernel<<<400, 128>>>(sen, nullptr, nullptr, nullptr, lns + 3 * 128, lnb + 3 * 128, sen, nullptr);
    mma_gemm<<<gSmall, 256, GEMM_SMEM>>>(sen, gsh_w, gsh_b, edge, 400, 128, 128, 0);
    gea_kernel<<<400, 128>>>(edge, gedge_w, gedge_b, senx, 1);
    if (out_size >= BIG + 51200)
        copy_kernel<<<(51200 + 255) / 256, 256>>>(senx, out + BIG, 51200);

    // GEANet node
    mma_gemm<<<gBig, 256, GEMM_SMEM>>>(x, gsh_w, gsh_b, v, ROWS, 128, 128, 0);
    gea_kernel<<<ROWS, 128>>>(v, gnode_w, gnode_b, ex, 0);

    // out = LN(x + dtw + oa + extra)
    ln_kernel<<<ROWS, 128>>>(x, dtw, k, ex, lns, lnb, res, nullptr);

    // out_attn = LN(FF1(out) + out)
    mma_gemm<<<gFFa, 256, GEMM_SMEM>>>(res, f1w1, f1b1, hid, ROWS, 2048, 128, 1);
    mma_gemm<<<gBig, 256, GEMM_SMEM>>>(hid, f1w2, f1b2, tmp, ROWS, 128, 2048, 0);
    ln_kernel<<<ROWS, 128>>>(tmp, res, nullptr, nullptr, lns + 128, lnb + 128, dtw, nullptr); // out_attn -> dtw

    // sp = LN(FF2(out_attn * sen_extra)); final out = out_attn + sp fused into LN
    mul_kernel<<<(BIG + 255) / 256, 256>>>(dtw, senx, res, BIG);
    mma_gemm<<<gFFa, 256, GEMM_SMEM>>>(res, f2w1, f2b1, hid, ROWS, 2048, 128, 1);
    mma_gemm<<<gBig, 256, GEMM_SMEM>>>(hid, f2w2, f2b2, tmp, ROWS, 128, 2048, 0);
    ln_kernel<<<ROWS, 128>>>(tmp, nullptr, nullptr, nullptr, lns + 256, lnb + 256, out, dtw);
}

// round 12
// speedup vs baseline: 5.1606x; 1.0857x over previous
#include <cuda_runtime.h>

#define ROWS 38400
#define BIG  4915200

// ---------------- device scratch ----------------
__device__ float g_q[BIG];
__device__ float g_k[BIG];
__device__ float g_v[BIG];
__device__ float g_o[BIG];
__device__ float g_dtw[BIG];
__device__ float g_ex[BIG];
__device__ float g_res[BIG];
__device__ float g_tmp[BIG];
__device__ float g_hid[78643200];   // 38400 x 2048 FF hidden
__device__ float g_xp[786432];
__device__ float g_kp[786432];
__device__ float g_vp[786432];
__device__ float g_sen[51200];
__device__ float g_edge[51200];
__device__ float g_senx[51200];

// ---------------- mma / cp.async helpers ----------------
__device__ __forceinline__ void mma8(float* c, const unsigned* a, const unsigned* b) {
    asm volatile(
        "mma.sync.aligned.m16n8k8.row.col.f32.tf32.tf32.f32 "
        "{%0,%1,%2,%3}, {%4,%5,%6,%7}, {%8,%9}, {%0,%1,%2,%3};"
        : "+f"(c[0]), "+f"(c[1]), "+f"(c[2]), "+f"(c[3])
        : "r"(a[0]), "r"(a[1]), "r"(a[2]), "r"(a[3]), "r"(b[0]), "r"(b[1]));
}
__device__ __forceinline__ void cpa16(unsigned dst, const float* src, bool p) {
    int sz = p ? 16 : 0;
    asm volatile("cp.async.cg.shared.global [%0], [%1], 16, %2;"
                 :: "r"(dst), "l"(src), "r"(sz));
}
#define CP_COMMIT() asm volatile("cp.async.commit_group;")
#define CP_WAIT1()  asm volatile("cp.async.wait_group 1;")

// ---------------- tf32 GEMM, cp.async 3-stage: C = epi(A[MxK] @ W[KxN] + bias) ----------------
// block tile 128x128, 8 warps (4M x 2N), warp tile 32x64, k-chunk 32.
__global__ void __launch_bounds__(256) mma_gemm(
    const float* __restrict__ A, const float* __restrict__ W,
    const float* __restrict__ bias, float* __restrict__ C,
    int M, int N, int K, int relu)
{
    extern __shared__ float smf[];
    float* As = smf;                 // 3 x 4608
    float* Bs = smf + 3 * 4608;      // 3 x 4352
    const unsigned sA = (unsigned)__cvta_generic_to_shared(As);
    const unsigned sB = (unsigned)__cvta_generic_to_shared(Bs);
    const int tid = threadIdx.x;
    const int lane = tid & 31, w = tid >> 5;
    const int mw = (w >> 1) * 32, nw = (w & 1) * 64;
    const int rowBlk = blockIdx.x * 128, colBlk = blockIdx.y * 128;
    const int gp = lane >> 2, tg = lane & 3;
    const int T = K >> 5;

    float acc[2][8][4];
#pragma unroll
    for (int mt = 0; mt < 2; mt++)
#pragma unroll
        for (int nt = 0; nt < 8; nt++)
#pragma unroll
            for (int i = 0; i < 4; i++) acc[mt][nt][i] = 0.f;

    auto issue = [&](int t) {
        if (t < T) {
            int s = t % 3, k0 = t * 32;
#pragma unroll
            for (int i = 0; i < 4; i++) {
                int idx = tid + i * 256;
                int r = idx >> 3, kq = idx & 7;
                int row = rowBlk + r;
                bool p = row < M;
                int rc = p ? row : (M - 1);
                cpa16(sA + (s * 4608 + r * 36 + kq * 4) * 4,
                      A + (long long)rc * K + k0 + kq * 4, p);
            }
#pragma unroll
            for (int i = 0; i < 4; i++) {
                int idx = tid + i * 256;
                int kk = idx >> 5, nq = idx & 31;
                cpa16(sB + (s * 4352 + kk * 136 + nq * 4) * 4,
                      W + (long long)(k0 + kk) * N + colBlk + nq * 4, true);
            }
        }
        CP_COMMIT();
    };

    issue(0); issue(1);
    for (int t = 0; t < T; t++) {
        CP_WAIT1();
        __syncthreads();
        const unsigned* Ad = (const unsigned*)(As + (t % 3) * 4608);
        const unsigned* Bd = (const unsigned*)(Bs + (t % 3) * 4352);
#pragma unroll
        for (int ks = 0; ks < 32; ks += 8) {
            unsigned a[2][4], b[8][2];
#pragma unroll
            for (int mt = 0; mt < 2; mt++) {
                int r = mw + mt * 16 + gp;
                a[mt][0] = Ad[r * 36 + ks + tg];
                a[mt][1] = Ad[(r + 8) * 36 + ks + tg];
                a[mt][2] = Ad[r * 36 + ks + tg + 4];
                a[mt][3] = Ad[(r + 8) * 36 + ks + tg + 4];
            }
#pragma unroll
            for (int nt = 0; nt < 8; nt++) {
                int n = nw + nt * 8 + gp;
                b[nt][0] = Bd[(ks + tg) * 136 + n];
                b[nt][1] = Bd[(ks + tg + 4) * 136 + n];
            }
#pragma unroll
            for (int mt = 0; mt < 2; mt++)
#pragma unroll
                for (int nt = 0; nt < 8; nt++)
                    mma8(acc[mt][nt], a[mt], b[nt]);
        }
        issue(t + 2);
    }
#pragma unroll
    for (int mt = 0; mt < 2; mt++) {
        int row = rowBlk + mw + mt * 16 + gp;
#pragma unroll
        for (int nt = 0; nt < 8; nt++) {
            int col = colBlk + nw + nt * 8 + tg * 2;
            float b0 = bias[col], b1 = bias[col + 1];
            float* cp = acc[mt][nt];
            float v0 = cp[0] + b0, v1 = cp[1] + b1;
            float v2 = cp[2] + b0, v3 = cp[3] + b1;
            if (relu) {
                v0 = fmaxf(v0, 0.f); v1 = fmaxf(v1, 0.f);
                v2 = fmaxf(v2, 0.f); v3 = fmaxf(v3, 0.f);
            }
            if (row < M)     *(float2*)&C[(long long)row * N + col]       = make_float2(v0, v1);
            if (row + 8 < M) *(float2*)&C[(long long)(row + 8) * N + col] = make_float2(v2, v3);
        }
    }
}

// ---------------- FF-a GEMM: C[38400x2048] = relu(A(*mulp)[38400x128] @ W[128x2048] + bias) ----------------
// block tile 128x256, 8 warps (2M x 4N), warp tile 64x64, k-chunk 32, 3-stage cp.async.
#define FFA_AS 4608
#define FFA_BS 8448
#define FFA_SMEM_FLOATS (3 * (FFA_AS + FFA_BS))
__global__ void __launch_bounds__(256) ffa_gemm(
    const float* __restrict__ A, const float* __restrict__ W,
    const float* __restrict__ bias, const float* __restrict__ mulp,
    float* __restrict__ C)
{
    extern __shared__ float smf[];
    float* As = smf;
    float* Bs = smf + 3 * FFA_AS;
    const unsigned sA = (unsigned)__cvta_generic_to_shared(As);
    const unsigned sB = (unsigned)__cvta_generic_to_shared(Bs);
    const int tid = threadIdx.x;
    const int lane = tid & 31, w = tid >> 5;
    const int mw = (w >> 2) * 64, nw = (w & 3) * 64;
    const int rowBlk = blockIdx.x * 128, colBlk = blockIdx.y * 256;
    const int gp = lane >> 2, tg = lane & 3;

    float acc[4][8][4];
#pragma unroll
    for (int mt = 0; mt < 4; mt++)
#pragma unroll
        for (int nt = 0; nt < 8; nt++)
#pragma unroll
            for (int i = 0; i < 4; i++) acc[mt][nt][i] = 0.f;

    auto issue = [&](int t) {
        if (t < 4) {
            int s = t % 3, k0 = t * 32;
            if (mulp == nullptr) {
#pragma unroll
                for (int i = 0; i < 4; i++) {
                    int idx = tid + i * 256;
                    int r = idx >> 3, kq = idx & 7;
                    cpa16(sA + (s * FFA_AS + r * 36 + kq * 4) * 4,
                          A + (long long)(rowBlk + r) * 128 + k0 + kq * 4, true);
                }
            } else {
#pragma unroll
                for (int i = 0; i < 4; i++) {
                    int idx = tid + i * 256;
                    int r = idx >> 3, kq = idx & 7;
                    int row = rowBlk + r;
                    float4 av = *(const float4*)(A + (long long)row * 128 + k0 + kq * 4);
                    float4 mv = *(const float4*)(mulp + (row % 400) * 128 + k0 + kq * 4);
                    *(float4*)(As + s * FFA_AS + r * 36 + kq * 4) =
                        make_float4(av.x * mv.x, av.y * mv.y, av.z * mv.z, av.w * mv.w);
                }
            }
#pragma unroll
            for (int i = 0; i < 8; i++) {
                int idx = tid + i * 256;
                int kk = idx >> 6, nq = idx & 63;
                cpa16(sB + (s * FFA_BS + kk * 264 + nq * 4) * 4,
                      W + (long long)(k0 + kk) * 2048 + colBlk + nq * 4, true);
            }
        }
        CP_COMMIT();
    };

    issue(0); issue(1);
    for (int t = 0; t < 4; t++) {
        CP_WAIT1();
        __syncthreads();
        const unsigned* Ad = (const unsigned*)(As + (t % 3) * FFA_AS);
        const unsigned* Bd = (const unsigned*)(Bs + (t % 3) * FFA_BS);
#pragma unroll
        for (int ks = 0; ks < 32; ks += 8) {
            unsigned a[4][4], b[8][2];
#pragma unroll
            for (int mt = 0; mt < 4; mt++) {
                int r = mw + mt * 16 + gp;
                a[mt][0] = Ad[r * 36 + ks + tg];
                a[mt][1] = Ad[(r + 8) * 36 + ks + tg];
                a[mt][2] = Ad[r * 36 + ks + tg + 4];
                a[mt][3] = Ad[(r + 8) * 36 + ks + tg + 4];
            }
#pragma unroll
            for (int nt = 0; nt < 8; nt++) {
                int n = nw + nt * 8 + gp;
                b[nt][0] = Bd[(ks + tg) * 264 + n];
                b[nt][1] = Bd[(ks + tg + 4) * 264 + n];
            }
#pragma unroll
            for (int mt = 0; mt < 4; mt++)
#pragma unroll
                for (int nt = 0; nt < 8; nt++)
                    mma8(acc[mt][nt], a[mt], b[nt]);
        }
        issue(t + 2);
    }
#pragma unroll
    for (int mt = 0; mt < 4; mt++) {
        long long row = rowBlk + mw + mt * 16 + gp;
#pragma unroll
        for (int nt = 0; nt < 8; nt++) {
            int col = colBlk + nw + nt * 8 + tg * 2;
            float b0 = bias[col], b1 = bias[col + 1];
            float* cp = acc[mt][nt];
            *(float2*)&C[row * 2048 + col] =
                make_float2(fmaxf(cp[0] + b0, 0.f), fmaxf(cp[1] + b1, 0.f));
            *(float2*)&C[(row + 8) * 2048 + col] =
                make_float2(fmaxf(cp[2] + b0, 0.f), fmaxf(cp[3] + b1, 0.f));
        }
    }
}

// ---------------- tensor-core full attention (400 keys), 2 blocks/SM ----------------
// SMEM floats: Kt[16*408] | Vt[16*404] | S[32*404] | Qs/Po overlap | ls
#define ATT_KT 0
#define ATT_VT 6528
#define ATT_S  12992
#define ATT_QS 25920
#define ATT_PO 25920
#define ATT_LS 28096
#define ATT_TC_FLOATS 28128
__global__ void __launch_bounds__(256) attn_tc_kernel(
    const float* __restrict__ q, const float* __restrict__ k, const float* __restrict__ v,
    float* __restrict__ o)
{
    extern __shared__ float sm[];
    float* Kt = sm + ATT_KT;
    float* Vt = sm + ATT_VT;
    float* S  = sm + ATT_S;
    float* Qs = sm + ATT_QS;
    float* ls = sm + ATT_LS;
    float* Po = sm + ATT_PO;
    int bid = blockIdx.x, bt = bid >> 3, h = bid & 7;
    int tid = threadIdx.x, lane = tid & 31, w = tid >> 5;
    int gp = lane >> 2, tg = lane & 3;
    int base = bt * 400 * 128 + h * 16;

    for (int i = tid; i < 6400; i += 256) {
        int key = i >> 4, d = i & 15;
        Kt[d * 408 + key] = k[base + key * 128 + d];
        Vt[d * 404 + key] = v[base + key * 128 + d];
    }
    __syncthreads();

    const unsigned* Ku = (const unsigned*)Kt;
    const unsigned* Vu = (const unsigned*)Vt;
    const unsigned* Qu = (const unsigned*)Qs;
    const unsigned* Pu = (const unsigned*)S;

    for (int qt = 0; qt < 400; qt += 32) {
        for (int i = tid; i < 512; i += 256) {
            int r = i >> 4, d = i & 15;
            int qr = qt + r;
            Qs[r * 20 + d] = (qr < 400) ? q[base + qr * 128 + d] : 0.f;
        }
        __syncthreads();
        // phase 1: S = 0.25 * Q K^T (hoisted Q fragments; K stored d-major stride 408)
        {
            unsigned af[2][2][4];
#pragma unroll
            for (int mt = 0; mt < 2; mt++)
#pragma unroll
                for (int ksi = 0; ksi < 2; ksi++) {
                    int r = mt * 16 + gp, ks = ksi * 8;
                    af[mt][ksi][0] = Qu[r * 20 + ks + tg];
                    af[mt][ksi][1] = Qu[(r + 8) * 20 + ks + tg];
                    af[mt][ksi][2] = Qu[r * 20 + ks + tg + 4];
                    af[mt][ksi][3] = Qu[(r + 8) * 20 + ks + tg + 4];
                }
            for (int nt = w; nt < 50; nt += 8) {
                float c0[4] = {0.f, 0.f, 0.f, 0.f};
                float c1[4] = {0.f, 0.f, 0.f, 0.f};
#pragma unroll
                for (int ksi = 0; ksi < 2; ksi++) {
                    int ks = ksi * 8;
                    unsigned b[2];
                    b[0] = Ku[(ks + tg) * 408 + nt * 8 + gp];
                    b[1] = Ku[(ks + tg + 4) * 408 + nt * 8 + gp];
                    mma8(c0, af[0][ksi], b);
                    mma8(c1, af[1][ksi], b);
                }
                int cc = nt * 8 + tg * 2;
                S[gp * 404 + cc]            = c0[0] * 0.25f;
                S[gp * 404 + cc + 1]        = c0[1] * 0.25f;
                S[(gp + 8) * 404 + cc]      = c0[2] * 0.25f;
                S[(gp + 8) * 404 + cc + 1]  = c0[3] * 0.25f;
                S[(gp + 16) * 404 + cc]     = c1[0] * 0.25f;
                S[(gp + 16) * 404 + cc + 1] = c1[1] * 0.25f;
                S[(gp + 24) * 404 + cc]     = c1[2] * 0.25f;
                S[(gp + 24) * 404 + cc + 1] = c1[3] * 0.25f;
            }
        }
        __syncthreads();
        // phase 2: row softmax (P stored back into S as fp32)
        for (int rr = 0; rr < 4; rr++) {
            int row = w * 4 + rr;
            float sc[13];
            float m = -3.4e38f;
#pragma unroll
            for (int j = 0; j < 13; j++) {
                int kk = lane + j * 32;
                float s_ = (kk < 400) ? S[row * 404 + kk] : -3.4e38f;
                sc[j] = s_; m = fmaxf(m, s_);
            }
#pragma unroll
            for (int off = 16; off; off >>= 1) m = fmaxf(m, __shfl_xor_sync(0xffffffffu, m, off));
            float l = 0.f;
#pragma unroll
            for (int j = 0; j < 13; j++) {
                int kk = lane + j * 32;
                if (kk < 400) {
                    float p_ = __expf(sc[j] - m);
                    S[row * 404 + kk] = p_;
                    l += p_;
                }
            }
#pragma unroll
            for (int off = 16; off; off >>= 1) l += __shfl_xor_sync(0xffffffffu, l, off);
            if (lane == 0) ls[row] = 1.f / l;
        }
        __syncthreads();
        // phase 3: O = P @ V, 8 warps via split-K (two 200-key halves)
        {
            int mt = w & 1, nt = (w >> 1) & 1, kh = w >> 2;
            float c[4] = {0.f, 0.f, 0.f, 0.f};
            int kbase = kh * 200;
#pragma unroll 5
            for (int i = 0; i < 25; i++) {
                int k0 = kbase + i * 8;
                unsigned a[4], b[2];
                a[0] = Pu[(mt * 16 + gp) * 404 + k0 + tg];
                a[1] = Pu[(mt * 16 + gp + 8) * 404 + k0 + tg];
                a[2] = Pu[(mt * 16 + gp) * 404 + k0 + tg + 4];
                a[3] = Pu[(mt * 16 + gp + 8) * 404 + k0 + tg + 4];
                b[0] = Vu[(nt * 8 + gp) * 404 + k0 + tg];
                b[1] = Vu[(nt * 8 + gp) * 404 + k0 + tg + 4];
                mma8(c, a, b);
            }
            int r0 = mt * 16 + gp, d0 = nt * 8 + tg * 2;
            if (kh == 1) {
                Po[r0 * 68 + d0]           = c[0];
                Po[r0 * 68 + d0 + 1]       = c[1];
                Po[(r0 + 8) * 68 + d0]     = c[2];
                Po[(r0 + 8) * 68 + d0 + 1] = c[3];
            }
            __syncthreads();
            if (kh == 0) {
                float s0 = ls[r0], s1 = ls[r0 + 8];
                int qr0 = qt + r0, qr1 = qt + r0 + 8;
                if (qr0 < 400) {
                    o[base + qr0 * 128 + d0]     = (c[0] + Po[r0 * 68 + d0]) * s0;
                    o[base + qr0 * 128 + d0 + 1] = (c[1] + Po[r0 * 68 + d0 + 1]) * s0;
                }
                if (qr1 < 400) {
                    o[base + qr1 * 128 + d0]     = (c[2] + Po[(r0 + 8) * 68 + d0]) * s1;
                    o[base + qr1 * 128 + d0 + 1] = (c[3] + Po[(r0 + 8) * 68 + d0 + 1]) * s1;
                }
            }
        }
        __syncthreads();
    }
}

// ---------------- LayerNorm of (a [+ b] [+ c] [+ d]) over last dim 128, optional +addp ----------------
__global__ void __launch_bounds__(128) ln_kernel(
    const float* __restrict__ a, const float* __restrict__ b,
    const float* __restrict__ c, const float* __restrict__ d,
    const float* __restrict__ gamma, const float* __restrict__ beta,
    float* __restrict__ out, const float* __restrict__ addp)
{
    __shared__ float red[8];
    long long idx = (long long)blockIdx.x * 128 + threadIdx.x;
    float v = a[idx];
    if (b) v += b[idx];
    if (c) v += c[idx];
    if (d) v += d[idx];
    float s = v, ss = v * v;
#pragma unroll
    for (int o = 16; o; o >>= 1) {
        s  += __shfl_xor_sync(0xffffffffu, s,  o);
        ss += __shfl_xor_sync(0xffffffffu, ss, o);
    }
    int w = threadIdx.x >> 5;
    if ((threadIdx.x & 31) == 0) { red[w] = s; red[4 + w] = ss; }
    __syncthreads();
    s  = red[0] + red[1] + red[2] + red[3];
    ss = red[4] + red[5] + red[6] + red[7];
    float m = s * (1.f / 128.f);
    float var = ss * (1.f / 128.f) - m * m;
    float inv = rsqrtf(var + 1e-5f);
    float r = (v - m) * inv * gamma[threadIdx.x] + beta[threadIdx.x];
    if (addp) r += addp[idx];
    out[idx] = r;
}

// ---------------- adaptive avg pool over node axis ----------------
__global__ void __launch_bounds__(128) pool_kernel(const float* __restrict__ x, float* __restrict__ xp)
{
    int bid = blockIdx.x;
    int bt = bid >> 6, c = bid & 63;
    int s = (c * 400) >> 6;
    int e = ((c + 1) * 400 + 63) >> 6;
    float sum = 0.f;
    for (int n = s; n < e; ++n) sum += x[(bt * 400 + n) * 128 + threadIdx.x];
    xp[bid * 128 + threadIdx.x] = sum / (float)(e - s);
}

// ---------------- GEANet per row (mode 0: node permuted store, 1: edge) ----------------
__global__ void __launch_bounds__(128) gea_kernel(
    const float* __restrict__ in, const float* __restrict__ w, const float* __restrict__ bb,
    float* __restrict__ outp, int mode)
{
    __shared__ float xr[128], tmp[128], s1[16], rs[8], w0[256], w1[256], b0v[16], b1v[16];
    int tid = threadIdx.x;
    int h = tid >> 4, u = tid & 15;
    w0[tid] = w[tid];        w0[128 + tid] = w[128 + tid];
    w1[tid] = w[256 + tid];  w1[128 + tid] = w[384 + tid];
    if (tid < 16) { b0v[tid] = bb[tid]; b1v[tid] = bb[16 + tid]; }
    int id = blockIdx.x;
    if (mode == 0) xr[tid] = in[id * 128 + tid];
    else           xr[tid] = in[id * 128 + u * 8 + h];
    __syncthreads();

    float a = b0v[u];
#pragma unroll
    for (int k = 0; k < 16; k++) a += xr[h * 16 + k] * w0[k * 16 + u];
    tmp[tid] = a;
    __syncthreads();
    float m = tmp[u];
#pragma unroll
    for (int hh = 1; hh < 8; hh++) m = fmaxf(m, tmp[hh * 16 + u]);
    float ev = __expf(a - m);
    __syncthreads();
    tmp[tid] = ev;
    __syncthreads();
    if (tid < 16) { float s = 0.f; for (int hh = 0; hh < 8; hh++) s += tmp[hh * 16 + tid]; s1[tid] = s; }
    __syncthreads();
    float vv = ev / s1[u];
    __syncthreads();
    tmp[tid] = vv;
    __syncthreads();
    if (tid < 8) { float s = 0.f; for (int uu = 0; uu < 16; uu++) s += tmp[tid * 16 + uu]; rs[tid] = s; }
    __syncthreads();
    float dn = vv / rs[h];
    __syncthreads();
    tmp[tid] = dn;
    __syncthreads();
    float o = b1v[u];
#pragma unroll
    for (int k = 0; k < 16; k++) o += tmp[h * 16 + k] * w1[k * 16 + u];

    if (mode == 0) {
        int b = id / 4800, r2 = id % 4800, t = r2 / 400, n = r2 % 400;
        outp[((b * 400 + n) * 12 + t) * 128 + tid] = o;
    } else {
        outp[id * 128 + tid] = o;
    }
}

// ---------------- pooled attention, 64 keys + positional bias ----------------
__global__ void __launch_bounds__(256) attn_pool_kernel(
    const float* __restrict__ q, const float* __restrict__ kp, const float* __restrict__ vp,
    const float* __restrict__ pos, float* __restrict__ o)
{
    __shared__ float Ks[16 * 65], Vs[16 * 65], pball[8 * 64];
    int bid = blockIdx.x;
    int bt = bid >> 3, h = bid & 7;
    int tid = threadIdx.x;
    int kbase = bt * 64 * 128 + h * 16;
    int qbase = bt * 400 * 128 + h * 16;
    for (int i = tid; i < 1024; i += 256) {
        int kk = i >> 4, d = i & 15;
        Ks[d * 65 + kk] = kp[kbase + kk * 128 + d];
        Vs[d * 65 + kk] = vp[kbase + kk * 128 + d];
    }
    __syncthreads();
    int warp = tid >> 5, lane = tid & 31;
    float* pb = pball + warp * 64;
    for (int qi = warp; qi < 400; qi += 8) {
        float qd[16];
#pragma unroll
        for (int d = 0; d < 16; d++) qd[d] = q[qbase + qi * 128 + d];
        float sc[2];
        float m = -3.4e38f;
#pragma unroll
        for (int j = 0; j < 2; j++) {
            int kk = lane + 32 * j;
            float s = 0.f;
#pragma unroll
            for (int d = 0; d < 16; d++) s += qd[d] * Ks[d * 65 + kk];
            s = s * 0.25f + pos[qi * 64 + kk];
            sc[j] = s; m = fmaxf(m, s);
        }
#pragma unroll
        for (int off = 16; off; off >>= 1) m = fmaxf(m, __shfl_xor_sync(0xffffffffu, m, off));
        float lsum = 0.f;
#pragma unroll
        for (int j = 0; j < 2; j++) { float p = __expf(sc[j] - m); sc[j] = p; lsum += p; }
#pragma unroll
        for (int off = 16; off; off >>= 1) lsum += __shfl_xor_sync(0xffffffffu, lsum, off);
        pb[lane] = sc[0]; pb[lane + 32] = sc[1];
        __syncwarp();
        int d = lane & 15, half = lane >> 4;
        float acc = 0.f;
#pragma unroll
        for (int i = 0; i < 32; ++i) { int c = 2 * i + half; acc += pb[c] * Vs[d * 65 + c]; }
        acc += __shfl_xor_sync(0xffffffffu, acc, 16);
        if (lane < 16) o[qbase + qi * 128 + d] = acc / lsum;
        __syncwarp();
    }
}

__global__ void copy_kernel(const float* __restrict__ a, float* __restrict__ o, int n)
{
    int i = blockIdx.x * 256 + threadIdx.x;
    if (i < n) o[i] = a[i];
}

// ---------------- host ----------------
static float* sym(const void* s) { void* p = nullptr; cudaGetSymbolAddress(&p, s); return (float*)p; }

extern "C" void kernel_launch(void* const* d_in, const int* in_sizes, int n_in,
                              void* d_out, int out_size)
{
    const float* x      = (const float*)d_in[0];
    const float* semb   = (const float*)d_in[1];
    const float* dqkv_w = (const float*)d_in[2];
    const float* dqkv_b = (const float*)d_in[3];
    const float* dout_w = (const float*)d_in[4];
    const float* dout_b = (const float*)d_in[5];
    const float* aqkv_w = (const float*)d_in[6];
    const float* aqkv_b = (const float*)d_in[7];
    const float* aout_w = (const float*)d_in[8];
    const float* aout_b = (const float*)d_in[9];
    const float* adp_pos= (const float*)d_in[10];
    const float* gsh_w  = (const float*)d_in[11];
    const float* gsh_b  = (const float*)d_in[12];
    const float* gnode_w= (const float*)d_in[13];
    const float* gnode_b= (const float*)d_in[14];
    const float* gedge_w= (const float*)d_in[15];
    const float* gedge_b= (const float*)d_in[16];
    const float* sp_w   = (const float*)d_in[17];
    const float* sp_b   = (const float*)d_in[18];
    const float* f1w1   = (const float*)d_in[19];
    const float* f1b1   = (const float*)d_in[20];
    const float* f1w2   = (const float*)d_in[21];
    const float* f1b2   = (const float*)d_in[22];
    const float* f2w1   = (const float*)d_in[23];
    const float* f2b1   = (const float*)d_in[24];
    const float* f2w2   = (const float*)d_in[25];
    const float* f2b2   = (const float*)d_in[26];
    const float* lns    = (const float*)d_in[27];
    const float* lnb    = (const float*)d_in[28];
    float* out = (float*)d_out;

    float *q = sym(g_q), *k = sym(g_k), *v = sym(g_v), *o = sym(g_o);
    float *dtw = sym(g_dtw), *ex = sym(g_ex), *res = sym(g_res), *tmp = sym(g_tmp);
    float *hid = sym(g_hid);
    float *xp = sym(g_xp), *kp = sym(g_kp), *vp = sym(g_vp);
    float *sen = sym(g_sen), *edge = sym(g_edge), *senx = sym(g_senx);

    const int GEMM_SMEM = 3 * (4608 + 4352) * 4;   // 107520 B
    const int ATT_SMEM  = ATT_TC_FLOATS * 4;       // 112512 B -> 2 blocks/SM
    const int FFA_SMEM  = FFA_SMEM_FLOATS * 4;     // 156672 B
    cudaFuncSetAttribute(mma_gemm, cudaFuncAttributeMaxDynamicSharedMemorySize, GEMM_SMEM);
    cudaFuncSetAttribute(attn_tc_kernel, cudaFuncAttributeMaxDynamicSharedMemorySize, ATT_SMEM);
    cudaFuncSetAttribute(ffa_gemm, cudaFuncAttributeMaxDynamicSharedMemorySize, FFA_SMEM);

    dim3 gBig(300, 1), gPool(48, 1), gSmall(4, 1), gFFa(300, 8);

    // dtw = full MHA
    mma_gemm<<<gBig, 256, GEMM_SMEM>>>(x, dqkv_w,         dqkv_b,       q, ROWS, 128, 128, 0);
    mma_gemm<<<gBig, 256, GEMM_SMEM>>>(x, dqkv_w + 16384, dqkv_b + 128, k, ROWS, 128, 128, 0);
    mma_gemm<<<gBig, 256, GEMM_SMEM>>>(x, dqkv_w + 32768, dqkv_b + 256, v, ROWS, 128, 128, 0);
    attn_tc_kernel<<<768, 256, ATT_SMEM>>>(q, k, v, o);
    mma_gemm<<<gBig, 256, GEMM_SMEM>>>(o, dout_w, dout_b, dtw, ROWS, 128, 128, 0);

    // pooled MHA (pool(xW+b) == (pool x)W + b)
    pool_kernel<<<6144, 128>>>(x, xp);
    mma_gemm<<<gBig,  256, GEMM_SMEM>>>(x,  aqkv_w,         aqkv_b,       q,  ROWS, 128, 128, 0);
    mma_gemm<<<gPool, 256, GEMM_SMEM>>>(xp, aqkv_w + 16384, aqkv_b + 128, kp, 6144, 128, 128, 0);
    mma_gemm<<<gPool, 256, GEMM_SMEM>>>(xp, aqkv_w + 32768, aqkv_b + 256, vp, 6144, 128, 128, 0);
    attn_pool_kernel<<<768, 256>>>(q, kp, vp, adp_pos, o);
    mma_gemm<<<gBig, 256, GEMM_SMEM>>>(o, aout_w, aout_b, k, ROWS, 128, 128, 0);   // oa -> k

    // sen + GEANet edge
    mma_gemm<<<gSmall, 256, GEMM_SMEM>>>(semb, sp_w, sp_b, sen, 400, 128, 128, 0);
    ln_kernel<<<400, 128>>>(sen, nullptr, nullptr, nullptr, lns + 3 * 128, lnb + 3 * 128, sen, nullptr);
    mma_gemm<<<gSmall, 256, GEMM_SMEM>>>(sen, gsh_w, gsh_b, edge, 400, 128, 128, 0);
    gea_kernel<<<400, 128>>>(edge, gedge_w, gedge_b, senx, 1);
    if (out_size >= BIG + 51200)
        copy_kernel<<<(51200 + 255) / 256, 256>>>(senx, out + BIG, 51200);

    // GEANet node
    mma_gemm<<<gBig, 256, GEMM_SMEM>>>(x, gsh_w, gsh_b, v, ROWS, 128, 128, 0);
    gea_kernel<<<ROWS, 128>>>(v, gnode_w, gnode_b, ex, 0);

    // out = LN(x + dtw + oa + extra)
    ln_kernel<<<ROWS, 128>>>(x, dtw, k, ex, lns, lnb, res, nullptr);

    // out_attn = LN(FF1(out) + out)
    ffa_gemm<<<gFFa, 256, FFA_SMEM>>>(res, f1w1, f1b1, nullptr, hid);
    mma_gemm<<<gBig, 256, GEMM_SMEM>>>(hid, f1w2, f1b2, tmp, ROWS, 128, 2048, 0);
    ln_kernel<<<ROWS, 128>>>(tmp, res, nullptr, nullptr, lns + 128, lnb + 128, dtw, nullptr); // out_attn -> dtw

    // sp = LN(FF2(out_attn * sen_extra)); final out = out_attn + sp fused into LN
    ffa_gemm<<<gFFa, 256, FFA_SMEM>>>(dtw, f2w1, f2b1, senx, hid);
    mma_gemm<<<gBig, 256, GEMM_SMEM>>>(hid, f2w2, f2b2, tmp, ROWS, 128, 2048, 0);
    ln_kernel<<<ROWS, 128>>>(tmp, nullptr, nullptr, nullptr, lns + 256, lnb + 256, out, dtw);
}

// round 13
// speedup vs baseline: 5.1714x; 1.0021x over previous
#include <cuda_runtime.h>

#define ROWS 38400
#define BIG  4915200

// ---------------- device scratch ----------------
__device__ float g_q[BIG];
__device__ float g_k[BIG];
__device__ float g_v[BIG];
__device__ float g_o[BIG];
__device__ float g_dtw[BIG];
__device__ float g_ex[BIG];
__device__ float g_res[BIG];
__device__ float g_tmp[BIG];
__device__ float g_hid[78643200];   // 38400 x 2048 FF hidden (also temp for pooled-attn out)
__device__ float g_xp[786432];
__device__ float g_kp[786432];
__device__ float g_vp[786432];
__device__ float g_sen[51200];
__device__ float g_edge[51200];
__device__ float g_senx[51200];

// ---------------- mma / cp.async helpers ----------------
__device__ __forceinline__ void mma8(float* c, const unsigned* a, const unsigned* b) {
    asm volatile(
        "mma.sync.aligned.m16n8k8.row.col.f32.tf32.tf32.f32 "
        "{%0,%1,%2,%3}, {%4,%5,%6,%7}, {%8,%9}, {%0,%1,%2,%3};"
        : "+f"(c[0]), "+f"(c[1]), "+f"(c[2]), "+f"(c[3])
        : "r"(a[0]), "r"(a[1]), "r"(a[2]), "r"(a[3]), "r"(b[0]), "r"(b[1]));
}
__device__ __forceinline__ void cpa16(unsigned dst, const float* src, bool p) {
    int sz = p ? 16 : 0;
    asm volatile("cp.async.cg.shared.global [%0], [%1], 16, %2;"
                 :: "r"(dst), "l"(src), "r"(sz));
}
#define CP_COMMIT() asm volatile("cp.async.commit_group;")
#define CP_WAIT1()  asm volatile("cp.async.wait_group 1;")

// ---------------- batched tf32 GEMM (N=K=128): C_y = A_y @ W_y + b_y ----------------
struct GSet {
    const float* A[5];
    const float* W[5];
    const float* Bv[5];
    float*       C[5];
};
__global__ void __launch_bounds__(256) mma_gemm_b(GSet g, int M)
{
    extern __shared__ float smf[];
    float* As = smf;                 // 3 x 4608
    float* Bs = smf + 3 * 4608;      // 3 x 4352
    const unsigned sA = (unsigned)__cvta_generic_to_shared(As);
    const unsigned sB = (unsigned)__cvta_generic_to_shared(Bs);
    const int y = blockIdx.y;
    const float* __restrict__ A = g.A[y];
    const float* __restrict__ W = g.W[y];
    const float* __restrict__ bias = g.Bv[y];
    float* __restrict__ C = g.C[y];
    const int tid = threadIdx.x;
    const int lane = tid & 31, w = tid >> 5;
    const int mw = (w >> 1) * 32, nw = (w & 1) * 64;
    const int rowBlk = blockIdx.x * 128;
    const int gp = lane >> 2, tg = lane & 3;

    float acc[2][8][4];
#pragma unroll
    for (int mt = 0; mt < 2; mt++)
#pragma unroll
        for (int nt = 0; nt < 8; nt++)
#pragma unroll
            for (int i = 0; i < 4; i++) acc[mt][nt][i] = 0.f;

    auto issue = [&](int t) {
        if (t < 4) {
            int s = t % 3, k0 = t * 32;
#pragma unroll
            for (int i = 0; i < 4; i++) {
                int idx = tid + i * 256;
                int r = idx >> 3, kq = idx & 7;
                int row = rowBlk + r;
                bool p = row < M;
                int rc = p ? row : (M - 1);
                cpa16(sA + (s * 4608 + r * 36 + kq * 4) * 4,
                      A + (long long)rc * 128 + k0 + kq * 4, p);
            }
#pragma unroll
            for (int i = 0; i < 4; i++) {
                int idx = tid + i * 256;
                int kk = idx >> 5, nq = idx & 31;
                cpa16(sB + (s * 4352 + kk * 136 + nq * 4) * 4,
                      W + (long long)(k0 + kk) * 128 + nq * 4, true);
            }
        }
        CP_COMMIT();
    };

    issue(0); issue(1);
    for (int t = 0; t < 4; t++) {
        CP_WAIT1();
        __syncthreads();
        const unsigned* Ad = (const unsigned*)(As + (t % 3) * 4608);
        const unsigned* Bd = (const unsigned*)(Bs + (t % 3) * 4352);
#pragma unroll
        for (int ks = 0; ks < 32; ks += 8) {
            unsigned a[2][4], b[8][2];
#pragma unroll
            for (int mt = 0; mt < 2; mt++) {
                int r = mw + mt * 16 + gp;
                a[mt][0] = Ad[r * 36 + ks + tg];
                a[mt][1] = Ad[(r + 8) * 36 + ks + tg];
                a[mt][2] = Ad[r * 36 + ks + tg + 4];
                a[mt][3] = Ad[(r + 8) * 36 + ks + tg + 4];
            }
#pragma unroll
            for (int nt = 0; nt < 8; nt++) {
                int n = nw + nt * 8 + gp;
                b[nt][0] = Bd[(ks + tg) * 136 + n];
                b[nt][1] = Bd[(ks + tg + 4) * 136 + n];
            }
#pragma unroll
            for (int mt = 0; mt < 2; mt++)
#pragma unroll
                for (int nt = 0; nt < 8; nt++)
                    mma8(acc[mt][nt], a[mt], b[nt]);
        }
        issue(t + 2);
    }
#pragma unroll
    for (int mt = 0; mt < 2; mt++) {
        int row = rowBlk + mw + mt * 16 + gp;
#pragma unroll
        for (int nt = 0; nt < 8; nt++) {
            int col = nw + nt * 8 + tg * 2;
            float b0 = bias[col], b1 = bias[col + 1];
            float* cp = acc[mt][nt];
            if (row < M)     *(float2*)&C[(long long)row * 128 + col]       = make_float2(cp[0] + b0, cp[1] + b1);
            if (row + 8 < M) *(float2*)&C[(long long)(row + 8) * 128 + col] = make_float2(cp[2] + b0, cp[3] + b1);
        }
    }
}

// ---------------- generic small GEMM (sen chain): C[Mx128] = A[Mx128] @ W + b ----------------
__global__ void __launch_bounds__(256) mma_gemm(
    const float* __restrict__ A, const float* __restrict__ W,
    const float* __restrict__ bias, float* __restrict__ C, int M)
{
    extern __shared__ float smf[];
    float* As = smf;
    float* Bs = smf + 3 * 4608;
    const unsigned sA = (unsigned)__cvta_generic_to_shared(As);
    const unsigned sB = (unsigned)__cvta_generic_to_shared(Bs);
    const int tid = threadIdx.x;
    const int lane = tid & 31, w = tid >> 5;
    const int mw = (w >> 1) * 32, nw = (w & 1) * 64;
    const int rowBlk = blockIdx.x * 128;
    const int gp = lane >> 2, tg = lane & 3;

    float acc[2][8][4];
#pragma unroll
    for (int mt = 0; mt < 2; mt++)
#pragma unroll
        for (int nt = 0; nt < 8; nt++)
#pragma unroll
            for (int i = 0; i < 4; i++) acc[mt][nt][i] = 0.f;

    auto issue = [&](int t) {
        if (t < 4) {
            int s = t % 3, k0 = t * 32;
#pragma unroll
            for (int i = 0; i < 4; i++) {
                int idx = tid + i * 256;
                int r = idx >> 3, kq = idx & 7;
                int row = rowBlk + r;
                bool p = row < M;
                int rc = p ? row : (M - 1);
                cpa16(sA + (s * 4608 + r * 36 + kq * 4) * 4,
                      A + (long long)rc * 128 + k0 + kq * 4, p);
            }
#pragma unroll
            for (int i = 0; i < 4; i++) {
                int idx = tid + i * 256;
                int kk = idx >> 5, nq = idx & 31;
                cpa16(sB + (s * 4352 + kk * 136 + nq * 4) * 4,
                      W + (long long)(k0 + kk) * 128 + nq * 4, true);
            }
        }
        CP_COMMIT();
    };

    issue(0); issue(1);
    for (int t = 0; t < 4; t++) {
        CP_WAIT1();
        __syncthreads();
        const unsigned* Ad = (const unsigned*)(As + (t % 3) * 4608);
        const unsigned* Bd = (const unsigned*)(Bs + (t % 3) * 4352);
#pragma unroll
        for (int ks = 0; ks < 32; ks += 8) {
            unsigned a[2][4], b[8][2];
#pragma unroll
            for (int mt = 0; mt < 2; mt++) {
                int r = mw + mt * 16 + gp;
                a[mt][0] = Ad[r * 36 + ks + tg];
                a[mt][1] = Ad[(r + 8) * 36 + ks + tg];
                a[mt][2] = Ad[r * 36 + ks + tg + 4];
                a[mt][3] = Ad[(r + 8) * 36 + ks + tg + 4];
            }
#pragma unroll
            for (int nt = 0; nt < 8; nt++) {
                int n = nw + nt * 8 + gp;
                b[nt][0] = Bd[(ks + tg) * 136 + n];
                b[nt][1] = Bd[(ks + tg + 4) * 136 + n];
            }
#pragma unroll
            for (int mt = 0; mt < 2; mt++)
#pragma unroll
                for (int nt = 0; nt < 8; nt++)
                    mma8(acc[mt][nt], a[mt], b[nt]);
        }
        issue(t + 2);
    }
#pragma unroll
    for (int mt = 0; mt < 2; mt++) {
        int row = rowBlk + mw + mt * 16 + gp;
#pragma unroll
        for (int nt = 0; nt < 8; nt++) {
            int col = nw + nt * 8 + tg * 2;
            float b0 = bias[col], b1 = bias[col + 1];
            float* cp = acc[mt][nt];
            if (row < M)     *(float2*)&C[(long long)row * 128 + col]       = make_float2(cp[0] + b0, cp[1] + b1);
            if (row + 8 < M) *(float2*)&C[(long long)(row + 8) * 128 + col] = make_float2(cp[2] + b0, cp[3] + b1);
        }
    }
}

// ---------------- FF-a GEMM: hid = relu(A(*mulp)[38400x128] @ W[128x2048] + bias) ----------------
#define FFA_AS 4608
#define FFA_BS 8448
#define FFA_SMEM_FLOATS (3 * (FFA_AS + FFA_BS))
__global__ void __launch_bounds__(256) ffa_gemm(
    const float* __restrict__ A, const float* __restrict__ W,
    const float* __restrict__ bias, const float* __restrict__ mulp,
    float* __restrict__ C)
{
    extern __shared__ float smf[];
    float* As = smf;
    float* Bs = smf + 3 * FFA_AS;
    const unsigned sA = (unsigned)__cvta_generic_to_shared(As);
    const unsigned sB = (unsigned)__cvta_generic_to_shared(Bs);
    const int tid = threadIdx.x;
    const int lane = tid & 31, w = tid >> 5;
    const int mw = (w >> 2) * 64, nw = (w & 3) * 64;
    const int rowBlk = blockIdx.x * 128, colBlk = blockIdx.y * 256;
    const int gp = lane >> 2, tg = lane & 3;

    float acc[4][8][4];
#pragma unroll
    for (int mt = 0; mt < 4; mt++)
#pragma unroll
        for (int nt = 0; nt < 8; nt++)
#pragma unroll
            for (int i = 0; i < 4; i++) acc[mt][nt][i] = 0.f;

    auto issue = [&](int t) {
        if (t < 4) {
            int s = t % 3, k0 = t * 32;
            if (mulp == nullptr) {
#pragma unroll
                for (int i = 0; i < 4; i++) {
                    int idx = tid + i * 256;
                    int r = idx >> 3, kq = idx & 7;
                    cpa16(sA + (s * FFA_AS + r * 36 + kq * 4) * 4,
                          A + (long long)(rowBlk + r) * 128 + k0 + kq * 4, true);
                }
            } else {
#pragma unroll
                for (int i = 0; i < 4; i++) {
                    int idx = tid + i * 256;
                    int r = idx >> 3, kq = idx & 7;
                    int row = rowBlk + r;
                    float4 av = *(const float4*)(A + (long long)row * 128 + k0 + kq * 4);
                    float4 mv = *(const float4*)(mulp + (row % 400) * 128 + k0 + kq * 4);
                    *(float4*)(As + s * FFA_AS + r * 36 + kq * 4) =
                        make_float4(av.x * mv.x, av.y * mv.y, av.z * mv.z, av.w * mv.w);
                }
            }
#pragma unroll
            for (int i = 0; i < 8; i++) {
                int idx = tid + i * 256;
                int kk = idx >> 6, nq = idx & 63;
                cpa16(sB + (s * FFA_BS + kk * 264 + nq * 4) * 4,
                      W + (long long)(k0 + kk) * 2048 + colBlk + nq * 4, true);
            }
        }
        CP_COMMIT();
    };

    issue(0); issue(1);
    for (int t = 0; t < 4; t++) {
        CP_WAIT1();
        __syncthreads();
        const unsigned* Ad = (const unsigned*)(As + (t % 3) * FFA_AS);
        const unsigned* Bd = (const unsigned*)(Bs + (t % 3) * FFA_BS);
#pragma unroll
        for (int ks = 0; ks < 32; ks += 8) {
            unsigned a[4][4], b[8][2];
#pragma unroll
            for (int mt = 0; mt < 4; mt++) {
                int r = mw + mt * 16 + gp;
                a[mt][0] = Ad[r * 36 + ks + tg];
                a[mt][1] = Ad[(r + 8) * 36 + ks + tg];
                a[mt][2] = Ad[r * 36 + ks + tg + 4];
                a[mt][3] = Ad[(r + 8) * 36 + ks + tg + 4];
            }
#pragma unroll
            for (int nt = 0; nt < 8; nt++) {
                int n = nw + nt * 8 + gp;
                b[nt][0] = Bd[(ks + tg) * 264 + n];
                b[nt][1] = Bd[(ks + tg + 4) * 264 + n];
            }
#pragma unroll
            for (int mt = 0; mt < 4; mt++)
#pragma unroll
                for (int nt = 0; nt < 8; nt++)
                    mma8(acc[mt][nt], a[mt], b[nt]);
        }
        issue(t + 2);
    }
#pragma unroll
    for (int mt = 0; mt < 4; mt++) {
        long long row = rowBlk + mw + mt * 16 + gp;
#pragma unroll
        for (int nt = 0; nt < 8; nt++) {
            int col = colBlk + nw + nt * 8 + tg * 2;
            float b0 = bias[col], b1 = bias[col + 1];
            float* cp = acc[mt][nt];
            *(float2*)&C[row * 2048 + col] =
                make_float2(fmaxf(cp[0] + b0, 0.f), fmaxf(cp[1] + b1, 0.f));
            *(float2*)&C[(row + 8) * 2048 + col] =
                make_float2(fmaxf(cp[2] + b0, 0.f), fmaxf(cp[3] + b1, 0.f));
        }
    }
}

// ---------------- FF-b GEMM: C[38400x128] = hid[38400x2048] @ W[2048x128] + bias ----------------
// block tile 256x128, 8 warps (4M x 2N), warp tile 64x64, k-chunk 32, 3-stage cp.async.
#define FFB_AS 9216   // 256*36
#define FFB_BS 4352   // 32*136
#define FFB_SMEM_FLOATS (3 * (FFB_AS + FFB_BS))
__global__ void __launch_bounds__(256) ffb_gemm(
    const float* __restrict__ A, const float* __restrict__ W,
    const float* __restrict__ bias, float* __restrict__ C)
{
    extern __shared__ float smf[];
    float* As = smf;
    float* Bs = smf + 3 * FFB_AS;
    const unsigned sA = (unsigned)__cvta_generic_to_shared(As);
    const unsigned sB = (unsigned)__cvta_generic_to_shared(Bs);
    const int tid = threadIdx.x;
    const int lane = tid & 31, w = tid >> 5;
    const int mw = (w >> 1) * 64, nw = (w & 1) * 64;
    const int rowBlk = blockIdx.x * 256;
    const int gp = lane >> 2, tg = lane & 3;

    float acc[4][8][4];
#pragma unroll
    for (int mt = 0; mt < 4; mt++)
#pragma unroll
        for (int nt = 0; nt < 8; nt++)
#pragma unroll
            for (int i = 0; i < 4; i++) acc[mt][nt][i] = 0.f;

    auto issue = [&](int t) {
        if (t < 64) {
            int s = t % 3, k0 = t * 32;
#pragma unroll
            for (int i = 0; i < 8; i++) {
                int idx = tid + i * 256;
                int r = idx >> 3, kq = idx & 7;
                cpa16(sA + (s * FFB_AS + r * 36 + kq * 4) * 4,
                      A + (long long)(rowBlk + r) * 2048 + k0 + kq * 4, true);
            }
#pragma unroll
            for (int i = 0; i < 4; i++) {
                int idx = tid + i * 256;
                int kk = idx >> 5, nq = idx & 31;
                cpa16(sB + (s * FFB_BS + kk * 136 + nq * 4) * 4,
                      W + (long long)(k0 + kk) * 128 + nq * 4, true);
            }
        }
        CP_COMMIT();
    };

    issue(0); issue(1);
    for (int t = 0; t < 64; t++) {
        CP_WAIT1();
        __syncthreads();
        const unsigned* Ad = (const unsigned*)(As + (t % 3) * FFB_AS);
        const unsigned* Bd = (const unsigned*)(Bs + (t % 3) * FFB_BS);
#pragma unroll
        for (int ks = 0; ks < 32; ks += 8) {
            unsigned a[4][4], b[8][2];
#pragma unroll
            for (int mt = 0; mt < 4; mt++) {
                int r = mw + mt * 16 + gp;
                a[mt][0] = Ad[r * 36 + ks + tg];
                a[mt][1] = Ad[(r + 8) * 36 + ks + tg];
                a[mt][2] = Ad[r * 36 + ks + tg + 4];
                a[mt][3] = Ad[(r + 8) * 36 + ks + tg + 4];
            }
#pragma unroll
            for (int nt = 0; nt < 8; nt++) {
                int n = nw + nt * 8 + gp;
                b[nt][0] = Bd[(ks + tg) * 136 + n];
                b[nt][1] = Bd[(ks + tg + 4) * 136 + n];
            }
#pragma unroll
            for (int mt = 0; mt < 4; mt++)
#pragma unroll
                for (int nt = 0; nt < 8; nt++)
                    mma8(acc[mt][nt], a[mt], b[nt]);
        }
        issue(t + 2);
    }
#pragma unroll
    for (int mt = 0; mt < 4; mt++) {
        long long row = rowBlk + mw + mt * 16 + gp;
#pragma unroll
        for (int nt = 0; nt < 8; nt++) {
            int col = nw + nt * 8 + tg * 2;
            float b0 = bias[col], b1 = bias[col + 1];
            float* cp = acc[mt][nt];
            *(float2*)&C[row * 128 + col]       = make_float2(cp[0] + b0, cp[1] + b1);
            *(float2*)&C[(row + 8) * 128 + col] = make_float2(cp[2] + b0, cp[3] + b1);
        }
    }
}

// ---------------- tensor-core full attention (400 keys), 2 blocks/SM ----------------
#define ATT_KT 0
#define ATT_VT 6528
#define ATT_S  12992
#define ATT_QS 25920
#define ATT_PO 25920
#define ATT_LS 28096
#define ATT_TC_FLOATS 28128
__global__ void __launch_bounds__(256) attn_tc_kernel(
    const float* __restrict__ q, const float* __restrict__ k, const float* __restrict__ v,
    float* __restrict__ o)
{
    extern __shared__ float sm[];
    float* Kt = sm + ATT_KT;
    float* Vt = sm + ATT_VT;
    float* S  = sm + ATT_S;
    float* Qs = sm + ATT_QS;
    float* ls = sm + ATT_LS;
    float* Po = sm + ATT_PO;
    int bid = blockIdx.x, bt = bid >> 3, h = bid & 7;
    int tid = threadIdx.x, lane = tid & 31, w = tid >> 5;
    int gp = lane >> 2, tg = lane & 3;
    int base = bt * 400 * 128 + h * 16;

    for (int i = tid; i < 6400; i += 256) {
        int key = i >> 4, d = i & 15;
        Kt[d * 408 + key] = k[base + key * 128 + d];
        Vt[d * 404 + key] = v[base + key * 128 + d];
    }
    __syncthreads();

    const unsigned* Ku = (const unsigned*)Kt;
    const unsigned* Vu = (const unsigned*)Vt;
    const unsigned* Qu = (const unsigned*)Qs;
    const unsigned* Pu = (const unsigned*)S;

    for (int qt = 0; qt < 400; qt += 32) {
        for (int i = tid; i < 512; i += 256) {
            int r = i >> 4, d = i & 15;
            int qr = qt + r;
            Qs[r * 20 + d] = (qr < 400) ? q[base + qr * 128 + d] : 0.f;
        }
        __syncthreads();
        {
            unsigned af[2][2][4];
#pragma unroll
            for (int mt = 0; mt < 2; mt++)
#pragma unroll
                for (int ksi = 0; ksi < 2; ksi++) {
                    int r = mt * 16 + gp, ks = ksi * 8;
                    af[mt][ksi][0] = Qu[r * 20 + ks + tg];
                    af[mt][ksi][1] = Qu[(r + 8) * 20 + ks + tg];
                    af[mt][ksi][2] = Qu[r * 20 + ks + tg + 4];
                    af[mt][ksi][3] = Qu[(r + 8) * 20 + ks + tg + 4];
                }
            for (int nt = w; nt < 50; nt += 8) {
                float c0[4] = {0.f, 0.f, 0.f, 0.f};
                float c1[4] = {0.f, 0.f, 0.f, 0.f};
#pragma unroll
                for (int ksi = 0; ksi < 2; ksi++) {
                    int ks = ksi * 8;
                    unsigned b[2];
                    b[0] = Ku[(ks + tg) * 408 + nt * 8 + gp];
                    b[1] = Ku[(ks + tg + 4) * 408 + nt * 8 + gp];
                    mma8(c0, af[0][ksi], b);
                    mma8(c1, af[1][ksi], b);
                }
                int cc = nt * 8 + tg * 2;
                S[gp * 404 + cc]            = c0[0] * 0.25f;
                S[gp * 404 + cc + 1]        = c0[1] * 0.25f;
                S[(gp + 8) * 404 + cc]      = c0[2] * 0.25f;
                S[(gp + 8) * 404 + cc + 1]  = c0[3] * 0.25f;
                S[(gp + 16) * 404 + cc]     = c1[0] * 0.25f;
                S[(gp + 16) * 404 + cc + 1] = c1[1] * 0.25f;
                S[(gp + 24) * 404 + cc]     = c1[2] * 0.25f;
                S[(gp + 24) * 404 + cc + 1] = c1[3] * 0.25f;
            }
        }
        __syncthreads();
        for (int rr = 0; rr < 4; rr++) {
            int row = w * 4 + rr;
            float sc[13];
            float m = -3.4e38f;
#pragma unroll
            for (int j = 0; j < 13; j++) {
                int kk = lane + j * 32;
                float s_ = (kk < 400) ? S[row * 404 + kk] : -3.4e38f;
                sc[j] = s_; m = fmaxf(m, s_);
            }
#pragma unroll
            for (int off = 16; off; off >>= 1) m = fmaxf(m, __shfl_xor_sync(0xffffffffu, m, off));
            float l = 0.f;
#pragma unroll
            for (int j = 0; j < 13; j++) {
                int kk = lane + j * 32;
                if (kk < 400) {
                    float p_ = __expf(sc[j] - m);
                    S[row * 404 + kk] = p_;
                    l += p_;
                }
            }
#pragma unroll
            for (int off = 16; off; off >>= 1) l += __shfl_xor_sync(0xffffffffu, l, off);
            if (lane == 0) ls[row] = 1.f / l;
        }
        __syncthreads();
        {
            int mt = w & 1, nt = (w >> 1) & 1, kh = w >> 2;
            float c[4] = {0.f, 0.f, 0.f, 0.f};
            int kbase = kh * 200;
#pragma unroll 5
            for (int i = 0; i < 25; i++) {
                int k0 = kbase + i * 8;
                unsigned a[4], b[2];
                a[0] = Pu[(mt * 16 + gp) * 404 + k0 + tg];
                a[1] = Pu[(mt * 16 + gp + 8) * 404 + k0 + tg];
                a[2] = Pu[(mt * 16 + gp) * 404 + k0 + tg + 4];
                a[3] = Pu[(mt * 16 + gp + 8) * 404 + k0 + tg + 4];
                b[0] = Vu[(nt * 8 + gp) * 404 + k0 + tg];
                b[1] = Vu[(nt * 8 + gp) * 404 + k0 + tg + 4];
                mma8(c, a, b);
            }
            int r0 = mt * 16 + gp, d0 = nt * 8 + tg * 2;
            if (kh == 1) {
                Po[r0 * 68 + d0]           = c[0];
                Po[r0 * 68 + d0 + 1]       = c[1];
                Po[(r0 + 8) * 68 + d0]     = c[2];
                Po[(r0 + 8) * 68 + d0 + 1] = c[3];
            }
            __syncthreads();
            if (kh == 0) {
                float s0 = ls[r0], s1 = ls[r0 + 8];
                int qr0 = qt + r0, qr1 = qt + r0 + 8;
                if (qr0 < 400) {
                    o[base + qr0 * 128 + d0]     = (c[0] + Po[r0 * 68 + d0]) * s0;
                    o[base + qr0 * 128 + d0 + 1] = (c[1] + Po[r0 * 68 + d0 + 1]) * s0;
                }
                if (qr1 < 400) {
                    o[base + qr1 * 128 + d0]     = (c[2] + Po[(r0 + 8) * 68 + d0]) * s1;
                    o[base + qr1 * 128 + d0 + 1] = (c[3] + Po[(r0 + 8) * 68 + d0 + 1]) * s1;
                }
            }
        }
        __syncthreads();
    }
}

// ---------------- LayerNorm of (a [+ b] [+ c] [+ d]), optional +addp ----------------
__global__ void __launch_bounds__(128) ln_kernel(
    const float* __restrict__ a, const float* __restrict__ b,
    const float* __restrict__ c, const float* __restrict__ d,
    const float* __restrict__ gamma, const float* __restrict__ beta,
    float* __restrict__ out, const float* __restrict__ addp)
{
    __shared__ float red[8];
    long long idx = (long long)blockIdx.x * 128 + threadIdx.x;
    float v = a[idx];
    if (b) v += b[idx];
    if (c) v += c[idx];
    if (d) v += d[idx];
    float s = v, ss = v * v;
#pragma unroll
    for (int o = 16; o; o >>= 1) {
        s  += __shfl_xor_sync(0xffffffffu, s,  o);
        ss += __shfl_xor_sync(0xffffffffu, ss, o);
    }
    int w = threadIdx.x >> 5;
    if ((threadIdx.x & 31) == 0) { red[w] = s; red[4 + w] = ss; }
    __syncthreads();
    s  = red[0] + red[1] + red[2] + red[3];
    ss = red[4] + red[5] + red[6] + red[7];
    float m = s * (1.f / 128.f);
    float var = ss * (1.f / 128.f) - m * m;
    float inv = rsqrtf(var + 1e-5f);
    float r = (v - m) * inv * gamma[threadIdx.x] + beta[threadIdx.x];
    if (addp) r += addp[idx];
    out[idx] = r;
}

// ---------------- adaptive avg pool over node axis ----------------
__global__ void __launch_bounds__(128) pool_kernel(const float* __restrict__ x, float* __restrict__ xp)
{
    int bid = blockIdx.x;
    int bt = bid >> 6, c = bid & 63;
    int s = (c * 400) >> 6;
    int e = ((c + 1) * 400 + 63) >> 6;
    float sum = 0.f;
    for (int n = s; n < e; ++n) sum += x[(bt * 400 + n) * 128 + threadIdx.x];
    xp[bid * 128 + threadIdx.x] = sum / (float)(e - s);
}

// ---------------- GEANet per row (mode 0: node permuted store, 1: edge) ----------------
__global__ void __launch_bounds__(128) gea_kernel(
    const float* __restrict__ in, const float* __restrict__ w, const float* __restrict__ bb,
    float* __restrict__ outp, int mode)
{
    __shared__ float xr[128], tmp[128], s1[16], rs[8], w0[256], w1[256], b0v[16], b1v[16];
    int tid = threadIdx.x;
    int h = tid >> 4, u = tid & 15;
    w0[tid] = w[tid];        w0[128 + tid] = w[128 + tid];
    w1[tid] = w[256 + tid];  w1[128 + tid] = w[384 + tid];
    if (tid < 16) { b0v[tid] = bb[tid]; b1v[tid] = bb[16 + tid]; }
    int id = blockIdx.x;
    if (mode == 0) xr[tid] = in[id * 128 + tid];
    else           xr[tid] = in[id * 128 + u * 8 + h];
    __syncthreads();

    float a = b0v[u];
#pragma unroll
    for (int k = 0; k < 16; k++) a += xr[h * 16 + k] * w0[k * 16 + u];
    tmp[tid] = a;
    __syncthreads();
    float m = tmp[u];
#pragma unroll
    for (int hh = 1; hh < 8; hh++) m = fmaxf(m, tmp[hh * 16 + u]);
    float ev = __expf(a - m);
    __syncthreads();
    tmp[tid] = ev;
    __syncthreads();
    if (tid < 16) { float s = 0.f; for (int hh = 0; hh < 8; hh++) s += tmp[hh * 16 + tid]; s1[tid] = s; }
    __syncthreads();
    float vv = ev / s1[u];
    __syncthreads();
    tmp[tid] = vv;
    __syncthreads();
    if (tid < 8) { float s = 0.f; for (int uu = 0; uu < 16; uu++) s += tmp[tid * 16 + uu]; rs[tid] = s; }
    __syncthreads();
    float dn = vv / rs[h];
    __syncthreads();
    tmp[tid] = dn;
    __syncthreads();
    float o = b1v[u];
#pragma unroll
    for (int k = 0; k < 16; k++) o += tmp[h * 16 + k] * w1[k * 16 + u];

    if (mode == 0) {
        int b = id / 4800, r2 = id % 4800, t = r2 / 400, n = r2 % 400;
        outp[((b * 400 + n) * 12 + t) * 128 + tid] = o;
    } else {
        outp[id * 128 + tid] = o;
    }
}

// ---------------- pooled attention, 64 keys + positional bias ----------------
__global__ void __launch_bounds__(256) attn_pool_kernel(
    const float* __restrict__ q, const float* __restrict__ kp, const float* __restrict__ vp,
    const float* __restrict__ pos, float* __restrict__ o)
{
    __shared__ float Ks[16 * 65], Vs[16 * 65], pball[8 * 64];
    int bid = blockIdx.x;
    int bt = bid >> 3, h = bid & 7;
    int tid = threadIdx.x;
    int kbase = bt * 64 * 128 + h * 16;
    int qbase = bt * 400 * 128 + h * 16;
    for (int i = tid; i < 1024; i += 256) {
        int kk = i >> 4, d = i & 15;
        Ks[d * 65 + kk] = kp[kbase + kk * 128 + d];
        Vs[d * 65 + kk] = vp[kbase + kk * 128 + d];
    }
    __syncthreads();
    int warp = tid >> 5, lane = tid & 31;
    float* pb = pball + warp * 64;
    for (int qi = warp; qi < 400; qi += 8) {
        float qd[16];
#pragma unroll
        for (int d = 0; d < 16; d++) qd[d] = q[qbase + qi * 128 + d];
        float sc[2];
        float m = -3.4e38f;
#pragma unroll
        for (int j = 0; j < 2; j++) {
            int kk = lane + 32 * j;
            float s = 0.f;
#pragma unroll
            for (int d = 0; d < 16; d++) s += qd[d] * Ks[d * 65 + kk];
            s = s * 0.25f + pos[qi * 64 + kk];
            sc[j] = s; m = fmaxf(m, s);
        }
#pragma unroll
        for (int off = 16; off; off >>= 1) m = fmaxf(m, __shfl_xor_sync(0xffffffffu, m, off));
        float lsum = 0.f;
#pragma unroll
        for (int j = 0; j < 2; j++) { float p = __expf(sc[j] - m); sc[j] = p; lsum += p; }
#pragma unroll
        for (int off = 16; off; off >>= 1) lsum += __shfl_xor_sync(0xffffffffu, lsum, off);
        pb[lane] = sc[0]; pb[lane + 32] = sc[1];
        __syncwarp();
        int d = lane & 15, half = lane >> 4;
        float acc = 0.f;
#pragma unroll
        for (int i = 0; i < 32; ++i) { int c = 2 * i + half; acc += pb[c] * Vs[d * 65 + c]; }
        acc += __shfl_xor_sync(0xffffffffu, acc, 16);
        if (lane < 16) o[qbase + qi * 128 + d] = acc / lsum;
        __syncwarp();
    }
}

__global__ void copy_kernel(const float* __restrict__ a, float* __restrict__ o, int n)
{
    int i = blockIdx.x * 256 + threadIdx.x;
    if (i < n) o[i] = a[i];
}

// ---------------- host ----------------
static float* sym(const void* s) { void* p = nullptr; cudaGetSymbolAddress(&p, s); return (float*)p; }

extern "C" void kernel_launch(void* const* d_in, const int* in_sizes, int n_in,
                              void* d_out, int out_size)
{
    const float* x      = (const float*)d_in[0];
    const float* semb   = (const float*)d_in[1];
    const float* dqkv_w = (const float*)d_in[2];
    const float* dqkv_b = (const float*)d_in[3];
    const float* dout_w = (const float*)d_in[4];
    const float* dout_b = (const float*)d_in[5];
    const float* aqkv_w = (const float*)d_in[6];
    const float* aqkv_b = (const float*)d_in[7];
    const float* aout_w = (const float*)d_in[8];
    const float* aout_b = (const float*)d_in[9];
    const float* adp_pos= (const float*)d_in[10];
    const float* gsh_w  = (const float*)d_in[11];
    const float* gsh_b  = (const float*)d_in[12];
    const float* gnode_w= (const float*)d_in[13];
    const float* gnode_b= (const float*)d_in[14];
    const float* gedge_w= (const float*)d_in[15];
    const float* gedge_b= (const float*)d_in[16];
    const float* sp_w   = (const float*)d_in[17];
    const float* sp_b   = (const float*)d_in[18];
    const float* f1w1   = (const float*)d_in[19];
    const float* f1b1   = (const float*)d_in[20];
    const float* f1w2   = (const float*)d_in[21];
    const float* f1b2   = (const float*)d_in[22];
    const float* f2w1   = (const float*)d_in[23];
    const float* f2b1   = (const float*)d_in[24];
    const float* f2w2   = (const float*)d_in[25];
    const float* f2b2   = (const float*)d_in[26];
    const float* lns    = (const float*)d_in[27];
    const float* lnb    = (const float*)d_in[28];
    float* out = (float*)d_out;

    float *q = sym(g_q), *k = sym(g_k), *v = sym(g_v), *o = sym(g_o);
    float *dtw = sym(g_dtw), *ex = sym(g_ex), *res = sym(g_res), *tmp = sym(g_tmp);
    float *hid = sym(g_hid);
    float *xp = sym(g_xp), *kp = sym(g_kp), *vp = sym(g_vp);
    float *sen = sym(g_sen), *edge = sym(g_edge), *senx = sym(g_senx);

    const int GEMM_SMEM = 3 * (4608 + 4352) * 4;   // 107520 B
    const int ATT_SMEM  = ATT_TC_FLOATS * 4;       // 112512 B -> 2 blocks/SM
    const int FFA_SMEM  = FFA_SMEM_FLOATS * 4;     // 156672 B
    const int FFB_SMEM  = FFB_SMEM_FLOATS * 4;     // 162816 B
    cudaFuncSetAttribute(mma_gemm,   cudaFuncAttributeMaxDynamicSharedMemorySize, GEMM_SMEM);
    cudaFuncSetAttribute(mma_gemm_b, cudaFuncAttributeMaxDynamicSharedMemorySize, GEMM_SMEM);
    cudaFuncSetAttribute(attn_tc_kernel, cudaFuncAttributeMaxDynamicSharedMemorySize, ATT_SMEM);
    cudaFuncSetAttribute(ffa_gemm, cudaFuncAttributeMaxDynamicSharedMemorySize, FFA_SMEM);
    cudaFuncSetAttribute(ffb_gemm, cudaFuncAttributeMaxDynamicSharedMemorySize, FFB_SMEM);

    // batch 1: five projections reading x -> dq, dk, dv, aq(in tmp), gshare(in res)
    GSet b1;
    b1.A[0] = x; b1.W[0] = dqkv_w;          b1.Bv[0] = dqkv_b;        b1.C[0] = q;
    b1.A[1] = x; b1.W[1] = dqkv_w + 16384;  b1.Bv[1] = dqkv_b + 128;  b1.C[1] = k;
    b1.A[2] = x; b1.W[2] = dqkv_w + 32768;  b1.Bv[2] = dqkv_b + 256;  b1.C[2] = v;
    b1.A[3] = x; b1.W[3] = aqkv_w;          b1.Bv[3] = aqkv_b;        b1.C[3] = tmp;
    b1.A[4] = x; b1.W[4] = gsh_w;           b1.Bv[4] = gsh_b;         b1.C[4] = res;
    mma_gemm_b<<<dim3(300, 5), 256, GEMM_SMEM>>>(b1, ROWS);

    pool_kernel<<<6144, 128>>>(x, xp);

    // batch 2: pooled K/V (pool(xW+b) == (pool x)W + b)
    GSet b2;
    b2.A[0] = xp; b2.W[0] = aqkv_w + 16384; b2.Bv[0] = aqkv_b + 128; b2.C[0] = kp;
    b2.A[1] = xp; b2.W[1] = aqkv_w + 32768; b2.Bv[1] = aqkv_b + 256; b2.C[1] = vp;
    b2.A[2] = xp; b2.W[2] = aqkv_w;         b2.Bv[2] = aqkv_b;       b2.C[2] = kp;
    b2.A[3] = b2.A[2]; b2.W[3] = b2.W[2];   b2.Bv[3] = b2.Bv[2];     b2.C[3] = kp;
    b2.A[4] = b2.A[2]; b2.W[4] = b2.W[2];   b2.Bv[4] = b2.Bv[2];     b2.C[4] = kp;
    mma_gemm_b<<<dim3(48, 2), 256, GEMM_SMEM>>>(b2, 6144);

    // attentions
    attn_tc_kernel<<<768, 256, ATT_SMEM>>>(q, k, v, o);
    attn_pool_kernel<<<768, 256>>>(tmp, kp, vp, adp_pos, hid);   // pooled-attn out -> hid temp

    // batch 3: output projections (dtw-out, adp-out)
    GSet b3;
    b3.A[0] = o;   b3.W[0] = dout_w; b3.Bv[0] = dout_b; b3.C[0] = dtw;
    b3.A[1] = hid; b3.W[1] = aout_w; b3.Bv[1] = aout_b; b3.C[1] = k;    // oa -> k
    b3.A[2] = b3.A[0]; b3.W[2] = b3.W[0]; b3.Bv[2] = b3.Bv[0]; b3.C[2] = dtw;
    b3.A[3] = b3.A[0]; b3.W[3] = b3.W[0]; b3.Bv[3] = b3.Bv[0]; b3.C[3] = dtw;
    b3.A[4] = b3.A[0]; b3.W[4] = b3.W[0]; b3.Bv[4] = b3.Bv[0]; b3.C[4] = dtw;
    mma_gemm_b<<<dim3(300, 2), 256, GEMM_SMEM>>>(b3, ROWS);

    // GEANet node (consumes gshare in res)
    gea_kernel<<<ROWS, 128>>>(res, gnode_w, gnode_b, ex, 0);

    // sen + GEANet edge
    mma_gemm<<<4, 256, GEMM_SMEM>>>(semb, sp_w, sp_b, sen, 400);
    ln_kernel<<<400, 128>>>(sen, nullptr, nullptr, nullptr, lns + 3 * 128, lnb + 3 * 128, sen, nullptr);
    mma_gemm<<<4, 256, GEMM_SMEM>>>(sen, gsh_w, gsh_b, edge, 400);
    gea_kernel<<<400, 128>>>(edge, gedge_w, gedge_b, senx, 1);
    if (out_size >= BIG + 51200)
        copy_kernel<<<(51200 + 255) / 256, 256>>>(senx, out + BIG, 51200);

    // out = LN(x + dtw + oa + extra)
    ln_kernel<<<ROWS, 128>>>(x, dtw, k, ex, lns, lnb, res, nullptr);

    // out_attn = LN(FF1(out) + out)
    ffa_gemm<<<dim3(300, 8), 256, FFA_SMEM>>>(res, f1w1, f1b1, nullptr, hid);
    ffb_gemm<<<150, 256, FFB_SMEM>>>(hid, f1w2, f1b2, tmp);
    ln_kernel<<<ROWS, 128>>>(tmp, res, nullptr, nullptr, lns + 128, lnb + 128, dtw, nullptr); // out_attn -> dtw

    // sp = LN(FF2(out_attn * sen_extra)); final out = out_attn + sp fused into LN
    ffa_gemm<<<dim3(300, 8), 256, FFA_SMEM>>>(dtw, f2w1, f2b1, senx, hid);
    ffb_gemm<<<150, 256, FFB_SMEM>>>(hid, f2w2, f2b2, tmp);
    ln_kernel<<<ROWS, 128>>>(tmp, nullptr, nullptr, nullptr, lns + 256, lnb + 256, out, dtw);
}

// round 14
// speedup vs baseline: 5.6680x; 1.0960x over previous
#include <cuda_runtime.h>

#define ROWS 38400
#define BIG  4915200

// ---------------- device scratch ----------------
__device__ float g_q[BIG];
__device__ float g_k[BIG];
__device__ float g_v[BIG];
__device__ float g_o[BIG];
__device__ float g_dtw[BIG];
__device__ float g_ex[BIG];
__device__ float g_res[BIG];
__device__ float g_tmp[BIG];
__device__ float g_hid[78643200];   // 38400 x 2048 FF hidden (also temp for pooled-attn out)
__device__ float g_xp[786432];
__device__ float g_kp[786432];
__device__ float g_vp[786432];
__device__ float g_sen[51200];
__device__ float g_edge[51200];
__device__ float g_senx[51200];

// ---------------- mma / cp.async helpers ----------------
__device__ __forceinline__ void mma8(float* c, const unsigned* a, const unsigned* b) {
    asm volatile(
        "mma.sync.aligned.m16n8k8.row.col.f32.tf32.tf32.f32 "
        "{%0,%1,%2,%3}, {%4,%5,%6,%7}, {%8,%9}, {%0,%1,%2,%3};"
        : "+f"(c[0]), "+f"(c[1]), "+f"(c[2]), "+f"(c[3])
        : "r"(a[0]), "r"(a[1]), "r"(a[2]), "r"(a[3]), "r"(b[0]), "r"(b[1]));
}
__device__ __forceinline__ void cpa16(unsigned dst, const float* src, bool p) {
    int sz = p ? 16 : 0;
    asm volatile("cp.async.cg.shared.global [%0], [%1], 16, %2;"
                 :: "r"(dst), "l"(src), "r"(sz));
}
#define CP_COMMIT() asm volatile("cp.async.commit_group;")
#define CP_WAIT1()  asm volatile("cp.async.wait_group 1;")

// ---------------- batched tf32 GEMM (N=K=128): C_y = A_y @ W_y + b_y ----------------
struct GSet {
    const float* A[5];
    const float* W[5];
    const float* Bv[5];
    float*       C[5];
};
__global__ void __launch_bounds__(256) mma_gemm_b(GSet g, int M)
{
    extern __shared__ float smf[];
    float* As = smf;                 // 3 x 4608
    float* Bs = smf + 3 * 4608;      // 3 x 4352
    const unsigned sA = (unsigned)__cvta_generic_to_shared(As);
    const unsigned sB = (unsigned)__cvta_generic_to_shared(Bs);
    const int y = blockIdx.y;
    const float* __restrict__ A = g.A[y];
    const float* __restrict__ W = g.W[y];
    const float* __restrict__ bias = g.Bv[y];
    float* __restrict__ C = g.C[y];
    const int tid = threadIdx.x;
    const int lane = tid & 31, w = tid >> 5;
    const int mw = (w >> 1) * 32, nw = (w & 1) * 64;
    const int rowBlk = blockIdx.x * 128;
    const int gp = lane >> 2, tg = lane & 3;

    float acc[2][8][4];
#pragma unroll
    for (int mt = 0; mt < 2; mt++)
#pragma unroll
        for (int nt = 0; nt < 8; nt++)
#pragma unroll
            for (int i = 0; i < 4; i++) acc[mt][nt][i] = 0.f;

    auto issue = [&](int t) {
        if (t < 4) {
            int s = t % 3, k0 = t * 32;
#pragma unroll
            for (int i = 0; i < 4; i++) {
                int idx = tid + i * 256;
                int r = idx >> 3, kq = idx & 7;
                int row = rowBlk + r;
                bool p = row < M;
                int rc = p ? row : (M - 1);
                cpa16(sA + (s * 4608 + r * 36 + kq * 4) * 4,
                      A + (long long)rc * 128 + k0 + kq * 4, p);
            }
#pragma unroll
            for (int i = 0; i < 4; i++) {
                int idx = tid + i * 256;
                int kk = idx >> 5, nq = idx & 31;
                cpa16(sB + (s * 4352 + kk * 136 + nq * 4) * 4,
                      W + (long long)(k0 + kk) * 128 + nq * 4, true);
            }
        }
        CP_COMMIT();
    };

    issue(0); issue(1);
    for (int t = 0; t < 4; t++) {
        CP_WAIT1();
        __syncthreads();
        const unsigned* Ad = (const unsigned*)(As + (t % 3) * 4608);
        const unsigned* Bd = (const unsigned*)(Bs + (t % 3) * 4352);
#pragma unroll
        for (int ks = 0; ks < 32; ks += 8) {
            unsigned a[2][4], b[8][2];
#pragma unroll
            for (int mt = 0; mt < 2; mt++) {
                int r = mw + mt * 16 + gp;
                a[mt][0] = Ad[r * 36 + ks + tg];
                a[mt][1] = Ad[(r + 8) * 36 + ks + tg];
                a[mt][2] = Ad[r * 36 + ks + tg + 4];
                a[mt][3] = Ad[(r + 8) * 36 + ks + tg + 4];
            }
#pragma unroll
            for (int nt = 0; nt < 8; nt++) {
                int n = nw + nt * 8 + gp;
                b[nt][0] = Bd[(ks + tg) * 136 + n];
                b[nt][1] = Bd[(ks + tg + 4) * 136 + n];
            }
#pragma unroll
            for (int mt = 0; mt < 2; mt++)
#pragma unroll
                for (int nt = 0; nt < 8; nt++)
                    mma8(acc[mt][nt], a[mt], b[nt]);
        }
        issue(t + 2);
    }
#pragma unroll
    for (int mt = 0; mt < 2; mt++) {
        int row = rowBlk + mw + mt * 16 + gp;
#pragma unroll
        for (int nt = 0; nt < 8; nt++) {
            int col = nw + nt * 8 + tg * 2;
            float b0 = bias[col], b1 = bias[col + 1];
            float* cp = acc[mt][nt];
            if (row < M)     *(float2*)&C[(long long)row * 128 + col]       = make_float2(cp[0] + b0, cp[1] + b1);
            if (row + 8 < M) *(float2*)&C[(long long)(row + 8) * 128 + col] = make_float2(cp[2] + b0, cp[3] + b1);
        }
    }
}

// ---------------- generic small GEMM (sen chain) ----------------
__global__ void __launch_bounds__(256) mma_gemm(
    const float* __restrict__ A, const float* __restrict__ W,
    const float* __restrict__ bias, float* __restrict__ C, int M)
{
    extern __shared__ float smf[];
    float* As = smf;
    float* Bs = smf + 3 * 4608;
    const unsigned sA = (unsigned)__cvta_generic_to_shared(As);
    const unsigned sB = (unsigned)__cvta_generic_to_shared(Bs);
    const int tid = threadIdx.x;
    const int lane = tid & 31, w = tid >> 5;
    const int mw = (w >> 1) * 32, nw = (w & 1) * 64;
    const int rowBlk = blockIdx.x * 128;
    const int gp = lane >> 2, tg = lane & 3;

    float acc[2][8][4];
#pragma unroll
    for (int mt = 0; mt < 2; mt++)
#pragma unroll
        for (int nt = 0; nt < 8; nt++)
#pragma unroll
            for (int i = 0; i < 4; i++) acc[mt][nt][i] = 0.f;

    auto issue = [&](int t) {
        if (t < 4) {
            int s = t % 3, k0 = t * 32;
#pragma unroll
            for (int i = 0; i < 4; i++) {
                int idx = tid + i * 256;
                int r = idx >> 3, kq = idx & 7;
                int row = rowBlk + r;
                bool p = row < M;
                int rc = p ? row : (M - 1);
                cpa16(sA + (s * 4608 + r * 36 + kq * 4) * 4,
                      A + (long long)rc * 128 + k0 + kq * 4, p);
            }
#pragma unroll
            for (int i = 0; i < 4; i++) {
                int idx = tid + i * 256;
                int kk = idx >> 5, nq = idx & 31;
                cpa16(sB + (s * 4352 + kk * 136 + nq * 4) * 4,
                      W + (long long)(k0 + kk) * 128 + nq * 4, true);
            }
        }
        CP_COMMIT();
    };

    issue(0); issue(1);
    for (int t = 0; t < 4; t++) {
        CP_WAIT1();
        __syncthreads();
        const unsigned* Ad = (const unsigned*)(As + (t % 3) * 4608);
        const unsigned* Bd = (const unsigned*)(Bs + (t % 3) * 4352);
#pragma unroll
        for (int ks = 0; ks < 32; ks += 8) {
            unsigned a[2][4], b[8][2];
#pragma unroll
            for (int mt = 0; mt < 2; mt++) {
                int r = mw + mt * 16 + gp;
                a[mt][0] = Ad[r * 36 + ks + tg];
                a[mt][1] = Ad[(r + 8) * 36 + ks + tg];
                a[mt][2] = Ad[r * 36 + ks + tg + 4];
                a[mt][3] = Ad[(r + 8) * 36 + ks + tg + 4];
            }
#pragma unroll
            for (int nt = 0; nt < 8; nt++) {
                int n = nw + nt * 8 + gp;
                b[nt][0] = Bd[(ks + tg) * 136 + n];
                b[nt][1] = Bd[(ks + tg + 4) * 136 + n];
            }
#pragma unroll
            for (int mt = 0; mt < 2; mt++)
#pragma unroll
                for (int nt = 0; nt < 8; nt++)
                    mma8(acc[mt][nt], a[mt], b[nt]);
        }
        issue(t + 2);
    }
#pragma unroll
    for (int mt = 0; mt < 2; mt++) {
        int row = rowBlk + mw + mt * 16 + gp;
#pragma unroll
        for (int nt = 0; nt < 8; nt++) {
            int col = nw + nt * 8 + tg * 2;
            float b0 = bias[col], b1 = bias[col + 1];
            float* cp = acc[mt][nt];
            if (row < M)     *(float2*)&C[(long long)row * 128 + col]       = make_float2(cp[0] + b0, cp[1] + b1);
            if (row + 8 < M) *(float2*)&C[(long long)(row + 8) * 128 + col] = make_float2(cp[2] + b0, cp[3] + b1);
        }
    }
}

// ---------------- FF-a GEMM: hid = relu(A(*mulp) @ W[128x2048] + bias) ----------------
#define FFA_AS 4608
#define FFA_BS 8448
#define FFA_SMEM_FLOATS (3 * (FFA_AS + FFA_BS))
__global__ void __launch_bounds__(256) ffa_gemm(
    const float* __restrict__ A, const float* __restrict__ W,
    const float* __restrict__ bias, const float* __restrict__ mulp,
    float* __restrict__ C)
{
    extern __shared__ float smf[];
    float* As = smf;
    float* Bs = smf + 3 * FFA_AS;
    const unsigned sA = (unsigned)__cvta_generic_to_shared(As);
    const unsigned sB = (unsigned)__cvta_generic_to_shared(Bs);
    const int tid = threadIdx.x;
    const int lane = tid & 31, w = tid >> 5;
    const int mw = (w >> 2) * 64, nw = (w & 3) * 64;
    const int rowBlk = blockIdx.x * 128, colBlk = blockIdx.y * 256;
    const int gp = lane >> 2, tg = lane & 3;

    float acc[4][8][4];
#pragma unroll
    for (int mt = 0; mt < 4; mt++)
#pragma unroll
        for (int nt = 0; nt < 8; nt++)
#pragma unroll
            for (int i = 0; i < 4; i++) acc[mt][nt][i] = 0.f;

    auto issue = [&](int t) {
        if (t < 4) {
            int s = t % 3, k0 = t * 32;
            if (mulp == nullptr) {
#pragma unroll
                for (int i = 0; i < 4; i++) {
                    int idx = tid + i * 256;
                    int r = idx >> 3, kq = idx & 7;
                    cpa16(sA + (s * FFA_AS + r * 36 + kq * 4) * 4,
                          A + (long long)(rowBlk + r) * 128 + k0 + kq * 4, true);
                }
            } else {
#pragma unroll
                for (int i = 0; i < 4; i++) {
                    int idx = tid + i * 256;
                    int r = idx >> 3, kq = idx & 7;
                    int row = rowBlk + r;
                    float4 av = *(const float4*)(A + (long long)row * 128 + k0 + kq * 4);
                    float4 mv = *(const float4*)(mulp + (row % 400) * 128 + k0 + kq * 4);
                    *(float4*)(As + s * FFA_AS + r * 36 + kq * 4) =
                        make_float4(av.x * mv.x, av.y * mv.y, av.z * mv.z, av.w * mv.w);
                }
            }
#pragma unroll
            for (int i = 0; i < 8; i++) {
                int idx = tid + i * 256;
                int kk = idx >> 6, nq = idx & 63;
                cpa16(sB + (s * FFA_BS + kk * 264 + nq * 4) * 4,
                      W + (long long)(k0 + kk) * 2048 + colBlk + nq * 4, true);
            }
        }
        CP_COMMIT();
    };

    issue(0); issue(1);
    for (int t = 0; t < 4; t++) {
        CP_WAIT1();
        __syncthreads();
        const unsigned* Ad = (const unsigned*)(As + (t % 3) * FFA_AS);
        const unsigned* Bd = (const unsigned*)(Bs + (t % 3) * FFA_BS);
#pragma unroll
        for (int ks = 0; ks < 32; ks += 8) {
            unsigned a[4][4], b[8][2];
#pragma unroll
            for (int mt = 0; mt < 4; mt++) {
                int r = mw + mt * 16 + gp;
                a[mt][0] = Ad[r * 36 + ks + tg];
                a[mt][1] = Ad[(r + 8) * 36 + ks + tg];
                a[mt][2] = Ad[r * 36 + ks + tg + 4];
                a[mt][3] = Ad[(r + 8) * 36 + ks + tg + 4];
            }
#pragma unroll
            for (int nt = 0; nt < 8; nt++) {
                int n = nw + nt * 8 + gp;
                b[nt][0] = Bd[(ks + tg) * 264 + n];
                b[nt][1] = Bd[(ks + tg + 4) * 264 + n];
            }
#pragma unroll
            for (int mt = 0; mt < 4; mt++)
#pragma unroll
                for (int nt = 0; nt < 8; nt++)
                    mma8(acc[mt][nt], a[mt], b[nt]);
        }
        issue(t + 2);
    }
#pragma unroll
    for (int mt = 0; mt < 4; mt++) {
        long long row = rowBlk + mw + mt * 16 + gp;
#pragma unroll
        for (int nt = 0; nt < 8; nt++) {
            int col = colBlk + nw + nt * 8 + tg * 2;
            float b0 = bias[col], b1 = bias[col + 1];
            float* cp = acc[mt][nt];
            *(float2*)&C[row * 2048 + col] =
                make_float2(fmaxf(cp[0] + b0, 0.f), fmaxf(cp[1] + b1, 0.f));
            *(float2*)&C[(row + 8) * 2048 + col] =
                make_float2(fmaxf(cp[2] + b0, 0.f), fmaxf(cp[3] + b1, 0.f));
        }
    }
}

// ---------------- FF-b GEMM: C = hid[38400x2048] @ W[2048x128] + bias ----------------
#define FFB_AS 9216
#define FFB_BS 4352
#define FFB_SMEM_FLOATS (3 * (FFB_AS + FFB_BS))
__global__ void __launch_bounds__(256) ffb_gemm(
    const float* __restrict__ A, const float* __restrict__ W,
    const float* __restrict__ bias, float* __restrict__ C)
{
    extern __shared__ float smf[];
    float* As = smf;
    float* Bs = smf + 3 * FFB_AS;
    const unsigned sA = (unsigned)__cvta_generic_to_shared(As);
    const unsigned sB = (unsigned)__cvta_generic_to_shared(Bs);
    const int tid = threadIdx.x;
    const int lane = tid & 31, w = tid >> 5;
    const int mw = (w >> 1) * 64, nw = (w & 1) * 64;
    const int rowBlk = blockIdx.x * 256;
    const int gp = lane >> 2, tg = lane & 3;

    float acc[4][8][4];
#pragma unroll
    for (int mt = 0; mt < 4; mt++)
#pragma unroll
        for (int nt = 0; nt < 8; nt++)
#pragma unroll
            for (int i = 0; i < 4; i++) acc[mt][nt][i] = 0.f;

    auto issue = [&](int t) {
        if (t < 64) {
            int s = t % 3, k0 = t * 32;
#pragma unroll
            for (int i = 0; i < 8; i++) {
                int idx = tid + i * 256;
                int r = idx >> 3, kq = idx & 7;
                cpa16(sA + (s * FFB_AS + r * 36 + kq * 4) * 4,
                      A + (long long)(rowBlk + r) * 2048 + k0 + kq * 4, true);
            }
#pragma unroll
            for (int i = 0; i < 4; i++) {
                int idx = tid + i * 256;
                int kk = idx >> 5, nq = idx & 31;
                cpa16(sB + (s * FFB_BS + kk * 136 + nq * 4) * 4,
                      W + (long long)(k0 + kk) * 128 + nq * 4, true);
            }
        }
        CP_COMMIT();
    };

    issue(0); issue(1);
    for (int t = 0; t < 64; t++) {
        CP_WAIT1();
        __syncthreads();
        const unsigned* Ad = (const unsigned*)(As + (t % 3) * FFB_AS);
        const unsigned* Bd = (const unsigned*)(Bs + (t % 3) * FFB_BS);
#pragma unroll
        for (int ks = 0; ks < 32; ks += 8) {
            unsigned a[4][4], b[8][2];
#pragma unroll
            for (int mt = 0; mt < 4; mt++) {
                int r = mw + mt * 16 + gp;
                a[mt][0] = Ad[r * 36 + ks + tg];
                a[mt][1] = Ad[(r + 8) * 36 + ks + tg];
                a[mt][2] = Ad[r * 36 + ks + tg + 4];
                a[mt][3] = Ad[(r + 8) * 36 + ks + tg + 4];
            }
#pragma unroll
            for (int nt = 0; nt < 8; nt++) {
                int n = nw + nt * 8 + gp;
                b[nt][0] = Bd[(ks + tg) * 136 + n];
                b[nt][1] = Bd[(ks + tg + 4) * 136 + n];
            }
#pragma unroll
            for (int mt = 0; mt < 4; mt++)
#pragma unroll
                for (int nt = 0; nt < 8; nt++)
                    mma8(acc[mt][nt], a[mt], b[nt]);
        }
        issue(t + 2);
    }
#pragma unroll
    for (int mt = 0; mt < 4; mt++) {
        long long row = rowBlk + mw + mt * 16 + gp;
#pragma unroll
        for (int nt = 0; nt < 8; nt++) {
            int col = nw + nt * 8 + tg * 2;
            float b0 = bias[col], b1 = bias[col + 1];
            float* cp = acc[mt][nt];
            *(float2*)&C[row * 128 + col]       = make_float2(cp[0] + b0, cp[1] + b1);
            *(float2*)&C[(row + 8) * 128 + col] = make_float2(cp[2] + b0, cp[3] + b1);
        }
    }
}

// ---------------- merged attention: blocks 0-767 full TC attn, 768-1535 pooled attn ----------------
#define ATT_KT 0
#define ATT_VT 6528
#define ATT_S  12992
#define ATT_QS 25920
#define ATT_PO 25920
#define ATT_LS 28096
#define ATT_TC_FLOATS 28128
__global__ void __launch_bounds__(256) attn_both_kernel(
    const float* __restrict__ q, const float* __restrict__ k, const float* __restrict__ v,
    float* __restrict__ o,
    const float* __restrict__ qa, const float* __restrict__ kp, const float* __restrict__ vp,
    const float* __restrict__ pos, float* __restrict__ oa)
{
    extern __shared__ float sm[];
    int tid = threadIdx.x, lane = tid & 31, w = tid >> 5;

    if (blockIdx.x < 768) {
        float* Kt = sm + ATT_KT;
        float* Vt = sm + ATT_VT;
        float* S  = sm + ATT_S;
        float* Qs = sm + ATT_QS;
        float* ls = sm + ATT_LS;
        float* Po = sm + ATT_PO;
        int bid = blockIdx.x, bt = bid >> 3, h = bid & 7;
        int gp = lane >> 2, tg = lane & 3;
        int base = bt * 400 * 128 + h * 16;

        for (int i = tid; i < 6400; i += 256) {
            int key = i >> 4, d = i & 15;
            Kt[d * 408 + key] = k[base + key * 128 + d];
            Vt[d * 404 + key] = v[base + key * 128 + d];
        }
        __syncthreads();

        const unsigned* Ku = (const unsigned*)Kt;
        const unsigned* Vu = (const unsigned*)Vt;
        const unsigned* Qu = (const unsigned*)Qs;
        const unsigned* Pu = (const unsigned*)S;

        for (int qt = 0; qt < 400; qt += 32) {
            for (int i = tid; i < 512; i += 256) {
                int r = i >> 4, d = i & 15;
                int qr = qt + r;
                Qs[r * 20 + d] = (qr < 400) ? q[base + qr * 128 + d] : 0.f;
            }
            __syncthreads();
            {
                unsigned af[2][2][4];
#pragma unroll
                for (int mt = 0; mt < 2; mt++)
#pragma unroll
                    for (int ksi = 0; ksi < 2; ksi++) {
                        int r = mt * 16 + gp, ks = ksi * 8;
                        af[mt][ksi][0] = Qu[r * 20 + ks + tg];
                        af[mt][ksi][1] = Qu[(r + 8) * 20 + ks + tg];
                        af[mt][ksi][2] = Qu[r * 20 + ks + tg + 4];
                        af[mt][ksi][3] = Qu[(r + 8) * 20 + ks + tg + 4];
                    }
                for (int nt = w; nt < 50; nt += 8) {
                    float c0[4] = {0.f, 0.f, 0.f, 0.f};
                    float c1[4] = {0.f, 0.f, 0.f, 0.f};
#pragma unroll
                    for (int ksi = 0; ksi < 2; ksi++) {
                        int ks = ksi * 8;
                        unsigned b[2];
                        b[0] = Ku[(ks + tg) * 408 + nt * 8 + gp];
                        b[1] = Ku[(ks + tg + 4) * 408 + nt * 8 + gp];
                        mma8(c0, af[0][ksi], b);
                        mma8(c1, af[1][ksi], b);
                    }
                    int cc = nt * 8 + tg * 2;
                    S[gp * 404 + cc]            = c0[0] * 0.25f;
                    S[gp * 404 + cc + 1]        = c0[1] * 0.25f;
                    S[(gp + 8) * 404 + cc]      = c0[2] * 0.25f;
                    S[(gp + 8) * 404 + cc + 1]  = c0[3] * 0.25f;
                    S[(gp + 16) * 404 + cc]     = c1[0] * 0.25f;
                    S[(gp + 16) * 404 + cc + 1] = c1[1] * 0.25f;
                    S[(gp + 24) * 404 + cc]     = c1[2] * 0.25f;
                    S[(gp + 24) * 404 + cc + 1] = c1[3] * 0.25f;
                }
            }
            __syncthreads();
            for (int rr = 0; rr < 4; rr++) {
                int row = w * 4 + rr;
                float sc[13];
                float m = -3.4e38f;
#pragma unroll
                for (int j = 0; j < 13; j++) {
                    int kk = lane + j * 32;
                    float s_ = (kk < 400) ? S[row * 404 + kk] : -3.4e38f;
                    sc[j] = s_; m = fmaxf(m, s_);
                }
#pragma unroll
                for (int off = 16; off; off >>= 1) m = fmaxf(m, __shfl_xor_sync(0xffffffffu, m, off));
                float l = 0.f;
#pragma unroll
                for (int j = 0; j < 13; j++) {
                    int kk = lane + j * 32;
                    if (kk < 400) {
                        float p_ = __expf(sc[j] - m);
                        S[row * 404 + kk] = p_;
                        l += p_;
                    }
                }
#pragma unroll
                for (int off = 16; off; off >>= 1) l += __shfl_xor_sync(0xffffffffu, l, off);
                if (lane == 0) ls[row] = 1.f / l;
            }
            __syncthreads();
            {
                int mt = w & 1, nt = (w >> 1) & 1, kh = w >> 2;
                float c[4] = {0.f, 0.f, 0.f, 0.f};
                int kbase = kh * 200;
                int gp2 = gp, tg2 = tg;
#pragma unroll 5
                for (int i = 0; i < 25; i++) {
                    int k0 = kbase + i * 8;
                    unsigned a[4], b[2];
                    a[0] = Pu[(mt * 16 + gp2) * 404 + k0 + tg2];
                    a[1] = Pu[(mt * 16 + gp2 + 8) * 404 + k0 + tg2];
                    a[2] = Pu[(mt * 16 + gp2) * 404 + k0 + tg2 + 4];
                    a[3] = Pu[(mt * 16 + gp2 + 8) * 404 + k0 + tg2 + 4];
                    b[0] = Vu[(nt * 8 + gp2) * 404 + k0 + tg2];
                    b[1] = Vu[(nt * 8 + gp2) * 404 + k0 + tg2 + 4];
                    mma8(c, a, b);
                }
                int r0 = mt * 16 + gp2, d0 = nt * 8 + tg2 * 2;
                if (kh == 1) {
                    Po[r0 * 68 + d0]           = c[0];
                    Po[r0 * 68 + d0 + 1]       = c[1];
                    Po[(r0 + 8) * 68 + d0]     = c[2];
                    Po[(r0 + 8) * 68 + d0 + 1] = c[3];
                }
                __syncthreads();
                if (kh == 0) {
                    float s0 = ls[r0], s1 = ls[r0 + 8];
                    int qr0 = qt + r0, qr1 = qt + r0 + 8;
                    if (qr0 < 400) {
                        o[base + qr0 * 128 + d0]     = (c[0] + Po[r0 * 68 + d0]) * s0;
                        o[base + qr0 * 128 + d0 + 1] = (c[1] + Po[r0 * 68 + d0 + 1]) * s0;
                    }
                    if (qr1 < 400) {
                        o[base + qr1 * 128 + d0]     = (c[2] + Po[(r0 + 8) * 68 + d0]) * s1;
                        o[base + qr1 * 128 + d0 + 1] = (c[3] + Po[(r0 + 8) * 68 + d0 + 1]) * s1;
                    }
                }
            }
            __syncthreads();
        }
    } else {
        // pooled attention: 64 keys + positional bias
        float* Ks = sm;                 // 16*65
        float* Vs = sm + 1040;          // 16*65
        float* pball = sm + 2080;       // 8*64
        int bid = blockIdx.x - 768;
        int bt = bid >> 3, h = bid & 7;
        int kbase = bt * 64 * 128 + h * 16;
        int qbase = bt * 400 * 128 + h * 16;
        for (int i = tid; i < 1024; i += 256) {
            int kk = i >> 4, d = i & 15;
            Ks[d * 65 + kk] = kp[kbase + kk * 128 + d];
            Vs[d * 65 + kk] = vp[kbase + kk * 128 + d];
        }
        __syncthreads();
        float* pb = pball + w * 64;
        for (int qi = w; qi < 400; qi += 8) {
            float qd[16];
#pragma unroll
            for (int d = 0; d < 16; d++) qd[d] = qa[qbase + qi * 128 + d];
            float sc[2];
            float m = -3.4e38f;
#pragma unroll
            for (int j = 0; j < 2; j++) {
                int kk = lane + 32 * j;
                float s = 0.f;
#pragma unroll
                for (int d = 0; d < 16; d++) s += qd[d] * Ks[d * 65 + kk];
                s = s * 0.25f + pos[qi * 64 + kk];
                sc[j] = s; m = fmaxf(m, s);
            }
#pragma unroll
            for (int off = 16; off; off >>= 1) m = fmaxf(m, __shfl_xor_sync(0xffffffffu, m, off));
            float lsum = 0.f;
#pragma unroll
            for (int j = 0; j < 2; j++) { float p = __expf(sc[j] - m); sc[j] = p; lsum += p; }
#pragma unroll
            for (int off = 16; off; off >>= 1) lsum += __shfl_xor_sync(0xffffffffu, lsum, off);
            pb[lane] = sc[0]; pb[lane + 32] = sc[1];
            __syncwarp();
            int d = lane & 15, half = lane >> 4;
            float acc = 0.f;
#pragma unroll
            for (int i = 0; i < 32; ++i) { int c = 2 * i + half; acc += pb[c] * Vs[d * 65 + c]; }
            acc += __shfl_xor_sync(0xffffffffu, acc, 16);
            if (lane < 16) oa[qbase + qi * 128 + d] = acc / lsum;
            __syncwarp();
        }
    }
}

// ---------------- warp-per-row LayerNorm: 4 rows/block, float4 lanes, shfl-only ----------------
__global__ void __launch_bounds__(128) ln4_kernel(
    const float* __restrict__ a, const float* __restrict__ b,
    const float* __restrict__ c, const float* __restrict__ d,
    const float* __restrict__ gamma, const float* __restrict__ beta,
    float* __restrict__ out, const float* __restrict__ addp)
{
    int lane = threadIdx.x & 31, wid = threadIdx.x >> 5;
    long long row = (long long)blockIdx.x * 4 + wid;
    long long base = row * 128 + lane * 4;
    float4 v = *(const float4*)(a + base);
    if (b) { float4 t = *(const float4*)(b + base); v.x += t.x; v.y += t.y; v.z += t.z; v.w += t.w; }
    if (c) { float4 t = *(const float4*)(c + base); v.x += t.x; v.y += t.y; v.z += t.z; v.w += t.w; }
    if (d) { float4 t = *(const float4*)(d + base); v.x += t.x; v.y += t.y; v.z += t.z; v.w += t.w; }
    float s = v.x + v.y + v.z + v.w;
    float ss = v.x * v.x + v.y * v.y + v.z * v.z + v.w * v.w;
#pragma unroll
    for (int off = 16; off; off >>= 1) {
        s  += __shfl_xor_sync(0xffffffffu, s,  off);
        ss += __shfl_xor_sync(0xffffffffu, ss, off);
    }
    float m = s * (1.f / 128.f);
    float var = ss * (1.f / 128.f) - m * m;
    float inv = rsqrtf(var + 1e-5f);
    float4 g  = *(const float4*)(gamma + lane * 4);
    float4 be = *(const float4*)(beta + lane * 4);
    float4 r;
    r.x = (v.x - m) * inv * g.x + be.x;
    r.y = (v.y - m) * inv * g.y + be.y;
    r.z = (v.z - m) * inv * g.z + be.z;
    r.w = (v.w - m) * inv * g.w + be.w;
    if (addp) {
        float4 t = *(const float4*)(addp + base);
        r.x += t.x; r.y += t.y; r.z += t.z; r.w += t.w;
    }
    *(float4*)(out + base) = r;
}

// ---------------- adaptive avg pool over node axis ----------------
__global__ void __launch_bounds__(128) pool_kernel(const float* __restrict__ x, float* __restrict__ xp)
{
    int bid = blockIdx.x;
    int bt = bid >> 6, c = bid & 63;
    int s = (c * 400) >> 6;
    int e = ((c + 1) * 400 + 63) >> 6;
    float sum = 0.f;
    for (int n = s; n < e; ++n) sum += x[(bt * 400 + n) * 128 + threadIdx.x];
    xp[bid * 128 + threadIdx.x] = sum / (float)(e - s);
}

// ---------------- warp-per-row GEANet (shfl-only, no smem) ----------------
// mode 0: node (permuted store); mode 1: edge (dual store).
// lane layout: u = lane&15, hh = lane>>4; lane holds h = hh*4 + j (j=0..3).
__global__ void __launch_bounds__(256) gea_warp(
    const float* __restrict__ in, const float* __restrict__ w, const float* __restrict__ bb,
    float* __restrict__ outp, float* __restrict__ outp2,
    int mode, int nrows, int rpw)
{
    int lane = threadIdx.x & 31, wid = threadIdx.x >> 5;
    int u = lane & 15, hh = lane >> 4;
    float w0c[16], w1c[16];
#pragma unroll
    for (int kk = 0; kk < 16; kk++) {
        w0c[kk] = w[kk * 16 + u];
        w1c[kk] = w[256 + kk * 16 + u];
    }
    float b0 = bb[u], b1 = bb[16 + u];
    int rowBase = (blockIdx.x * 8 + wid) * rpw;

    for (int rr = 0; rr < rpw; rr++) {
        int id = rowBase + rr;
        if (id >= nrows) return;
        float xr[4];
#pragma unroll
        for (int j = 0; j < 4; j++) {
            int h = hh * 4 + j;
            int dloc = (mode == 0) ? (h * 16 + u) : (u * 8 + h);
            xr[j] = in[(long long)id * 128 + dloc];
        }
        // GEMM1: a[h][u] = b0[u] + sum_k x[h][k] * w0[k][u]
        float a[4] = {b0, b0, b0, b0};
#pragma unroll
        for (int kk = 0; kk < 16; kk++) {
            int src = (hh << 4) | kk;
            float x0 = __shfl_sync(0xffffffffu, xr[0], src);
            float x1 = __shfl_sync(0xffffffffu, xr[1], src);
            float x2 = __shfl_sync(0xffffffffu, xr[2], src);
            float x3 = __shfl_sync(0xffffffffu, xr[3], src);
            a[0] += x0 * w0c[kk]; a[1] += x1 * w0c[kk];
            a[2] += x2 * w0c[kk]; a[3] += x3 * w0c[kk];
        }
        // softmax over h (8 values per u): partner lane is lane^16
        float mx = fmaxf(fmaxf(a[0], a[1]), fmaxf(a[2], a[3]));
        mx = fmaxf(mx, __shfl_xor_sync(0xffffffffu, mx, 16));
        float e0 = __expf(a[0] - mx), e1 = __expf(a[1] - mx);
        float e2 = __expf(a[2] - mx), e3 = __expf(a[3] - mx);
        float den = e0 + e1 + e2 + e3;
        den += __shfl_xor_sync(0xffffffffu, den, 16);
        float vv[4] = {e0 / den, e1 / den, e2 / den, e3 / den};
        // row-sum over u for each h: butterfly over bits 0..3 (stays within half)
        float rs[4] = {vv[0], vv[1], vv[2], vv[3]};
#pragma unroll
        for (int msk = 1; msk < 16; msk <<= 1) {
            rs[0] += __shfl_xor_sync(0xffffffffu, rs[0], msk);
            rs[1] += __shfl_xor_sync(0xffffffffu, rs[1], msk);
            rs[2] += __shfl_xor_sync(0xffffffffu, rs[2], msk);
            rs[3] += __shfl_xor_sync(0xffffffffu, rs[3], msk);
        }
        float dn[4] = {vv[0] / rs[0], vv[1] / rs[1], vv[2] / rs[2], vv[3] / rs[3]};
        // GEMM2: o[h][u] = b1[u] + sum_k dn[h][k] * w1[k][u]
        float o4[4] = {b1, b1, b1, b1};
#pragma unroll
        for (int kk = 0; kk < 16; kk++) {
            int src = (hh << 4) | kk;
            float x0 = __shfl_sync(0xffffffffu, dn[0], src);
            float x1 = __shfl_sync(0xffffffffu, dn[1], src);
            float x2 = __shfl_sync(0xffffffffu, dn[2], src);
            float x3 = __shfl_sync(0xffffffffu, dn[3], src);
            o4[0] += x0 * w1c[kk]; o4[1] += x1 * w1c[kk];
            o4[2] += x2 * w1c[kk]; o4[3] += x3 * w1c[kk];
        }
        if (mode == 0) {
            int bI = id / 4800, r2 = id % 4800, t = r2 / 400, n = r2 % 400;
            long long ob = ((long long)(bI * 400 + n) * 12 + t) * 128;
#pragma unroll
            for (int j = 0; j < 4; j++) outp[ob + (hh * 4 + j) * 16 + u] = o4[j];
        } else {
            long long ob = (long long)id * 128;
#pragma unroll
            for (int j = 0; j < 4; j++) {
                int dloc = (hh * 4 + j) * 16 + u;
                outp[ob + dloc] = o4[j];
                if (outp2) outp2[ob + dloc] = o4[j];
            }
        }
    }
}

// ---------------- host ----------------
static float* sym(const void* s) { void* p = nullptr; cudaGetSymbolAddress(&p, s); return (float*)p; }

extern "C" void kernel_launch(void* const* d_in, const int* in_sizes, int n_in,
                              void* d_out, int out_size)
{
    const float* x      = (const float*)d_in[0];
    const float* semb   = (const float*)d_in[1];
    const float* dqkv_w = (const float*)d_in[2];
    const float* dqkv_b = (const float*)d_in[3];
    const float* dout_w = (const float*)d_in[4];
    const float* dout_b = (const float*)d_in[5];
    const float* aqkv_w = (const float*)d_in[6];
    const float* aqkv_b = (const float*)d_in[7];
    const float* aout_w = (const float*)d_in[8];
    const float* aout_b = (const float*)d_in[9];
    const float* adp_pos= (const float*)d_in[10];
    const float* gsh_w  = (const float*)d_in[11];
    const float* gsh_b  = (const float*)d_in[12];
    const float* gnode_w= (const float*)d_in[13];
    const float* gnode_b= (const float*)d_in[14];
    const float* gedge_w= (const float*)d_in[15];
    const float* gedge_b= (const float*)d_in[16];
    const float* sp_w   = (const float*)d_in[17];
    const float* sp_b   = (const float*)d_in[18];
    const float* f1w1   = (const float*)d_in[19];
    const float* f1b1   = (const float*)d_in[20];
    const float* f1w2   = (const float*)d_in[21];
    const float* f1b2   = (const float*)d_in[22];
    const float* f2w1   = (const float*)d_in[23];
    const float* f2b1   = (const float*)d_in[24];
    const float* f2w2   = (const float*)d_in[25];
    const float* f2b2   = (const float*)d_in[26];
    const float* lns    = (const float*)d_in[27];
    const float* lnb    = (const float*)d_in[28];
    float* out = (float*)d_out;

    float *q = sym(g_q), *k = sym(g_k), *v = sym(g_v), *o = sym(g_o);
    float *dtw = sym(g_dtw), *ex = sym(g_ex), *res = sym(g_res), *tmp = sym(g_tmp);
    float *hid = sym(g_hid);
    float *xp = sym(g_xp), *kp = sym(g_kp), *vp = sym(g_vp);
    float *sen = sym(g_sen), *edge = sym(g_edge), *senx = sym(g_senx);

    const int GEMM_SMEM = 3 * (4608 + 4352) * 4;   // 107520 B
    const int ATT_SMEM  = ATT_TC_FLOATS * 4;       // 112512 B -> 2 blocks/SM
    const int FFA_SMEM  = FFA_SMEM_FLOATS * 4;     // 156672 B
    const int FFB_SMEM  = FFB_SMEM_FLOATS * 4;     // 162816 B
    cudaFuncSetAttribute(mma_gemm,   cudaFuncAttributeMaxDynamicSharedMemorySize, GEMM_SMEM);
    cudaFuncSetAttribute(mma_gemm_b, cudaFuncAttributeMaxDynamicSharedMemorySize, GEMM_SMEM);
    cudaFuncSetAttribute(attn_both_kernel, cudaFuncAttributeMaxDynamicSharedMemorySize, ATT_SMEM);
    cudaFuncSetAttribute(ffa_gemm, cudaFuncAttributeMaxDynamicSharedMemorySize, FFA_SMEM);
    cudaFuncSetAttribute(ffb_gemm, cudaFuncAttributeMaxDynamicSharedMemorySize, FFB_SMEM);

    // batch 1: five projections reading x -> dq, dk, dv, aq(in tmp), gshare(in res)
    GSet b1;
    b1.A[0] = x; b1.W[0] = dqkv_w;          b1.Bv[0] = dqkv_b;        b1.C[0] = q;
    b1.A[1] = x; b1.W[1] = dqkv_w + 16384;  b1.Bv[1] = dqkv_b + 128;  b1.C[1] = k;
    b1.A[2] = x; b1.W[2] = dqkv_w + 32768;  b1.Bv[2] = dqkv_b + 256;  b1.C[2] = v;
    b1.A[3] = x; b1.W[3] = aqkv_w;          b1.Bv[3] = aqkv_b;        b1.C[3] = tmp;
    b1.A[4] = x; b1.W[4] = gsh_w;           b1.Bv[4] = gsh_b;         b1.C[4] = res;
    mma_gemm_b<<<dim3(300, 5), 256, GEMM_SMEM>>>(b1, ROWS);

    pool_kernel<<<6144, 128>>>(x, xp);

    // batch 2: pooled K/V
    GSet b2;
    b2.A[0] = xp; b2.W[0] = aqkv_w + 16384; b2.Bv[0] = aqkv_b + 128; b2.C[0] = kp;
    b2.A[1] = xp; b2.W[1] = aqkv_w + 32768; b2.Bv[1] = aqkv_b + 256; b2.C[1] = vp;
    b2.A[2] = xp; b2.W[2] = b2.W[0];        b2.Bv[2] = b2.Bv[0];     b2.C[2] = kp;
    b2.A[3] = xp; b2.W[3] = b2.W[0];        b2.Bv[3] = b2.Bv[0];     b2.C[3] = kp;
    b2.A[4] = xp; b2.W[4] = b2.W[0];        b2.Bv[4] = b2.Bv[0];     b2.C[4] = kp;
    mma_gemm_b<<<dim3(48, 2), 256, GEMM_SMEM>>>(b2, 6144);

    // GEANet node (consumes gshare in res) — independent of attention
    gea_warp<<<960, 256>>>(res, gnode_w, gnode_b, ex, nullptr, 0, ROWS, 5);

    // merged attentions: blocks 0-767 full TC, 768-1535 pooled (out -> hid temp)
    attn_both_kernel<<<1536, 256, ATT_SMEM>>>(q, k, v, o, tmp, kp, vp, adp_pos, hid);

    // batch 3: output projections (dtw-out, adp-out)
    GSet b3;
    b3.A[0] = o;   b3.W[0] = dout_w; b3.Bv[0] = dout_b; b3.C[0] = dtw;
    b3.A[1] = hid; b3.W[1] = aout_w; b3.Bv[1] = aout_b; b3.C[1] = k;    // oa -> k
    b3.A[2] = o;   b3.W[2] = b3.W[0]; b3.Bv[2] = b3.Bv[0]; b3.C[2] = dtw;
    b3.A[3] = o;   b3.W[3] = b3.W[0]; b3.Bv[3] = b3.Bv[0]; b3.C[3] = dtw;
    b3.A[4] = o;   b3.W[4] = b3.W[0]; b3.Bv[4] = b3.Bv[0]; b3.C[4] = dtw;
    mma_gemm_b<<<dim3(300, 2), 256, GEMM_SMEM>>>(b3, ROWS);

    // sen + GEANet edge (edge dual-writes senx and the output tail)
    mma_gemm<<<4, 256, GEMM_SMEM>>>(semb, sp_w, sp_b, sen, 400);
    ln4_kernel<<<100, 128>>>(sen, nullptr, nullptr, nullptr, lns + 3 * 128, lnb + 3 * 128, sen, nullptr);
    mma_gemm<<<4, 256, GEMM_SMEM>>>(sen, gsh_w, gsh_b, edge, 400);
    gea_warp<<<50, 256>>>(edge, gedge_w, gedge_b, senx,
                          (out_size >= BIG + 51200) ? (out + BIG) : nullptr, 1, 400, 1);

    // out = LN(x + dtw + oa + extra)
    ln4_kernel<<<9600, 128>>>(x, dtw, k, ex, lns, lnb, res, nullptr);

    // out_attn = LN(FF1(out) + out)
    ffa_gemm<<<dim3(300, 8), 256, FFA_SMEM>>>(res, f1w1, f1b1, nullptr, hid);
    ffb_gemm<<<150, 256, FFB_SMEM>>>(hid, f1w2, f1b2, tmp);
    ln4_kernel<<<9600, 128>>>(tmp, res, nullptr, nullptr, lns + 128, lnb + 128, dtw, nullptr); // out_attn -> dtw

    // sp = LN(FF2(out_attn * sen_extra)); final out = out_attn + sp fused into LN
    ffa_gemm<<<dim3(300, 8), 256, FFA_SMEM>>>(dtw, f2w1, f2b1, senx, hid);
    ffb_gemm<<<150, 256, FFB_SMEM>>>(hid, f2w2, f2b2, tmp);
    ln4_kernel<<<9600, 128>>>(tmp, nullptr, nullptr, nullptr, lns + 256, lnb + 256, out, dtw);
}

// round 15
// speedup vs baseline: 6.0187x; 1.0619x over previous
#include <cuda_runtime.h>

#define ROWS 38400
#define BIG  4915200

// ---------------- device scratch ----------------
__device__ float g_q[BIG];
__device__ float g_k[BIG];
__device__ float g_v[BIG];
__device__ float g_o[BIG];
__device__ float g_oa[BIG];
__device__ float g_dtw[BIG];
__device__ float g_ex[BIG];
__device__ float g_res[BIG];
__device__ float g_tmp[BIG];
__device__ float g_xp[786432];
__device__ float g_kp[786432];
__device__ float g_vp[786432];
__device__ float g_sen[51200];
__device__ float g_edge[51200];
__device__ float g_senx[51200];

// ---------------- mma / cp.async helpers ----------------
__device__ __forceinline__ void mma8(float* c, const unsigned* a, const unsigned* b) {
    asm volatile(
        "mma.sync.aligned.m16n8k8.row.col.f32.tf32.tf32.f32 "
        "{%0,%1,%2,%3}, {%4,%5,%6,%7}, {%8,%9}, {%0,%1,%2,%3};"
        : "+f"(c[0]), "+f"(c[1]), "+f"(c[2]), "+f"(c[3])
        : "r"(a[0]), "r"(a[1]), "r"(a[2]), "r"(a[3]), "r"(b[0]), "r"(b[1]));
}
__device__ __forceinline__ void cpa16(unsigned dst, const float* src, bool p) {
    int sz = p ? 16 : 0;
    asm volatile("cp.async.cg.shared.global [%0], [%1], 16, %2;"
                 :: "r"(dst), "l"(src), "r"(sz));
}
#define CP_COMMIT() asm volatile("cp.async.commit_group;")
#define CP_WAIT1()  asm volatile("cp.async.wait_group 1;")
#define CP_WAIT0()  asm volatile("cp.async.wait_group 0;")

// ---------------- batched tf32 GEMM (N=K=128) ----------------
struct GSet {
    const float* A[5];
    const float* W[5];
    const float* Bv[5];
    float*       C[5];
};
__global__ void __launch_bounds__(256) mma_gemm_b(GSet g, int M)
{
    extern __shared__ float smf[];
    float* As = smf;
    float* Bs = smf + 3 * 4608;
    const unsigned sA = (unsigned)__cvta_generic_to_shared(As);
    const unsigned sB = (unsigned)__cvta_generic_to_shared(Bs);
    const int y = blockIdx.y;
    const float* __restrict__ A = g.A[y];
    const float* __restrict__ W = g.W[y];
    const float* __restrict__ bias = g.Bv[y];
    float* __restrict__ C = g.C[y];
    const int tid = threadIdx.x;
    const int lane = tid & 31, w = tid >> 5;
    const int mw = (w >> 1) * 32, nw = (w & 1) * 64;
    const int rowBlk = blockIdx.x * 128;
    const int gp = lane >> 2, tg = lane & 3;

    float acc[2][8][4];
#pragma unroll
    for (int mt = 0; mt < 2; mt++)
#pragma unroll
        for (int nt = 0; nt < 8; nt++)
#pragma unroll
            for (int i = 0; i < 4; i++) acc[mt][nt][i] = 0.f;

    auto issue = [&](int t) {
        if (t < 4) {
            int s = t % 3, k0 = t * 32;
#pragma unroll
            for (int i = 0; i < 4; i++) {
                int idx = tid + i * 256;
                int r = idx >> 3, kq = idx & 7;
                int row = rowBlk + r;
                bool p = row < M;
                int rc = p ? row : (M - 1);
                cpa16(sA + (s * 4608 + r * 36 + kq * 4) * 4,
                      A + (long long)rc * 128 + k0 + kq * 4, p);
            }
#pragma unroll
            for (int i = 0; i < 4; i++) {
                int idx = tid + i * 256;
                int kk = idx >> 5, nq = idx & 31;
                cpa16(sB + (s * 4352 + kk * 136 + nq * 4) * 4,
                      W + (long long)(k0 + kk) * 128 + nq * 4, true);
            }
        }
        CP_COMMIT();
    };

    issue(0); issue(1);
    for (int t = 0; t < 4; t++) {
        CP_WAIT1();
        __syncthreads();
        const unsigned* Ad = (const unsigned*)(As + (t % 3) * 4608);
        const unsigned* Bd = (const unsigned*)(Bs + (t % 3) * 4352);
#pragma unroll
        for (int ks = 0; ks < 32; ks += 8) {
            unsigned a[2][4], b[8][2];
#pragma unroll
            for (int mt = 0; mt < 2; mt++) {
                int r = mw + mt * 16 + gp;
                a[mt][0] = Ad[r * 36 + ks + tg];
                a[mt][1] = Ad[(r + 8) * 36 + ks + tg];
                a[mt][2] = Ad[r * 36 + ks + tg + 4];
                a[mt][3] = Ad[(r + 8) * 36 + ks + tg + 4];
            }
#pragma unroll
            for (int nt = 0; nt < 8; nt++) {
                int n = nw + nt * 8 + gp;
                b[nt][0] = Bd[(ks + tg) * 136 + n];
                b[nt][1] = Bd[(ks + tg + 4) * 136 + n];
            }
#pragma unroll
            for (int mt = 0; mt < 2; mt++)
#pragma unroll
                for (int nt = 0; nt < 8; nt++)
                    mma8(acc[mt][nt], a[mt], b[nt]);
        }
        issue(t + 2);
    }
#pragma unroll
    for (int mt = 0; mt < 2; mt++) {
        int row = rowBlk + mw + mt * 16 + gp;
#pragma unroll
        for (int nt = 0; nt < 8; nt++) {
            int col = nw + nt * 8 + tg * 2;
            float b0 = bias[col], b1 = bias[col + 1];
            float* cp = acc[mt][nt];
            if (row < M)     *(float2*)&C[(long long)row * 128 + col]       = make_float2(cp[0] + b0, cp[1] + b1);
            if (row + 8 < M) *(float2*)&C[(long long)(row + 8) * 128 + col] = make_float2(cp[2] + b0, cp[3] + b1);
        }
    }
}

// ---------------- generic small GEMM (sen chain) ----------------
__global__ void __launch_bounds__(256) mma_gemm(
    const float* __restrict__ A, const float* __restrict__ W,
    const float* __restrict__ bias, float* __restrict__ C, int M)
{
    extern __shared__ float smf[];
    float* As = smf;
    float* Bs = smf + 3 * 4608;
    const unsigned sA = (unsigned)__cvta_generic_to_shared(As);
    const unsigned sB = (unsigned)__cvta_generic_to_shared(Bs);
    const int tid = threadIdx.x;
    const int lane = tid & 31, w = tid >> 5;
    const int mw = (w >> 1) * 32, nw = (w & 1) * 64;
    const int rowBlk = blockIdx.x * 128;
    const int gp = lane >> 2, tg = lane & 3;

    float acc[2][8][4];
#pragma unroll
    for (int mt = 0; mt < 2; mt++)
#pragma unroll
        for (int nt = 0; nt < 8; nt++)
#pragma unroll
            for (int i = 0; i < 4; i++) acc[mt][nt][i] = 0.f;

    auto issue = [&](int t) {
        if (t < 4) {
            int s = t % 3, k0 = t * 32;
#pragma unroll
            for (int i = 0; i < 4; i++) {
                int idx = tid + i * 256;
                int r = idx >> 3, kq = idx & 7;
                int row = rowBlk + r;
                bool p = row < M;
                int rc = p ? row : (M - 1);
                cpa16(sA + (s * 4608 + r * 36 + kq * 4) * 4,
                      A + (long long)rc * 128 + k0 + kq * 4, p);
            }
#pragma unroll
            for (int i = 0; i < 4; i++) {
                int idx = tid + i * 256;
                int kk = idx >> 5, nq = idx & 31;
                cpa16(sB + (s * 4352 + kk * 136 + nq * 4) * 4,
                      W + (long long)(k0 + kk) * 128 + nq * 4, true);
            }
        }
        CP_COMMIT();
    };

    issue(0); issue(1);
    for (int t = 0; t < 4; t++) {
        CP_WAIT1();
        __syncthreads();
        const unsigned* Ad = (const unsigned*)(As + (t % 3) * 4608);
        const unsigned* Bd = (const unsigned*)(Bs + (t % 3) * 4352);
#pragma unroll
        for (int ks = 0; ks < 32; ks += 8) {
            unsigned a[2][4], b[8][2];
#pragma unroll
            for (int mt = 0; mt < 2; mt++) {
                int r = mw + mt * 16 + gp;
                a[mt][0] = Ad[r * 36 + ks + tg];
                a[mt][1] = Ad[(r + 8) * 36 + ks + tg];
                a[mt][2] = Ad[r * 36 + ks + tg + 4];
                a[mt][3] = Ad[(r + 8) * 36 + ks + tg + 4];
            }
#pragma unroll
            for (int nt = 0; nt < 8; nt++) {
                int n = nw + nt * 8 + gp;
                b[nt][0] = Bd[(ks + tg) * 136 + n];
                b[nt][1] = Bd[(ks + tg + 4) * 136 + n];
            }
#pragma unroll
            for (int mt = 0; mt < 2; mt++)
#pragma unroll
                for (int nt = 0; nt < 8; nt++)
                    mma8(acc[mt][nt], a[mt], b[nt]);
        }
        issue(t + 2);
    }
#pragma unroll
    for (int mt = 0; mt < 2; mt++) {
        int row = rowBlk + mw + mt * 16 + gp;
#pragma unroll
        for (int nt = 0; nt < 8; nt++) {
            int col = nw + nt * 8 + tg * 2;
            float b0 = bias[col], b1 = bias[col + 1];
            float* cp = acc[mt][nt];
            if (row < M)     *(float2*)&C[(long long)row * 128 + col]       = make_float2(cp[0] + b0, cp[1] + b1);
            if (row + 8 < M) *(float2*)&C[(long long)(row + 8) * 128 + col] = make_float2(cp[2] + b0, cp[3] + b1);
        }
    }
}

// ---------------- fused FF: C = relu(A(*mulp) @ W1 + b1) @ W2 + b2, hidden in SMEM ----------------
// 128 rows/block; 32 chunks of 64 hidden cols. SMEM floats:
// A[128*132]=16896 | W1[128*72]=9216 | H[128*68]=8704 | W2 2x[64*136]=17408  -> 52224 (204.0 KB)
#define FFF_A  0
#define FFF_W1 16896
#define FFF_H  26112
#define FFF_W2 34816
#define FFF_FLOATS 52224
__global__ void __launch_bounds__(256) ff_fused(
    const float* __restrict__ A, const float* __restrict__ W1,
    const float* __restrict__ b1v, const float* __restrict__ W2,
    const float* __restrict__ b2v, const float* __restrict__ mulp,
    float* __restrict__ C)
{
    extern __shared__ float smf[];
    float* As  = smf + FFF_A;
    float* W1s = smf + FFF_W1;
    float* Hs  = smf + FFF_H;
    float* W2s = smf + FFF_W2;
    const unsigned sW1 = (unsigned)__cvta_generic_to_shared(W1s);
    const unsigned sW2 = (unsigned)__cvta_generic_to_shared(W2s);
    const int tid = threadIdx.x;
    const int lane = tid & 31, w = tid >> 5;
    const int gp = lane >> 2, tg = lane & 3;
    const int mw1 = (w >> 1) * 32, nw1 = (w & 1) * 32;   // GEMM1 warp tile 32x32 (of 128x64)
    const int mw2 = (w >> 1) * 32, nw2 = (w & 1) * 64;   // GEMM2 warp tile 32x64 (of 128x128)
    const long long rowBlk = (long long)blockIdx.x * 128;

    // stage A once (optional elementwise mul)
    for (int i = tid; i < 4096; i += 256) {
        int r = i >> 5, kq = i & 31;
        long long row = rowBlk + r;
        float4 av = *(const float4*)(A + row * 128 + kq * 4);
        if (mulp) {
            float4 mv = *(const float4*)(mulp + (row % 400) * 128 + kq * 4);
            av.x *= mv.x; av.y *= mv.y; av.z *= mv.z; av.w *= mv.w;
        }
        *(float4*)(As + r * 132 + kq * 4) = av;
    }

    auto loadW1 = [&](int c) {
#pragma unroll
        for (int i = 0; i < 8; i++) {
            int idx = tid + i * 256;
            int kk = idx >> 4, nq = idx & 15;
            cpa16(sW1 + (kk * 72 + nq * 4) * 4,
                  W1 + (long long)kk * 2048 + c * 64 + nq * 4, true);
        }
    };
    auto loadW2 = [&](int c, int buf) {
#pragma unroll
        for (int i = 0; i < 8; i++) {
            int idx = tid + i * 256;
            int kk = idx >> 5, nq = idx & 31;
            cpa16(sW2 + (buf * 8704 + kk * 136 + nq * 4) * 4,
                  W2 + (long long)(c * 64 + kk) * 128 + nq * 4, true);
        }
    };

    loadW1(0); loadW2(0, 0);
    CP_COMMIT();

    float acc[2][8][4];
#pragma unroll
    for (int mt = 0; mt < 2; mt++)
#pragma unroll
        for (int nt = 0; nt < 8; nt++)
#pragma unroll
            for (int i = 0; i < 4; i++) acc[mt][nt][i] = 0.f;

    CP_WAIT0();
    __syncthreads();

    const unsigned* Au = (const unsigned*)As;
    const unsigned* Hu = (const unsigned*)Hs;

    for (int c = 0; c < 32; c++) {
        // GEMM1: acc1 = A[128x128] @ W1chunk[128x64]
        float acc1[2][4][4];
#pragma unroll
        for (int mt = 0; mt < 2; mt++)
#pragma unroll
            for (int nt = 0; nt < 4; nt++)
#pragma unroll
                for (int i = 0; i < 4; i++) acc1[mt][nt][i] = 0.f;
        const unsigned* W1u = (const unsigned*)W1s;
#pragma unroll
        for (int ks = 0; ks < 128; ks += 8) {
            unsigned a[2][4], b[4][2];
#pragma unroll
            for (int mt = 0; mt < 2; mt++) {
                int r = mw1 + mt * 16 + gp;
                a[mt][0] = Au[r * 132 + ks + tg];
                a[mt][1] = Au[(r + 8) * 132 + ks + tg];
                a[mt][2] = Au[r * 132 + ks + tg + 4];
                a[mt][3] = Au[(r + 8) * 132 + ks + tg + 4];
            }
#pragma unroll
            for (int nt = 0; nt < 4; nt++) {
                int n = nw1 + nt * 8 + gp;
                b[nt][0] = W1u[(ks + tg) * 72 + n];
                b[nt][1] = W1u[(ks + tg + 4) * 72 + n];
            }
#pragma unroll
            for (int mt = 0; mt < 2; mt++)
#pragma unroll
                for (int nt = 0; nt < 4; nt++)
                    mma8(acc1[mt][nt], a[mt], b[nt]);
        }
        __syncthreads();   // S0: previous GEMM2 readers of H done
        // store H = relu(acc1 + b1)
#pragma unroll
        for (int mt = 0; mt < 2; mt++) {
            int r = mw1 + mt * 16 + gp;
#pragma unroll
            for (int nt = 0; nt < 4; nt++) {
                int col = nw1 + nt * 8 + tg * 2;
                float g0 = b1v[c * 64 + col], g1 = b1v[c * 64 + col + 1];
                float* cp = acc1[mt][nt];
                *(float2*)&Hs[r * 68 + col] =
                    make_float2(fmaxf(cp[0] + g0, 0.f), fmaxf(cp[1] + g1, 0.f));
                *(float2*)&Hs[(r + 8) * 68 + col] =
                    make_float2(fmaxf(cp[2] + g0, 0.f), fmaxf(cp[3] + g1, 0.f));
            }
        }
        __syncthreads();   // S1: H visible; W1 consumed
        if (c + 1 < 32) { loadW1(c + 1); loadW2(c + 1, (c + 1) & 1); }
        CP_COMMIT();
        // GEMM2: acc += H[128x64] @ W2chunk[64x128]
        const unsigned* W2u = (const unsigned*)(W2s + (c & 1) * 8704);
#pragma unroll
        for (int ks = 0; ks < 64; ks += 8) {
            unsigned a[2][4], b[8][2];
#pragma unroll
            for (int mt = 0; mt < 2; mt++) {
                int r = mw2 + mt * 16 + gp;
                a[mt][0] = Hu[r * 68 + ks + tg];
                a[mt][1] = Hu[(r + 8) * 68 + ks + tg];
                a[mt][2] = Hu[r * 68 + ks + tg + 4];
                a[mt][3] = Hu[(r + 8) * 68 + ks + tg + 4];
            }
#pragma unroll
            for (int nt = 0; nt < 8; nt++) {
                int n = nw2 + nt * 8 + gp;
                b[nt][0] = W2u[(ks + tg) * 136 + n];
                b[nt][1] = W2u[(ks + tg + 4) * 136 + n];
            }
#pragma unroll
            for (int mt = 0; mt < 2; mt++)
#pragma unroll
                for (int nt = 0; nt < 8; nt++)
                    mma8(acc[mt][nt], a[mt], b[nt]);
        }
        CP_WAIT0();
        __syncthreads();   // S2: prefetched W visible to all
    }
#pragma unroll
    for (int mt = 0; mt < 2; mt++) {
        long long row = rowBlk + mw2 + mt * 16 + gp;
#pragma unroll
        for (int nt = 0; nt < 8; nt++) {
            int col = nw2 + nt * 8 + tg * 2;
            float b0 = b2v[col], b1 = b2v[col + 1];
            float* cp = acc[mt][nt];
            *(float2*)&C[row * 128 + col]       = make_float2(cp[0] + b0, cp[1] + b1);
            *(float2*)&C[(row + 8) * 128 + col] = make_float2(cp[2] + b0, cp[3] + b1);
        }
    }
}

// ---------------- merged: full TC attn (0-767) | pooled attn (768-1535) | gea node (1536-2495) ----------------
#define ATT_KT 0
#define ATT_VT 6528
#define ATT_S  12992
#define ATT_QS 25920
#define ATT_PO 25920
#define ATT_LS 28096
#define ATT_TC_FLOATS 28128
__global__ void __launch_bounds__(256) attn_both_kernel(
    const float* __restrict__ q, const float* __restrict__ k, const float* __restrict__ v,
    float* __restrict__ o,
    const float* __restrict__ qa, const float* __restrict__ kp, const float* __restrict__ vp,
    const float* __restrict__ pos, float* __restrict__ oa,
    const float* __restrict__ gin, const float* __restrict__ gw, const float* __restrict__ gb,
    float* __restrict__ gout)
{
    extern __shared__ float sm[];
    int tid = threadIdx.x, lane = tid & 31, w = tid >> 5;

    if (blockIdx.x < 768) {
        float* Kt = sm + ATT_KT;
        float* Vt = sm + ATT_VT;
        float* S  = sm + ATT_S;
        float* Qs = sm + ATT_QS;
        float* ls = sm + ATT_LS;
        float* Po = sm + ATT_PO;
        int bid = blockIdx.x, bt = bid >> 3, h = bid & 7;
        int gp = lane >> 2, tg = lane & 3;
        int base = bt * 400 * 128 + h * 16;

        for (int i = tid; i < 6400; i += 256) {
            int key = i >> 4, d = i & 15;
            Kt[d * 408 + key] = k[base + key * 128 + d];
            Vt[d * 404 + key] = v[base + key * 128 + d];
        }
        __syncthreads();

        const unsigned* Ku = (const unsigned*)Kt;
        const unsigned* Vu = (const unsigned*)Vt;
        const unsigned* Qu = (const unsigned*)Qs;
        const unsigned* Pu = (const unsigned*)S;

        for (int qt = 0; qt < 400; qt += 32) {
            for (int i = tid; i < 512; i += 256) {
                int r = i >> 4, d = i & 15;
                int qr = qt + r;
                Qs[r * 20 + d] = (qr < 400) ? q[base + qr * 128 + d] : 0.f;
            }
            __syncthreads();
            {
                unsigned af[2][2][4];
#pragma unroll
                for (int mt = 0; mt < 2; mt++)
#pragma unroll
                    for (int ksi = 0; ksi < 2; ksi++) {
                        int r = mt * 16 + gp, ks = ksi * 8;
                        af[mt][ksi][0] = Qu[r * 20 + ks + tg];
                        af[mt][ksi][1] = Qu[(r + 8) * 20 + ks + tg];
                        af[mt][ksi][2] = Qu[r * 20 + ks + tg + 4];
                        af[mt][ksi][3] = Qu[(r + 8) * 20 + ks + tg + 4];
                    }
                for (int nt = w; nt < 50; nt += 8) {
                    float c0[4] = {0.f, 0.f, 0.f, 0.f};
                    float c1[4] = {0.f, 0.f, 0.f, 0.f};
#pragma unroll
                    for (int ksi = 0; ksi < 2; ksi++) {
                        int ks = ksi * 8;
                        unsigned b[2];
                        b[0] = Ku[(ks + tg) * 408 + nt * 8 + gp];
                        b[1] = Ku[(ks + tg + 4) * 408 + nt * 8 + gp];
                        mma8(c0, af[0][ksi], b);
                        mma8(c1, af[1][ksi], b);
                    }
                    int cc = nt * 8 + tg * 2;
                    S[gp * 404 + cc]            = c0[0] * 0.25f;
                    S[gp * 404 + cc + 1]        = c0[1] * 0.25f;
                    S[(gp + 8) * 404 + cc]      = c0[2] * 0.25f;
                    S[(gp + 8) * 404 + cc + 1]  = c0[3] * 0.25f;
                    S[(gp + 16) * 404 + cc]     = c1[0] * 0.25f;
                    S[(gp + 16) * 404 + cc + 1] = c1[1] * 0.25f;
                    S[(gp + 24) * 404 + cc]     = c1[2] * 0.25f;
                    S[(gp + 24) * 404 + cc + 1] = c1[3] * 0.25f;
                }
            }
            __syncthreads();
            for (int rr = 0; rr < 4; rr++) {
                int row = w * 4 + rr;
                float sc[13];
                float m = -3.4e38f;
#pragma unroll
                for (int j = 0; j < 13; j++) {
                    int kk = lane + j * 32;
                    float s_ = (kk < 400) ? S[row * 404 + kk] : -3.4e38f;
                    sc[j] = s_; m = fmaxf(m, s_);
                }
#pragma unroll
                for (int off = 16; off; off >>= 1) m = fmaxf(m, __shfl_xor_sync(0xffffffffu, m, off));
                float l = 0.f;
#pragma unroll
                for (int j = 0; j < 13; j++) {
                    int kk = lane + j * 32;
                    if (kk < 400) {
                        float p_ = __expf(sc[j] - m);
                        S[row * 404 + kk] = p_;
                        l += p_;
                    }
                }
#pragma unroll
                for (int off = 16; off; off >>= 1) l += __shfl_xor_sync(0xffffffffu, l, off);
                if (lane == 0) ls[row] = 1.f / l;
            }
            __syncthreads();
            {
                int mt = w & 1, nt = (w >> 1) & 1, kh = w >> 2;
                float c[4] = {0.f, 0.f, 0.f, 0.f};
                int kbase = kh * 200;
                int gp2 = lane >> 2, tg2 = lane & 3;
#pragma unroll 5
                for (int i = 0; i < 25; i++) {
                    int k0 = kbase + i * 8;
                    unsigned a[4], b[2];
                    a[0] = Pu[(mt * 16 + gp2) * 404 + k0 + tg2];
                    a[1] = Pu[(mt * 16 + gp2 + 8) * 404 + k0 + tg2];
                    a[2] = Pu[(mt * 16 + gp2) * 404 + k0 + tg2 + 4];
                    a[3] = Pu[(mt * 16 + gp2 + 8) * 404 + k0 + tg2 + 4];
                    b[0] = Vu[(nt * 8 + gp2) * 404 + k0 + tg2];
                    b[1] = Vu[(nt * 8 + gp2) * 404 + k0 + tg2 + 4];
                    mma8(c, a, b);
                }
                int r0 = mt * 16 + gp2, d0 = nt * 8 + tg2 * 2;
                if (kh == 1) {
                    Po[r0 * 68 + d0]           = c[0];
                    Po[r0 * 68 + d0 + 1]       = c[1];
                    Po[(r0 + 8) * 68 + d0]     = c[2];
                    Po[(r0 + 8) * 68 + d0 + 1] = c[3];
                }
                __syncthreads();
                if (kh == 0) {
                    float s0 = ls[r0], s1 = ls[r0 + 8];
                    int qr0 = qt + r0, qr1 = qt + r0 + 8;
                    if (qr0 < 400) {
                        o[base + qr0 * 128 + d0]     = (c[0] + Po[r0 * 68 + d0]) * s0;
                        o[base + qr0 * 128 + d0 + 1] = (c[1] + Po[r0 * 68 + d0 + 1]) * s0;
                    }
                    if (qr1 < 400) {
                        o[base + qr1 * 128 + d0]     = (c[2] + Po[(r0 + 8) * 68 + d0]) * s1;
                        o[base + qr1 * 128 + d0 + 1] = (c[3] + Po[(r0 + 8) * 68 + d0 + 1]) * s1;
                    }
                }
            }
            __syncthreads();
        }
    } else if (blockIdx.x < 1536) {
        // pooled attention
        float* Ks = sm;
        float* Vs = sm + 1040;
        float* pball = sm + 2080;
        int bid = blockIdx.x - 768;
        int bt = bid >> 3, h = bid & 7;
        int kbase = bt * 64 * 128 + h * 16;
        int qbase = bt * 400 * 128 + h * 16;
        for (int i = tid; i < 1024; i += 256) {
            int kk = i >> 4, d = i & 15;
            Ks[d * 65 + kk] = kp[kbase + kk * 128 + d];
            Vs[d * 65 + kk] = vp[kbase + kk * 128 + d];
        }
        __syncthreads();
        float* pb = pball + w * 64;
        for (int qi = w; qi < 400; qi += 8) {
            float qd[16];
#pragma unroll
            for (int d = 0; d < 16; d++) qd[d] = qa[qbase + qi * 128 + d];
            float sc[2];
            float m = -3.4e38f;
#pragma unroll
            for (int j = 0; j < 2; j++) {
                int kk = lane + 32 * j;
                float s = 0.f;
#pragma unroll
                for (int d = 0; d < 16; d++) s += qd[d] * Ks[d * 65 + kk];
                s = s * 0.25f + pos[qi * 64 + kk];
                sc[j] = s; m = fmaxf(m, s);
            }
#pragma unroll
            for (int off = 16; off; off >>= 1) m = fmaxf(m, __shfl_xor_sync(0xffffffffu, m, off));
            float lsum = 0.f;
#pragma unroll
            for (int j = 0; j < 2; j++) { float p = __expf(sc[j] - m); sc[j] = p; lsum += p; }
#pragma unroll
            for (int off = 16; off; off >>= 1) lsum += __shfl_xor_sync(0xffffffffu, lsum, off);
            pb[lane] = sc[0]; pb[lane + 32] = sc[1];
            __syncwarp();
            int d = lane & 15, half = lane >> 4;
            float acc = 0.f;
#pragma unroll
            for (int i = 0; i < 32; ++i) { int c = 2 * i + half; acc += pb[c] * Vs[d * 65 + c]; }
            acc += __shfl_xor_sync(0xffffffffu, acc, 16);
            if (lane < 16) oa[qbase + qi * 128 + d] = acc / lsum;
            __syncwarp();
        }
    } else {
        // GEANet node: warp-per-row, 5 rows/warp
        int u = lane & 15, hh = lane >> 4;
        float w0c[16], w1c[16];
#pragma unroll
        for (int kk = 0; kk < 16; kk++) {
            w0c[kk] = gw[kk * 16 + u];
            w1c[kk] = gw[256 + kk * 16 + u];
        }
        float b0 = gb[u], b1 = gb[16 + u];
        int rowBase = ((blockIdx.x - 1536) * 8 + w) * 5;
#pragma unroll
        for (int rr = 0; rr < 5; rr++) {
            int id = rowBase + rr;
            float xr[4];
#pragma unroll
            for (int j = 0; j < 4; j++)
                xr[j] = gin[(long long)id * 128 + (hh * 4 + j) * 16 + u];
            float a[4] = {b0, b0, b0, b0};
#pragma unroll
            for (int kk = 0; kk < 16; kk++) {
                int src = (hh << 4) | kk;
                float x0 = __shfl_sync(0xffffffffu, xr[0], src);
                float x1 = __shfl_sync(0xffffffffu, xr[1], src);
                float x2 = __shfl_sync(0xffffffffu, xr[2], src);
                float x3 = __shfl_sync(0xffffffffu, xr[3], src);
                a[0] += x0 * w0c[kk]; a[1] += x1 * w0c[kk];
                a[2] += x2 * w0c[kk]; a[3] += x3 * w0c[kk];
            }
            float mx = fmaxf(fmaxf(a[0], a[1]), fmaxf(a[2], a[3]));
            mx = fmaxf(mx, __shfl_xor_sync(0xffffffffu, mx, 16));
            float e0 = __expf(a[0] - mx), e1 = __expf(a[1] - mx);
            float e2 = __expf(a[2] - mx), e3 = __expf(a[3] - mx);
            float den = e0 + e1 + e2 + e3;
            den += __shfl_xor_sync(0xffffffffu, den, 16);
            float vv[4] = {e0 / den, e1 / den, e2 / den, e3 / den};
            float rs[4] = {vv[0], vv[1], vv[2], vv[3]};
#pragma unroll
            for (int msk = 1; msk < 16; msk <<= 1) {
                rs[0] += __shfl_xor_sync(0xffffffffu, rs[0], msk);
                rs[1] += __shfl_xor_sync(0xffffffffu, rs[1], msk);
                rs[2] += __shfl_xor_sync(0xffffffffu, rs[2], msk);
                rs[3] += __shfl_xor_sync(0xffffffffu, rs[3], msk);
            }
            float dn[4] = {vv[0] / rs[0], vv[1] / rs[1], vv[2] / rs[2], vv[3] / rs[3]};
            float o4[4] = {b1, b1, b1, b1};
#pragma unroll
            for (int kk = 0; kk < 16; kk++) {
                int src = (hh << 4) | kk;
                float x0 = __shfl_sync(0xffffffffu, dn[0], src);
                float x1 = __shfl_sync(0xffffffffu, dn[1], src);
                float x2 = __shfl_sync(0xffffffffu, dn[2], src);
                float x3 = __shfl_sync(0xffffffffu, dn[3], src);
                o4[0] += x0 * w1c[kk]; o4[1] += x1 * w1c[kk];
                o4[2] += x2 * w1c[kk]; o4[3] += x3 * w1c[kk];
            }
            int bI = id / 4800, r2 = id % 4800, t = r2 / 400, n = r2 % 400;
            long long ob = ((long long)(bI * 400 + n) * 12 + t) * 128;
#pragma unroll
            for (int j = 0; j < 4; j++) gout[ob + (hh * 4 + j) * 16 + u] = o4[j];
        }
    }
}

// ---------------- warp-per-row GEANet edge (standalone) ----------------
__global__ void __launch_bounds__(256) gea_edge(
    const float* __restrict__ in, const float* __restrict__ w, const float* __restrict__ bb,
    float* __restrict__ outp, float* __restrict__ outp2)
{
    int lane = threadIdx.x & 31, wid = threadIdx.x >> 5;
    int u = lane & 15, hh = lane >> 4;
    float w0c[16], w1c[16];
#pragma unroll
    for (int kk = 0; kk < 16; kk++) {
        w0c[kk] = w[kk * 16 + u];
        w1c[kk] = w[256 + kk * 16 + u];
    }
    float b0 = bb[u], b1 = bb[16 + u];
    int id = blockIdx.x * 8 + wid;
    if (id >= 400) return;
    float xr[4];
#pragma unroll
    for (int j = 0; j < 4; j++)
        xr[j] = in[(long long)id * 128 + u * 8 + (hh * 4 + j)];
    float a[4] = {b0, b0, b0, b0};
#pragma unroll
    for (int kk = 0; kk < 16; kk++) {
        int src = (hh << 4) | kk;
        float x0 = __shfl_sync(0xffffffffu, xr[0], src);
        float x1 = __shfl_sync(0xffffffffu, xr[1], src);
        float x2 = __shfl_sync(0xffffffffu, xr[2], src);
        float x3 = __shfl_sync(0xffffffffu, xr[3], src);
        a[0] += x0 * w0c[kk]; a[1] += x1 * w0c[kk];
        a[2] += x2 * w0c[kk]; a[3] += x3 * w0c[kk];
    }
    float mx = fmaxf(fmaxf(a[0], a[1]), fmaxf(a[2], a[3]));
    mx = fmaxf(mx, __shfl_xor_sync(0xffffffffu, mx, 16));
    float e0 = __expf(a[0] - mx), e1 = __expf(a[1] - mx);
    float e2 = __expf(a[2] - mx), e3 = __expf(a[3] - mx);
    float den = e0 + e1 + e2 + e3;
    den += __shfl_xor_sync(0xffffffffu, den, 16);
    float vv[4] = {e0 / den, e1 / den, e2 / den, e3 / den};
    float rs[4] = {vv[0], vv[1], vv[2], vv[3]};
#pragma unroll
    for (int msk = 1; msk < 16; msk <<= 1) {
        rs[0] += __shfl_xor_sync(0xffffffffu, rs[0], msk);
        rs[1] += __shfl_xor_sync(0xffffffffu, rs[1], msk);
        rs[2] += __shfl_xor_sync(0xffffffffu, rs[2], msk);
        rs[3] += __shfl_xor_sync(0xffffffffu, rs[3], msk);
    }
    float dn[4] = {vv[0] / rs[0], vv[1] / rs[1], vv[2] / rs[2], vv[3] / rs[3]};
    float o4[4] = {b1, b1, b1, b1};
#pragma unroll
    for (int kk = 0; kk < 16; kk++) {
        int src = (hh << 4) | kk;
        float x0 = __shfl_sync(0xffffffffu, dn[0], src);
        float x1 = __shfl_sync(0xffffffffu, dn[1], src);
        float x2 = __shfl_sync(0xffffffffu, dn[2], src);
        float x3 = __shfl_sync(0xffffffffu, dn[3], src);
        o4[0] += x0 * w1c[kk]; o4[1] += x1 * w1c[kk];
        o4[2] += x2 * w1c[kk]; o4[3] += x3 * w1c[kk];
    }
    long long ob = (long long)id * 128;
#pragma unroll
    for (int j = 0; j < 4; j++) {
        int dloc = (hh * 4 + j) * 16 + u;
        outp[ob + dloc] = o4[j];
        if (outp2) outp2[ob + dloc] = o4[j];
    }
}

// ---------------- warp-per-row LayerNorm ----------------
__global__ void __launch_bounds__(128) ln4_kernel(
    const float* __restrict__ a, const float* __restrict__ b,
    const float* __restrict__ c, const float* __restrict__ d,
    const float* __restrict__ gamma, const float* __restrict__ beta,
    float* __restrict__ out, const float* __restrict__ addp)
{
    int lane = threadIdx.x & 31, wid = threadIdx.x >> 5;
    long long row = (long long)blockIdx.x * 4 + wid;
    long long base = row * 128 + lane * 4;
    float4 v = *(const float4*)(a + base);
    if (b) { float4 t = *(const float4*)(b + base); v.x += t.x; v.y += t.y; v.z += t.z; v.w += t.w; }
    if (c) { float4 t = *(const float4*)(c + base); v.x += t.x; v.y += t.y; v.z += t.z; v.w += t.w; }
    if (d) { float4 t = *(const float4*)(d + base); v.x += t.x; v.y += t.y; v.z += t.z; v.w += t.w; }
    float s = v.x + v.y + v.z + v.w;
    float ss = v.x * v.x + v.y * v.y + v.z * v.z + v.w * v.w;
#pragma unroll
    for (int off = 16; off; off >>= 1) {
        s  += __shfl_xor_sync(0xffffffffu, s,  off);
        ss += __shfl_xor_sync(0xffffffffu, ss, off);
    }
    float m = s * (1.f / 128.f);
    float var = ss * (1.f / 128.f) - m * m;
    float inv = rsqrtf(var + 1e-5f);
    float4 g  = *(const float4*)(gamma + lane * 4);
    float4 be = *(const float4*)(beta + lane * 4);
    float4 r;
    r.x = (v.x - m) * inv * g.x + be.x;
    r.y = (v.y - m) * inv * g.y + be.y;
    r.z = (v.z - m) * inv * g.z + be.z;
    r.w = (v.w - m) * inv * g.w + be.w;
    if (addp) {
        float4 t = *(const float4*)(addp + base);
        r.x += t.x; r.y += t.y; r.z += t.z; r.w += t.w;
    }
    *(float4*)(out + base) = r;
}

// ---------------- adaptive avg pool ----------------
__global__ void __launch_bounds__(128) pool_kernel(const float* __restrict__ x, float* __restrict__ xp)
{
    int bid = blockIdx.x;
    int bt = bid >> 6, c = bid & 63;
    int s = (c * 400) >> 6;
    int e = ((c + 1) * 400 + 63) >> 6;
    float sum = 0.f;
    for (int n = s; n < e; ++n) sum += x[(bt * 400 + n) * 128 + threadIdx.x];
    xp[bid * 128 + threadIdx.x] = sum / (float)(e - s);
}

// ---------------- host ----------------
static float* sym(const void* s) { void* p = nullptr; cudaGetSymbolAddress(&p, s); return (float*)p; }

extern "C" void kernel_launch(void* const* d_in, const int* in_sizes, int n_in,
                              void* d_out, int out_size)
{
    const float* x      = (const float*)d_in[0];
    const float* semb   = (const float*)d_in[1];
    const float* dqkv_w = (const float*)d_in[2];
    const float* dqkv_b = (const float*)d_in[3];
    const float* dout_w = (const float*)d_in[4];
    const float* dout_b = (const float*)d_in[5];
    const float* aqkv_w = (const float*)d_in[6];
    const float* aqkv_b = (const float*)d_in[7];
    const float* aout_w = (const float*)d_in[8];
    const float* aout_b = (const float*)d_in[9];
    const float* adp_pos= (const float*)d_in[10];
    const float* gsh_w  = (const float*)d_in[11];
    const float* gsh_b  = (const float*)d_in[12];
    const float* gnode_w= (const float*)d_in[13];
    const float* gnode_b= (const float*)d_in[14];
    const float* gedge_w= (const float*)d_in[15];
    const float* gedge_b= (const float*)d_in[16];
    const float* sp_w   = (const float*)d_in[17];
    const float* sp_b   = (const float*)d_in[18];
    const float* f1w1   = (const float*)d_in[19];
    const float* f1b1   = (const float*)d_in[20];
    const float* f1w2   = (const float*)d_in[21];
    const float* f1b2   = (const float*)d_in[22];
    const float* f2w1   = (const float*)d_in[23];
    const float* f2b1   = (const float*)d_in[24];
    const float* f2w2   = (const float*)d_in[25];
    const float* f2b2   = (const float*)d_in[26];
    const float* lns    = (const float*)d_in[27];
    const float* lnb    = (const float*)d_in[28];
    float* out = (float*)d_out;

    float *q = sym(g_q), *k = sym(g_k), *v = sym(g_v), *o = sym(g_o), *oa = sym(g_oa);
    float *dtw = sym(g_dtw), *ex = sym(g_ex), *res = sym(g_res), *tmp = sym(g_tmp);
    float *xp = sym(g_xp), *kp = sym(g_kp), *vp = sym(g_vp);
    float *sen = sym(g_sen), *edge = sym(g_edge), *senx = sym(g_senx);

    const int GEMM_SMEM = 3 * (4608 + 4352) * 4;   // 107520 B
    const int ATT_SMEM  = ATT_TC_FLOATS * 4;       // 112512 B -> 2 blocks/SM
    const int FFF_SMEM  = FFF_FLOATS * 4;          // 208896 B
    cudaFuncSetAttribute(mma_gemm,   cudaFuncAttributeMaxDynamicSharedMemorySize, GEMM_SMEM);
    cudaFuncSetAttribute(mma_gemm_b, cudaFuncAttributeMaxDynamicSharedMemorySize, GEMM_SMEM);
    cudaFuncSetAttribute(attn_both_kernel, cudaFuncAttributeMaxDynamicSharedMemorySize, ATT_SMEM);
    cudaFuncSetAttribute(ff_fused, cudaFuncAttributeMaxDynamicSharedMemorySize, FFF_SMEM);

    // batch 1: five projections reading x
    GSet b1;
    b1.A[0] = x; b1.W[0] = dqkv_w;          b1.Bv[0] = dqkv_b;        b1.C[0] = q;
    b1.A[1] = x; b1.W[1] = dqkv_w + 16384;  b1.Bv[1] = dqkv_b + 128;  b1.C[1] = k;
    b1.A[2] = x; b1.W[2] = dqkv_w + 32768;  b1.Bv[2] = dqkv_b + 256;  b1.C[2] = v;
    b1.A[3] = x; b1.W[3] = aqkv_w;          b1.Bv[3] = aqkv_b;        b1.C[3] = tmp;
    b1.A[4] = x; b1.W[4] = gsh_w;           b1.Bv[4] = gsh_b;         b1.C[4] = res;
    mma_gemm_b<<<dim3(300, 5), 256, GEMM_SMEM>>>(b1, ROWS);

    pool_kernel<<<6144, 128>>>(x, xp);

    // batch 2: pooled K/V
    GSet b2;
    b2.A[0] = xp; b2.W[0] = aqkv_w + 16384; b2.Bv[0] = aqkv_b + 128; b2.C[0] = kp;
    b2.A[1] = xp; b2.W[1] = aqkv_w + 32768; b2.Bv[1] = aqkv_b + 256; b2.C[1] = vp;
    b2.A[2] = xp; b2.W[2] = b2.W[0];        b2.Bv[2] = b2.Bv[0];     b2.C[2] = kp;
    b2.A[3] = xp; b2.W[3] = b2.W[0];        b2.Bv[3] = b2.Bv[0];     b2.C[3] = kp;
    b2.A[4] = xp; b2.W[4] = b2.W[0];        b2.Bv[4] = b2.Bv[0];     b2.C[4] = kp;
    mma_gemm_b<<<dim3(48, 2), 256, GEMM_SMEM>>>(b2, 6144);

    // merged: full attn | pooled attn | gea node
    attn_both_kernel<<<2496, 256, ATT_SMEM>>>(q, k, v, o, tmp, kp, vp, adp_pos, oa,
                                              res, gnode_w, gnode_b, ex);

    // batch 3: output projections
    GSet b3;
    b3.A[0] = o;  b3.W[0] = dout_w; b3.Bv[0] = dout_b; b3.C[0] = dtw;
    b3.A[1] = oa; b3.W[1] = aout_w; b3.Bv[1] = aout_b; b3.C[1] = k;    // oa-proj -> k
    b3.A[2] = o;  b3.W[2] = b3.W[0]; b3.Bv[2] = b3.Bv[0]; b3.C[2] = dtw;
    b3.A[3] = o;  b3.W[3] = b3.W[0]; b3.Bv[3] = b3.Bv[0]; b3.C[3] = dtw;
    b3.A[4] = o;  b3.W[4] = b3.W[0]; b3.Bv[4] = b3.Bv[0]; b3.C[4] = dtw;
    mma_gemm_b<<<dim3(300, 2), 256, GEMM_SMEM>>>(b3, ROWS);

    // sen + GEANet edge (dual-writes senx and output tail)
    mma_gemm<<<4, 256, GEMM_SMEM>>>(semb, sp_w, sp_b, sen, 400);
    ln4_kernel<<<100, 128>>>(sen, nullptr, nullptr, nullptr, lns + 3 * 128, lnb + 3 * 128, sen, nullptr);
    mma_gemm<<<4, 256, GEMM_SMEM>>>(sen, gsh_w, gsh_b, edge, 400);
    gea_edge<<<50, 256>>>(edge, gedge_w, gedge_b, senx,
                          (out_size >= BIG + 51200) ? (out + BIG) : nullptr);

    // out = LN(x + dtw + oa_proj + extra)
    ln4_kernel<<<9600, 128>>>(x, dtw, k, ex, lns, lnb, res, nullptr);

    // out_attn = LN(FF1(out) + out)
    ff_fused<<<300, 256, FFF_SMEM>>>(res, f1w1, f1b1, f1w2, f1b2, nullptr, tmp);
    ln4_kernel<<<9600, 128>>>(tmp, res, nullptr, nullptr, lns + 128, lnb + 128, dtw, nullptr);

    // sp = LN(FF2(out_attn * sen_extra)); final out = out_attn + sp fused into LN
    ff_fused<<<300, 256, FFF_SMEM>>>(dtw, f2w1, f2b1, f2w2, f2b2, senx, tmp);
    ln4_kernel<<<9600, 128>>>(tmp, nullptr, nullptr, nullptr, lns + 256, lnb + 256, out, dtw);
}